// round 2
// baseline (speedup 1.0000x reference)
#include <cuda_runtime.h>
#include <math.h>

#define HID   1024
#define BNUM  8
#define SLEN  2048
#define QLEN  2048

// Scratch for projected Q, K, V (device globals: allocation-free per harness rules)
__device__ float g_Qp[(size_t)BNUM * QLEN * HID];
__device__ float g_Kp[(size_t)BNUM * SLEN * HID];
__device__ float g_Vp[(size_t)BNUM * SLEN * HID];

// ---------------------------------------------------------------------------
// NT GEMM: C[m,n] = alpha * sum_k A[m,k] * B[n,k] (+ bias[n])
// A: [M,K] row-major, B: [N,K] row-major, C: [M,N] row-major.
// 128x128 block, BK=8, 256 threads, 8x8 micro-tile per thread.
// All dims assumed multiples of 128 / 8 (true for this problem).
// ---------------------------------------------------------------------------
__global__ __launch_bounds__(256, 2)
void gemm_nt_kernel(const float* __restrict__ A, const float* __restrict__ B,
                    float* __restrict__ C, const float* __restrict__ bias,
                    int M, int N, int K, float alpha,
                    size_t sA, size_t sB, size_t sC)
{
    __shared__ float As[8][128];
    __shared__ float Bs[8][128];

    const float* Ab = A + (size_t)blockIdx.z * sA;
    const float* Bb = B + (size_t)blockIdx.z * sB;
    float*       Cb = C + (size_t)blockIdx.z * sC;

    const int bm = blockIdx.y * 128;
    const int bn = blockIdx.x * 128;
    const int tid = threadIdx.x;

    // global->smem load mapping: thread pair covers one row's 8 k-floats (32B)
    const int lrow = tid >> 1;          // 0..127
    const int lcol = (tid & 1) << 2;    // 0 or 4

    const int ty = tid >> 4;            // 0..15
    const int tx = tid & 15;            // 0..15

    float acc[8][8];
#pragma unroll
    for (int i = 0; i < 8; i++)
#pragma unroll
        for (int j = 0; j < 8; j++) acc[i][j] = 0.0f;

    for (int k0 = 0; k0 < K; k0 += 8) {
        float4 a4 = *(const float4*)(Ab + (size_t)(bm + lrow) * K + k0 + lcol);
        float4 b4 = *(const float4*)(Bb + (size_t)(bn + lrow) * K + k0 + lcol);
        As[lcol + 0][lrow] = a4.x; As[lcol + 1][lrow] = a4.y;
        As[lcol + 2][lrow] = a4.z; As[lcol + 3][lrow] = a4.w;
        Bs[lcol + 0][lrow] = b4.x; Bs[lcol + 1][lrow] = b4.y;
        Bs[lcol + 2][lrow] = b4.z; Bs[lcol + 3][lrow] = b4.w;
        __syncthreads();

#pragma unroll
        for (int kk = 0; kk < 8; kk++) {
            float ra[8], rb[8];
#pragma unroll
            for (int i = 0; i < 8; i++) ra[i] = As[kk][ty * 8 + i];
#pragma unroll
            for (int j = 0; j < 8; j++) rb[j] = Bs[kk][tx * 8 + j];
#pragma unroll
            for (int i = 0; i < 8; i++)
#pragma unroll
                for (int j = 0; j < 8; j++) acc[i][j] += ra[i] * rb[j];
        }
        __syncthreads();
    }

#pragma unroll
    for (int i = 0; i < 8; i++) {
        const int row = bm + ty * 8 + i;
#pragma unroll
        for (int j = 0; j < 8; j += 4) {
            const int col = bn + tx * 8 + j;
            float4 o;
            o.x = alpha * acc[i][j + 0];
            o.y = alpha * acc[i][j + 1];
            o.z = alpha * acc[i][j + 2];
            o.w = alpha * acc[i][j + 3];
            if (bias != nullptr) {
                o.x += bias[col + 0]; o.y += bias[col + 1];
                o.z += bias[col + 2]; o.w += bias[col + 3];
            }
            *(float4*)(Cb + (size_t)row * N + col) = o;
        }
    }
}

// ---------------------------------------------------------------------------
// TN GEMM: C[m,n] = sum_k A[k,m] * B[k,n]
// A: [K,M] row-major (attn [S,Q]), B: [K,N] row-major (V [S,H]), C: [M,N].
// ---------------------------------------------------------------------------
__global__ __launch_bounds__(256, 2)
void gemm_tn_kernel(const float* __restrict__ A, const float* __restrict__ B,
                    float* __restrict__ C,
                    int M, int N, int K,
                    size_t sA, size_t sB, size_t sC)
{
    __shared__ float As[8][128];
    __shared__ float Bs[8][128];

    const float* Ab = A + (size_t)blockIdx.z * sA;
    const float* Bb = B + (size_t)blockIdx.z * sB;
    float*       Cb = C + (size_t)blockIdx.z * sC;

    const int bm = blockIdx.y * 128;
    const int bn = blockIdx.x * 128;
    const int tid = threadIdx.x;

    const int krow = tid >> 5;           // 0..7
    const int mcol = (tid & 31) << 2;    // 0..124

    const int ty = tid >> 4;
    const int tx = tid & 15;

    float acc[8][8];
#pragma unroll
    for (int i = 0; i < 8; i++)
#pragma unroll
        for (int j = 0; j < 8; j++) acc[i][j] = 0.0f;

    for (int k0 = 0; k0 < K; k0 += 8) {
        *(float4*)&As[krow][mcol] =
            *(const float4*)(Ab + (size_t)(k0 + krow) * M + bm + mcol);
        *(float4*)&Bs[krow][mcol] =
            *(const float4*)(Bb + (size_t)(k0 + krow) * N + bn + mcol);
        __syncthreads();

#pragma unroll
        for (int kk = 0; kk < 8; kk++) {
            float ra[8], rb[8];
#pragma unroll
            for (int i = 0; i < 8; i++) ra[i] = As[kk][ty * 8 + i];
#pragma unroll
            for (int j = 0; j < 8; j++) rb[j] = Bs[kk][tx * 8 + j];
#pragma unroll
            for (int i = 0; i < 8; i++)
#pragma unroll
                for (int j = 0; j < 8; j++) acc[i][j] += ra[i] * rb[j];
        }
        __syncthreads();
    }

#pragma unroll
    for (int i = 0; i < 8; i++) {
        const int row = bm + ty * 8 + i;
#pragma unroll
        for (int j = 0; j < 8; j += 4) {
            const int col = bn + tx * 8 + j;
            float4 o;
            o.x = acc[i][j + 0]; o.y = acc[i][j + 1];
            o.z = acc[i][j + 2]; o.w = acc[i][j + 3];
            *(float4*)(Cb + (size_t)row * N + col) = o;
        }
    }
}

// ---------------------------------------------------------------------------
// Column softmax over the S axis of attn [B, S, Q], in place.
// One thread owns one q-column; rows are read coalesced across the block.
// ---------------------------------------------------------------------------
__global__ void softmax_col_kernel(float* __restrict__ attn)
{
    const int b = blockIdx.y;
    const int q = blockIdx.x * blockDim.x + threadIdx.x;
    float* p = attn + (size_t)b * SLEN * QLEN + q;

    float m = -1e30f;
    for (int s = 0; s < SLEN; s++)
        m = fmaxf(m, p[(size_t)s * QLEN]);

    float sum = 0.0f;
    for (int s = 0; s < SLEN; s++) {
        float e = __expf(p[(size_t)s * QLEN] - m);
        sum += e;
        p[(size_t)s * QLEN] = e;
    }

    const float inv = 1.0f / sum;
    for (int s = 0; s < SLEN; s++)
        p[(size_t)s * QLEN] *= inv;
}

// ---------------------------------------------------------------------------
extern "C" void kernel_launch(void* const* d_in, const int* in_sizes, int n_in,
                              void* d_out, int out_size)
{
    const float* queries = (const float*)d_in[0];
    const float* keys    = (const float*)d_in[1];
    const float* values  = (const float*)d_in[2];
    const float* Wq      = (const float*)d_in[3];
    const float* bq      = (const float*)d_in[4];
    const float* Wk      = (const float*)d_in[5];
    const float* bk      = (const float*)d_in[6];
    const float* Wv      = (const float*)d_in[7];
    const float* bv      = (const float*)d_in[8];

    float* ctx  = (float*)d_out;                                 // [B,Q,H]
    float* attn = (float*)d_out + (size_t)BNUM * QLEN * HID;     // [B,S,Q]

    float *qp, *kp, *vp;
    cudaGetSymbolAddress((void**)&qp, g_Qp);
    cudaGetSymbolAddress((void**)&kp, g_Kp);
    cudaGetSymbolAddress((void**)&vp, g_Vp);

    const float scale = 0.03125f;  // 1/sqrt(1024)

    // 1) Projections: [B*L, H] x [H, H]^T + bias (batch folded into M)
    {
        dim3 grid(HID / 128, (BNUM * QLEN) / 128, 1);
        gemm_nt_kernel<<<grid, 256>>>(queries, Wq, qp, bq,
                                      BNUM * QLEN, HID, HID, 1.0f, 0, 0, 0);
        gemm_nt_kernel<<<grid, 256>>>(keys, Wk, kp, bk,
                                      BNUM * SLEN, HID, HID, 1.0f, 0, 0, 0);
        gemm_nt_kernel<<<grid, 256>>>(values, Wv, vp, bv,
                                      BNUM * SLEN, HID, HID, 1.0f, 0, 0, 0);
    }

    // 2) scores[b,s,q] = scale * K[b,s,:] . Q[b,q,:]   (batched NT)
    {
        dim3 grid(QLEN / 128, SLEN / 128, BNUM);
        gemm_nt_kernel<<<grid, 256>>>(kp, qp, attn, nullptr,
                                      SLEN, QLEN, HID, scale,
                                      (size_t)SLEN * HID, (size_t)QLEN * HID,
                                      (size_t)SLEN * QLEN);
    }

    // 3) softmax over S (axis=1), in place in d_out's attn region
    {
        dim3 grid(QLEN / 256, BNUM);
        softmax_col_kernel<<<grid, 256>>>(attn);
    }

    // 4) context[b,q,h] = sum_s attn[b,s,q] * V[b,s,h]   (batched TN)
    {
        dim3 grid(HID / 128, QLEN / 128, BNUM);
        gemm_tn_kernel<<<grid, 256>>>(attn, vp, ctx,
                                      QLEN, HID, SLEN,
                                      (size_t)SLEN * QLEN, (size_t)SLEN * HID,
                                      (size_t)QLEN * HID);
    }
}

// round 4
// speedup vs baseline: 2.7360x; 2.7360x over previous
#include <cuda_runtime.h>
#include <cuda_fp16.h>
#include <cstdint>
#include <math.h>

#define HID   1024
#define BNUM  8
#define SLEN  2048
#define QLEN  2048

// ---------------- scratch (device globals: allocation-free) ----------------
__device__ float g_Qp[(size_t)BNUM * QLEN * HID];   // projected Q  [B,Q,H]
__device__ float g_Kp[(size_t)BNUM * SLEN * HID];   // projected K  [B,S,H]
__device__ float g_Vp[(size_t)BNUM * SLEN * HID];   // projected V  [B,S,H]
__device__ float g_Vt[(size_t)BNUM * HID  * SLEN];  // V transposed [B,H,S]
__device__ float g_St[(size_t)BNUM * QLEN * SLEN];  // scores^T / attn^T [B,Q,S]

// ---------------- tile geometry ----------------
#define TM   128
#define TN   128
#define TKF  32            // K floats per mainloop iter (= 2 k16 steps)
#define ROWH 40            // halves per smem row (32 data + 8 pad)
#define ROWB 80            // bytes per smem row
#define TILE_B (128 * ROWB)      // 10240 B per tile
#define BUF_B  (4 * TILE_B)      // A_hi, A_lo, B_hi, B_lo
#define GEMM_SMEM (2 * BUF_B)    // 81920 B (double buffered)

// ---------------- small PTX helpers ----------------
__device__ __forceinline__ uint32_t smem_u32(const void* p) {
    uint32_t a;
    asm("{ .reg .u64 t; cvta.to.shared.u64 t, %1; cvt.u32.u64 %0, t; }"
        : "=r"(a) : "l"(p));
    return a;
}

__device__ __forceinline__ void ldsm4(uint32_t* r, uint32_t addr) {
    asm volatile("ldmatrix.sync.aligned.m8n8.x4.shared.b16 {%0,%1,%2,%3}, [%4];"
                 : "=r"(r[0]), "=r"(r[1]), "=r"(r[2]), "=r"(r[3]) : "r"(addr));
}

__device__ __forceinline__ void mma16816(float* c, const uint32_t* a,
                                         const uint32_t* b) {
    asm volatile(
        "mma.sync.aligned.m16n8k16.row.col.f32.f16.f16.f32 "
        "{%0,%1,%2,%3}, {%4,%5,%6,%7}, {%8,%9}, {%0,%1,%2,%3};"
        : "+f"(c[0]), "+f"(c[1]), "+f"(c[2]), "+f"(c[3])
        : "r"(a[0]), "r"(a[1]), "r"(a[2]), "r"(a[3]), "r"(b[0]), "r"(b[1]));
}

// ---------------------------------------------------------------------------
// fp16-split tensor-core NT GEMM.
// C[m,n] = alpha * sum_k A[m,k]*B[n,k] (+ bias[n]); A:[M,K], B:[N,K] row-major.
// split=1: a=hi+lo fp16 decomposition, 3 MMAs (hi*hi + hi*lo + lo*hi), eps~2^-22.
// split=0: plain fp16 (used for attn*V where operands are well-conditioned).
// ---------------------------------------------------------------------------
extern "C" __global__ void __launch_bounds__(256)
gemm_fp16s(const float* __restrict__ A, const float* __restrict__ B,
           float* __restrict__ C, const float* __restrict__ bias,
           int M, int N, int K, float alpha, int split,
           size_t sA, size_t sB, size_t sC)
{
    extern __shared__ char sm[];
    const uint32_t sb = smem_u32(sm);

    const int tid  = threadIdx.x;
    const int lane = tid & 31;
    const int w    = tid >> 5;
    const int wm   = w & 1;          // 2 warps along M
    const int wn   = w >> 1;         // 4 warps along N
    const int g    = lane >> 2;
    const int t    = lane & 3;

    const float* Ab = A + (size_t)blockIdx.z * sA;
    const float* Bb = B + (size_t)blockIdx.z * sB;
    float*       Cb = C + (size_t)blockIdx.z * sC;
    const int bm = blockIdx.y * TM;
    const int bn = blockIdx.x * TN;

    // ldmatrix per-thread address components
    const int a_r   = ((lane >> 3) & 1) * 8 + (lane & 7);  // row within 16-tile
    const int a_c8  = (lane >> 4) * 8;                     // col offset (halves)
    const int b_r   = (lane >> 4) * 8 + (lane & 7);
    const int b_c8  = ((lane >> 3) & 1) * 8;

    float acc[4][4][4];
#pragma unroll
    for (int i = 0; i < 4; i++)
#pragma unroll
        for (int j = 0; j < 4; j++)
#pragma unroll
            for (int e = 0; e < 4; e++) acc[i][j][e] = 0.0f;

    float4 ra[4], rb[4];

    const int NK = K / TKF;

    // ---- prologue: load k-tile 0, convert, store to buffer 0 ----
#pragma unroll
    for (int i = 0; i < 4; i++) {
        int f = tid + 256 * i;
        ra[i] = *(const float4*)(Ab + (size_t)(bm + (f >> 3)) * K + (f & 7) * 4);
        rb[i] = *(const float4*)(Bb + (size_t)(bn + (f >> 3)) * K + (f & 7) * 4);
    }
    {
        char* base = sm;  // buffer 0
#pragma unroll
        for (int i = 0; i < 4; i++) {
            int f = tid + 256 * i;
            uint32_t off = (uint32_t)((f >> 3) * ROWB + (f & 7) * 8);
            float4 va = ra[i], vb = rb[i];
            __half2 ah0 = __floats2half2_rn(va.x, va.y);
            __half2 ah1 = __floats2half2_rn(va.z, va.w);
            __half2 bh0 = __floats2half2_rn(vb.x, vb.y);
            __half2 bh1 = __floats2half2_rn(vb.z, vb.w);
            *(uint2*)(base + off) =
                make_uint2(*(uint32_t*)&ah0, *(uint32_t*)&ah1);
            *(uint2*)(base + 2 * TILE_B + off) =
                make_uint2(*(uint32_t*)&bh0, *(uint32_t*)&bh1);
            if (split) {
                float2 fa0 = __half22float2(ah0), fa1 = __half22float2(ah1);
                float2 fb0 = __half22float2(bh0), fb1 = __half22float2(bh1);
                __half2 al0 = __floats2half2_rn(va.x - fa0.x, va.y - fa0.y);
                __half2 al1 = __floats2half2_rn(va.z - fa1.x, va.w - fa1.y);
                __half2 bl0 = __floats2half2_rn(vb.x - fb0.x, vb.y - fb0.y);
                __half2 bl1 = __floats2half2_rn(vb.z - fb1.x, vb.w - fb1.y);
                *(uint2*)(base + TILE_B + off) =
                    make_uint2(*(uint32_t*)&al0, *(uint32_t*)&al1);
                *(uint2*)(base + 3 * TILE_B + off) =
                    make_uint2(*(uint32_t*)&bl0, *(uint32_t*)&bl1);
            }
        }
    }
    __syncthreads();

    for (int kt = 0; kt < NK; kt++) {
        const int p = kt & 1;

        // prefetch next k-tile into registers (overlaps with MMA below)
        if (kt + 1 < NK) {
            const float* Ag = Ab + (size_t)bm * K + (kt + 1) * TKF;
            const float* Bg = Bb + (size_t)bn * K + (kt + 1) * TKF;
#pragma unroll
            for (int i = 0; i < 4; i++) {
                int f = tid + 256 * i;
                ra[i] = *(const float4*)(Ag + (size_t)(f >> 3) * K + (f & 7) * 4);
                rb[i] = *(const float4*)(Bg + (size_t)(f >> 3) * K + (f & 7) * 4);
            }
        }

        // ---- MMA phase on buffer p ----
        const uint32_t sa_hi = sb + p * BUF_B;
        const uint32_t sa_lo = sa_hi + TILE_B;
        const uint32_t sb_hi = sa_hi + 2 * TILE_B;
        const uint32_t sb_lo = sa_hi + 3 * TILE_B;

#pragma unroll
        for (int ks = 0; ks < 2; ks++) {
            const int k0 = ks * 16;  // halves

            uint32_t bh[8], bl[8];
#pragma unroll
            for (int j = 0; j < 2; j++) {
                uint32_t addr = (uint32_t)((wn * 32 + j * 16 + b_r) * ROWB +
                                           (k0 + b_c8) * 2);
                ldsm4(bh + 4 * j, sb_hi + addr);
                if (split) ldsm4(bl + 4 * j, sb_lo + addr);
            }

            uint32_t ah[4][4], al[4][4];
#pragma unroll
            for (int mf = 0; mf < 4; mf++) {
                uint32_t addr = (uint32_t)((wm * 64 + mf * 16 + a_r) * ROWB +
                                           (k0 + a_c8) * 2);
                ldsm4(ah[mf], sa_hi + addr);
                if (split) ldsm4(al[mf], sa_lo + addr);
            }

#pragma unroll
            for (int mf = 0; mf < 4; mf++)
#pragma unroll
                for (int nf = 0; nf < 4; nf++) {
                    mma16816(acc[mf][nf], ah[mf], bh + 2 * nf);
                    if (split) {
                        mma16816(acc[mf][nf], ah[mf], bl + 2 * nf);
                        mma16816(acc[mf][nf], al[mf], bh + 2 * nf);
                    }
                }
        }

        // ---- convert + store next tile into buffer p^1 ----
        if (kt + 1 < NK) {
            char* base = sm + (p ^ 1) * BUF_B;
#pragma unroll
            for (int i = 0; i < 4; i++) {
                int f = tid + 256 * i;
                uint32_t off = (uint32_t)((f >> 3) * ROWB + (f & 7) * 8);
                float4 va = ra[i], vb = rb[i];
                __half2 ah0 = __floats2half2_rn(va.x, va.y);
                __half2 ah1 = __floats2half2_rn(va.z, va.w);
                __half2 bh0 = __floats2half2_rn(vb.x, vb.y);
                __half2 bh1 = __floats2half2_rn(vb.z, vb.w);
                *(uint2*)(base + off) =
                    make_uint2(*(uint32_t*)&ah0, *(uint32_t*)&ah1);
                *(uint2*)(base + 2 * TILE_B + off) =
                    make_uint2(*(uint32_t*)&bh0, *(uint32_t*)&bh1);
                if (split) {
                    float2 fa0 = __half22float2(ah0), fa1 = __half22float2(ah1);
                    float2 fb0 = __half22float2(bh0), fb1 = __half22float2(bh1);
                    __half2 al0 = __floats2half2_rn(va.x - fa0.x, va.y - fa0.y);
                    __half2 al1 = __floats2half2_rn(va.z - fa1.x, va.w - fa1.y);
                    __half2 bl0 = __floats2half2_rn(vb.x - fb0.x, vb.y - fb0.y);
                    __half2 bl1 = __floats2half2_rn(vb.z - fb1.x, vb.w - fb1.y);
                    *(uint2*)(base + TILE_B + off) =
                        make_uint2(*(uint32_t*)&al0, *(uint32_t*)&al1);
                    *(uint2*)(base + 3 * TILE_B + off) =
                        make_uint2(*(uint32_t*)&bl0, *(uint32_t*)&bl1);
                }
            }
            __syncthreads();
        }
    }

    // ---- epilogue ----
#pragma unroll
    for (int mf = 0; mf < 4; mf++) {
        const int row0 = bm + wm * 64 + mf * 16 + g;
        const int row1 = row0 + 8;
#pragma unroll
        for (int nf = 0; nf < 4; nf++) {
            const int col = bn + wn * 32 + nf * 8 + 2 * t;
            float bx = 0.0f, by = 0.0f;
            if (bias != nullptr) { bx = bias[col]; by = bias[col + 1]; }
            float2 o0, o1;
            o0.x = alpha * acc[mf][nf][0] + bx;
            o0.y = alpha * acc[mf][nf][1] + by;
            o1.x = alpha * acc[mf][nf][2] + bx;
            o1.y = alpha * acc[mf][nf][3] + by;
            *(float2*)(Cb + (size_t)row0 * N + col) = o0;
            *(float2*)(Cb + (size_t)row1 * N + col) = o1;
        }
    }
}

// ---------------- row softmax over last axis (len SLEN) ----------------
__global__ void __launch_bounds__(256) softmax_rows(float* __restrict__ x)
{
    __shared__ float red[8];
    const size_t row = blockIdx.x;
    float4* p = (float4*)(x + row * (size_t)SLEN);
    const int tid = threadIdx.x;
    const int wid = tid >> 5, lane = tid & 31;

    float4 a = p[tid];
    float4 b = p[tid + 256];

    float m = fmaxf(fmaxf(fmaxf(a.x, a.y), fmaxf(a.z, a.w)),
                    fmaxf(fmaxf(b.x, b.y), fmaxf(b.z, b.w)));
#pragma unroll
    for (int o = 16; o > 0; o >>= 1)
        m = fmaxf(m, __shfl_xor_sync(0xFFFFFFFFu, m, o));
    if (lane == 0) red[wid] = m;
    __syncthreads();
    m = red[0];
#pragma unroll
    for (int j = 1; j < 8; j++) m = fmaxf(m, red[j]);
    __syncthreads();

    a.x = __expf(a.x - m); a.y = __expf(a.y - m);
    a.z = __expf(a.z - m); a.w = __expf(a.w - m);
    b.x = __expf(b.x - m); b.y = __expf(b.y - m);
    b.z = __expf(b.z - m); b.w = __expf(b.w - m);

    float s = a.x + a.y + a.z + a.w + b.x + b.y + b.z + b.w;
#pragma unroll
    for (int o = 16; o > 0; o >>= 1)
        s += __shfl_xor_sync(0xFFFFFFFFu, s, o);
    if (lane == 0) red[wid] = s;
    __syncthreads();
    s = 0.0f;
#pragma unroll
    for (int j = 0; j < 8; j++) s += red[j];
    const float inv = 1.0f / s;

    a.x *= inv; a.y *= inv; a.z *= inv; a.w *= inv;
    b.x *= inv; b.y *= inv; b.z *= inv; b.w *= inv;
    p[tid] = a;
    p[tid + 256] = b;
}

// ---------------- tiled transpose: out[c][r] = in[r][c] ----------------
__global__ void __launch_bounds__(256)
transpose_k(const float* __restrict__ in, float* __restrict__ out,
            int R, int C, size_t sI, size_t sO)
{
    __shared__ float t[32][33];
    const float* ib = in + (size_t)blockIdx.z * sI;
    float*       ob = out + (size_t)blockIdx.z * sO;
    const int x0 = blockIdx.x * 32;
    const int y0 = blockIdx.y * 32;
    const int tx = threadIdx.x, ty = threadIdx.y;

#pragma unroll
    for (int i = ty; i < 32; i += 8)
        t[i][tx] = ib[(size_t)(y0 + i) * C + x0 + tx];
    __syncthreads();
#pragma unroll
    for (int i = ty; i < 32; i += 8)
        ob[(size_t)(x0 + i) * R + y0 + tx] = t[tx][i];
}

// ---------------- launcher ----------------
extern "C" void kernel_launch(void* const* d_in, const int* in_sizes, int n_in,
                              void* d_out, int out_size)
{
    const float* queries = (const float*)d_in[0];
    const float* keys    = (const float*)d_in[1];
    const float* values  = (const float*)d_in[2];
    const float* Wq      = (const float*)d_in[3];
    const float* bq      = (const float*)d_in[4];
    const float* Wk      = (const float*)d_in[5];
    const float* bk      = (const float*)d_in[6];
    const float* Wv      = (const float*)d_in[7];
    const float* bv      = (const float*)d_in[8];

    float* ctx  = (float*)d_out;                                // [B,Q,H]
    float* attn = (float*)d_out + (size_t)BNUM * QLEN * HID;    // [B,S,Q]

    float *qp, *kp, *vp, *vt, *st;
    cudaGetSymbolAddress((void**)&qp, g_Qp);
    cudaGetSymbolAddress((void**)&kp, g_Kp);
    cudaGetSymbolAddress((void**)&vp, g_Vp);
    cudaGetSymbolAddress((void**)&vt, g_Vt);
    cudaGetSymbolAddress((void**)&st, g_St);

    cudaFuncSetAttribute(gemm_fp16s,
                         cudaFuncAttributeMaxDynamicSharedMemorySize, GEMM_SMEM);

    const float scale = 0.03125f;   // 1/sqrt(1024)

    // 1) projections (batch folded into M), split fp16 (high precision)
    {
        dim3 g(HID / TN, (BNUM * QLEN) / TM, 1);
        gemm_fp16s<<<g, 256, GEMM_SMEM>>>(queries, Wq, qp, bq,
                                          BNUM * QLEN, HID, HID, 1.0f, 1, 0, 0, 0);
        gemm_fp16s<<<g, 256, GEMM_SMEM>>>(keys, Wk, kp, bk,
                                          BNUM * SLEN, HID, HID, 1.0f, 1, 0, 0, 0);
        gemm_fp16s<<<g, 256, GEMM_SMEM>>>(values, Wv, vp, bv,
                                          BNUM * SLEN, HID, HID, 1.0f, 1, 0, 0, 0);
    }

    // 2) Vt[b,h,s] = Vp[b,s,h]
    {
        dim3 g(HID / 32, SLEN / 32, BNUM);
        transpose_k<<<g, dim3(32, 8)>>>(vp, vt, SLEN, HID,
                                        (size_t)SLEN * HID, (size_t)SLEN * HID);
    }

    // 3) scores^T[b,q,s] = scale * Qp[b,q,:] . Kp[b,s,:]  (split fp16)
    {
        dim3 g(SLEN / TN, QLEN / TM, BNUM);
        gemm_fp16s<<<g, 256, GEMM_SMEM>>>(qp, kp, st, nullptr,
                                          QLEN, SLEN, HID, scale, 1,
                                          (size_t)QLEN * HID, (size_t)SLEN * HID,
                                          (size_t)QLEN * SLEN);
    }

    // 4) softmax over contiguous S axis of scores^T, in place -> attn^T
    softmax_rows<<<BNUM * QLEN, 256>>>(st);

    // 5) attn[b,s,q] = attn^T[b,q,s]  (required output)
    {
        dim3 g(SLEN / 32, QLEN / 32, BNUM);
        transpose_k<<<g, dim3(32, 8)>>>(st, attn, QLEN, SLEN,
                                        (size_t)QLEN * SLEN, (size_t)QLEN * SLEN);
    }

    // 6) ctx[b,q,h] = sum_s attn^T[b,q,s] * Vt[b,h,s]  (plain fp16: operands
    //    are softmax weights in [0,1] and values; rounding error ~4e-4)
    {
        dim3 g(HID / TN, QLEN / TM, BNUM);
        gemm_fp16s<<<g, 256, GEMM_SMEM>>>(st, vt, ctx, nullptr,
                                          QLEN, HID, SLEN, 1.0f, 0,
                                          (size_t)QLEN * SLEN, (size_t)SLEN * HID,
                                          (size_t)QLEN * HID);
    }
}

// round 5
// speedup vs baseline: 4.0597x; 1.4838x over previous
#include <cuda_runtime.h>
#include <cuda_fp16.h>
#include <cstdint>
#include <math.h>

#define HID   1024
#define BNUM  8
#define SLEN  2048
#define QLEN  2048

// ---------------- scratch (device globals: allocation-free) ----------------
__device__ float g_KM[(size_t)BNUM * SLEN * HID];   // keys * M        [B,S,H]
__device__ float g_Vp[(size_t)BNUM * SLEN * HID];   // projected V     [B,S,H]
__device__ float g_St[(size_t)BNUM * SLEN * QLEN];  // raw scores      [B,S,Q]
__device__ float g_Mt[(size_t)HID * HID];           // 32 * Wq^T Wk    [H,H]
__device__ float g_part[(size_t)BNUM * 8 * QLEN];   // softmax partial sums
__device__ float g_vrow[(size_t)BNUM * SLEN];       // keys * (Wk^T bq)
__device__ float g_vec[HID];
__device__ int   g_flag;

// ---------------- tile geometry ----------------
#define TM   128
#define TN   128
#define TKF  32              // K floats per mainloop iter (= 2 k16 steps)
#define ROWB 80              // NT: bytes per smem row (32+8 halves)
#define ROWT 272             // TN: bytes per smem row (128+8 halves)
#define TILE_B (128 * ROWB)        // 10240 B per tile (TN tile 8704 fits)
#define BUF_B  (4 * TILE_B)        // A_hi, A_lo, B_hi, B_lo
#define GEMM_SMEM (2 * BUF_B)      // 81920 B

// ---------------- PTX helpers ----------------
__device__ __forceinline__ uint32_t smem_u32(const void* p) {
    uint32_t a;
    asm("{ .reg .u64 t; cvta.to.shared.u64 t, %1; cvt.u32.u64 %0, t; }"
        : "=r"(a) : "l"(p));
    return a;
}
__device__ __forceinline__ void ldsm4(uint32_t* r, uint32_t addr) {
    asm volatile("ldmatrix.sync.aligned.m8n8.x4.shared.b16 {%0,%1,%2,%3}, [%4];"
                 : "=r"(r[0]), "=r"(r[1]), "=r"(r[2]), "=r"(r[3]) : "r"(addr));
}
__device__ __forceinline__ void ldsm4t(uint32_t* r, uint32_t addr) {
    asm volatile("ldmatrix.sync.aligned.m8n8.x4.trans.shared.b16 {%0,%1,%2,%3}, [%4];"
                 : "=r"(r[0]), "=r"(r[1]), "=r"(r[2]), "=r"(r[3]) : "r"(addr));
}
__device__ __forceinline__ void mma16816(float* c, const uint32_t* a,
                                         const uint32_t* b) {
    asm volatile(
        "mma.sync.aligned.m16n8k16.row.col.f32.f16.f16.f32 "
        "{%0,%1,%2,%3}, {%4,%5,%6,%7}, {%8,%9}, {%0,%1,%2,%3};"
        : "+f"(c[0]), "+f"(c[1]), "+f"(c[2]), "+f"(c[3])
        : "r"(a[0]), "r"(a[1]), "r"(a[2]), "r"(a[3]), "r"(b[0]), "r"(b[1]));
}

// convert float4 -> fp16 hi (and lo residual if SPLIT) and store 8B each
template <bool SPLIT>
__device__ __forceinline__ void cvt_sts(char* hi, char* lo, uint32_t off,
                                        float4 v) {
    __half2 h0 = __floats2half2_rn(v.x, v.y);
    __half2 h1 = __floats2half2_rn(v.z, v.w);
    *(uint2*)(hi + off) = make_uint2(*(uint32_t*)&h0, *(uint32_t*)&h1);
    if (SPLIT) {
        float2 f0 = __half22float2(h0), f1 = __half22float2(h1);
        __half2 l0 = __floats2half2_rn(v.x - f0.x, v.y - f0.y);
        __half2 l1 = __floats2half2_rn(v.z - f1.x, v.w - f1.y);
        *(uint2*)(lo + off) = make_uint2(*(uint32_t*)&l0, *(uint32_t*)&l1);
    }
}

// ---------------------------------------------------------------------------
// fp16(-split) tensor-core GEMM, 128x128x32 tiles, double buffered.
// TRANS=0 (NT): C[m,n] = alpha*sum_k A[m,k]*B[n,k] (+bias), A:[M,K] B:[N,K].
// TRANS=1 (TN): C[m,n] = alpha*sum_k A[k,m]*B[k,n] (+bias), A:[K,M] B:[K,N].
// SPLIT=1: two-term fp16 decomposition, 3 MMAs per fragment pair (eps~2^-22).
// ---------------------------------------------------------------------------
template <bool TRANS, bool SPLIT>
__device__ __forceinline__ void gemm_body(
    const float* __restrict__ A, const float* __restrict__ B,
    float* __restrict__ C, const float* __restrict__ bias,
    int M, int N, int K, int ldA, int ldB, float alpha,
    size_t sA, size_t sB, size_t sC)
{
    extern __shared__ char sm[];
    const uint32_t sb = smem_u32(sm);

    const int tid  = threadIdx.x;
    const int lane = tid & 31;
    const int w    = tid >> 5;
    const int wm   = w & 1;
    const int wn   = w >> 1;
    const int g    = lane >> 2;
    const int t    = lane & 3;

    const float* Ab = A + (size_t)blockIdx.z * sA;
    const float* Bb = B + (size_t)blockIdx.z * sB;
    float*       Cb = C + (size_t)blockIdx.z * sC;
    const int bm = blockIdx.y * TM;
    const int bn = blockIdx.x * TN;

    // NT ldmatrix address components (A non-trans / B non-trans)
    const int a_r  = ((lane >> 3) & 1) * 8 + (lane & 7);
    const int a_c8 = (lane >> 4) * 8;
    const int b_r  = (lane >> 4) * 8 + (lane & 7);
    const int b_c8 = ((lane >> 3) & 1) * 8;
    // TN trans-ldmatrix address components
    const int at_r  = (lane >> 4) * 8 + (lane & 7);          // k row
    const int at_c8 = ((lane >> 3) & 1) * 8;                 // m offset
    const int bt_r  = ((lane >> 3) & 1) * 8 + (lane & 7);    // k row
    const int bt_c8 = (lane >> 4) * 8;                       // n offset

    float acc[4][4][4];
#pragma unroll
    for (int i = 0; i < 4; i++)
#pragma unroll
        for (int j = 0; j < 4; j++)
#pragma unroll
            for (int e = 0; e < 4; e++) acc[i][j][e] = 0.0f;

    float4 ra[4], rb[4];
    const int NK = K / TKF;

    auto ldg_tiles = [&](int kt) {
        if (!TRANS) {
            const float* Ag = Ab + (size_t)bm * ldA + kt * TKF;
            const float* Bg = Bb + (size_t)bn * ldB + kt * TKF;
#pragma unroll
            for (int i = 0; i < 4; i++) {
                int f = tid + 256 * i;
                ra[i] = *(const float4*)(Ag + (size_t)(f >> 3) * ldA + (f & 7) * 4);
                rb[i] = *(const float4*)(Bg + (size_t)(f >> 3) * ldB + (f & 7) * 4);
            }
        } else {
            const float* Ag = Ab + (size_t)(kt * TKF) * ldA + bm;
            const float* Bg = Bb + (size_t)(kt * TKF) * ldB + bn;
#pragma unroll
            for (int i = 0; i < 4; i++) {
                int f = tid + 256 * i;
                ra[i] = *(const float4*)(Ag + (size_t)(f >> 5) * ldA + (f & 31) * 4);
                rb[i] = *(const float4*)(Bg + (size_t)(f >> 5) * ldB + (f & 31) * 4);
            }
        }
    };

    auto sts_tiles = [&](int p) {
        char* base = sm + p * BUF_B;
#pragma unroll
        for (int i = 0; i < 4; i++) {
            int f = tid + 256 * i;
            uint32_t off = TRANS ? (uint32_t)((f >> 5) * ROWT + (f & 31) * 8)
                                 : (uint32_t)((f >> 3) * ROWB + (f & 7) * 8);
            cvt_sts<SPLIT>(base, base + TILE_B, off, ra[i]);
            cvt_sts<SPLIT>(base + 2 * TILE_B, base + 3 * TILE_B, off, rb[i]);
        }
    };

    // prologue
    ldg_tiles(0);
    sts_tiles(0);
    __syncthreads();

    for (int kt = 0; kt < NK; kt++) {
        const int p = kt & 1;
        if (kt + 1 < NK) ldg_tiles(kt + 1);

        const uint32_t sa_hi = sb + p * BUF_B;
        const uint32_t sa_lo = sa_hi + TILE_B;
        const uint32_t sb_hi = sa_hi + 2 * TILE_B;
        const uint32_t sb_lo = sa_hi + 3 * TILE_B;

#pragma unroll
        for (int ks = 0; ks < 2; ks++) {
            const int k0 = ks * 16;

            uint32_t bh[8], bl[8];
#pragma unroll
            for (int j = 0; j < 2; j++) {
                if (!TRANS) {
                    uint32_t addr = (uint32_t)((wn * 32 + j * 16 + b_r) * ROWB +
                                               (k0 + b_c8) * 2);
                    ldsm4(bh + 4 * j, sb_hi + addr);
                    if (SPLIT) ldsm4(bl + 4 * j, sb_lo + addr);
                } else {
                    uint32_t addr = (uint32_t)((k0 + bt_r) * ROWT +
                                               (wn * 32 + j * 16 + bt_c8) * 2);
                    ldsm4t(bh + 4 * j, sb_hi + addr);
                    if (SPLIT) ldsm4t(bl + 4 * j, sb_lo + addr);
                }
            }

            uint32_t ah[4][4], al[4][4];
#pragma unroll
            for (int mf = 0; mf < 4; mf++) {
                if (!TRANS) {
                    uint32_t addr = (uint32_t)((wm * 64 + mf * 16 + a_r) * ROWB +
                                               (k0 + a_c8) * 2);
                    ldsm4(ah[mf], sa_hi + addr);
                    if (SPLIT) ldsm4(al[mf], sa_lo + addr);
                } else {
                    uint32_t addr = (uint32_t)((k0 + at_r) * ROWT +
                                               (wm * 64 + mf * 16 + at_c8) * 2);
                    ldsm4t(ah[mf], sa_hi + addr);
                    if (SPLIT) ldsm4t(al[mf], sa_lo + addr);
                }
            }

#pragma unroll
            for (int mf = 0; mf < 4; mf++)
#pragma unroll
                for (int nf = 0; nf < 4; nf++) {
                    mma16816(acc[mf][nf], ah[mf], bh + 2 * nf);
                    if (SPLIT) {
                        mma16816(acc[mf][nf], ah[mf], bl + 2 * nf);
                        mma16816(acc[mf][nf], al[mf], bh + 2 * nf);
                    }
                }
        }

        if (kt + 1 < NK) {
            sts_tiles(p ^ 1);
            __syncthreads();
        }
    }

    // epilogue
#pragma unroll
    for (int mf = 0; mf < 4; mf++) {
        const int row0 = bm + wm * 64 + mf * 16 + g;
        const int row1 = row0 + 8;
#pragma unroll
        for (int nf = 0; nf < 4; nf++) {
            const int col = bn + wn * 32 + nf * 8 + 2 * t;
            float bx = 0.0f, by = 0.0f;
            if (bias != nullptr) { bx = bias[col]; by = bias[col + 1]; }
            float2 o0, o1;
            o0.x = alpha * acc[mf][nf][0] + bx;
            o0.y = alpha * acc[mf][nf][1] + by;
            o1.x = alpha * acc[mf][nf][2] + bx;
            o1.y = alpha * acc[mf][nf][3] + by;
            *(float2*)(Cb + (size_t)row0 * N + col) = o0;
            *(float2*)(Cb + (size_t)row1 * N + col) = o1;
        }
    }
}

extern "C" __global__ void __launch_bounds__(256)
g_nt_s(const float* A, const float* B, float* C, const float* bias,
       int M, int N, int K, int ldA, int ldB, float alpha,
       size_t sA, size_t sB, size_t sC)
{ gemm_body<false, true>(A, B, C, bias, M, N, K, ldA, ldB, alpha, sA, sB, sC); }

extern "C" __global__ void __launch_bounds__(256)
g_tn_s(const float* A, const float* B, float* C, const float* bias,
       int M, int N, int K, int ldA, int ldB, float alpha,
       size_t sA, size_t sB, size_t sC)
{ gemm_body<true, true>(A, B, C, bias, M, N, K, ldA, ldB, alpha, sA, sB, sC); }

extern "C" __global__ void __launch_bounds__(256)
g_tn_p(const float* A, const float* B, float* C, const float* bias,
       int M, int N, int K, int ldA, int ldB, float alpha,
       size_t sA, size_t sB, size_t sC)
{ gemm_body<true, false>(A, B, C, bias, M, N, K, ldA, ldB, alpha, sA, sB, sC); }

// ---------------- bias rank-1 correction (general-bq path) ----------------
__global__ void bias_flag_k(const float* __restrict__ bq) {
    int any = 0;
    for (int i = threadIdx.x; i < HID; i += 256) any |= (bq[i] != 0.0f);
    int r = __syncthreads_or(any);
    if (threadIdx.x == 0) g_flag = r ? 1 : 0;
}
__global__ void vec_k(const float* __restrict__ Wk, const float* __restrict__ bq) {
    int i = blockIdx.x * 256 + threadIdx.x;
    float s = 0.0f;
    if (g_flag) {
        for (int o = 0; o < HID; o++) s += Wk[(size_t)o * HID + i] * bq[o];
    }
    g_vec[i] = s;
}
__global__ void vrow_k(const float* __restrict__ keys) {
    int r = blockIdx.x * 256 + threadIdx.x;
    float s = 0.0f;
    if (g_flag) {
        const float* kr = keys + (size_t)r * HID;
        for (int i = 0; i < HID; i++) s += kr[i] * g_vec[i];
    }
    g_vrow[r] = s;
}

// ---------------- 2-pass column softmax over s of St[B,S,Q] ----------------
// No max-subtraction (scores are O(1); exp range-safe; math identical).
__global__ void __launch_bounds__(256) softmax_p1(const float* __restrict__ St)
{
    const int b = blockIdx.y, sc = blockIdx.z;
    const int q = blockIdx.x * 256 + threadIdx.x;
    const float* base = St + ((size_t)b * SLEN + sc * 256) * QLEN + q;
    const float* vr = g_vrow + (size_t)b * SLEN + sc * 256;
    float sum = 0.0f;
#pragma unroll 4
    for (int i = 0; i < 256; i++)
        sum += __expf(base[(size_t)i * QLEN] + vr[i]);
    g_part[((size_t)b * 8 + sc) * QLEN + q] = sum;
}
__global__ void __launch_bounds__(256)
softmax_p2(const float* __restrict__ St, float* __restrict__ attn)
{
    const int b = blockIdx.y, sc = blockIdx.z;
    const int q = blockIdx.x * 256 + threadIdx.x;
    float tot = 0.0f;
#pragma unroll
    for (int j = 0; j < 8; j++) tot += g_part[((size_t)b * 8 + j) * QLEN + q];
    const float inv = 1.0f / tot;
    const float* base = St + ((size_t)b * SLEN + sc * 256) * QLEN + q;
    const float* vr = g_vrow + (size_t)b * SLEN + sc * 256;
    float* out = attn + ((size_t)b * SLEN + sc * 256) * QLEN + q;
#pragma unroll 4
    for (int i = 0; i < 256; i++)
        out[(size_t)i * QLEN] = __expf(base[(size_t)i * QLEN] + vr[i]) * inv;
}

// ---------------- launcher ----------------
extern "C" void kernel_launch(void* const* d_in, const int* in_sizes, int n_in,
                              void* d_out, int out_size)
{
    const float* queries = (const float*)d_in[0];
    const float* keys    = (const float*)d_in[1];
    const float* values  = (const float*)d_in[2];
    const float* Wq      = (const float*)d_in[3];
    const float* bq      = (const float*)d_in[4];
    const float* Wk      = (const float*)d_in[5];
    // d_in[6] = bk: only enters scores via per-q-constant terms -> cancels in softmax
    const float* Wv      = (const float*)d_in[7];
    const float* bv      = (const float*)d_in[8];

    float* ctx  = (float*)d_out;                                // [B,Q,H]
    float* attn = (float*)d_out + (size_t)BNUM * QLEN * HID;    // [B,S,Q]

    float *km, *vp, *st, *mt;
    cudaGetSymbolAddress((void**)&km, g_KM);
    cudaGetSymbolAddress((void**)&vp, g_Vp);
    cudaGetSymbolAddress((void**)&st, g_St);
    cudaGetSymbolAddress((void**)&mt, g_Mt);

    cudaFuncSetAttribute(g_nt_s, cudaFuncAttributeMaxDynamicSharedMemorySize, GEMM_SMEM);
    cudaFuncSetAttribute(g_tn_s, cudaFuncAttributeMaxDynamicSharedMemorySize, GEMM_SMEM);
    cudaFuncSetAttribute(g_tn_p, cudaFuncAttributeMaxDynamicSharedMemorySize, GEMM_SMEM);

    // 0) bias rank-1 correction chain (exactly zero work when bq == 0)
    bias_flag_k<<<1, 256>>>(bq);
    vec_k<<<HID / 256, 256>>>(Wk, bq);
    vrow_k<<<(BNUM * SLEN) / 256, 256>>>(keys);

    // 1) Mt = 32 * Wq^T Wk   (TN, split; x32 keeps fp16-split lo terms normal)
    g_tn_s<<<dim3(8, 8, 1), 256, GEMM_SMEM>>>(Wq, Wk, mt, nullptr,
                                              HID, HID, HID, HID, HID, 32.0f,
                                              0, 0, 0);

    // 2) V projection: Vp = values*Wv^T + bv  (NT, split, batch folded in M)
    g_nt_s<<<dim3(HID / TN, (BNUM * SLEN) / TM, 1), 256, GEMM_SMEM>>>(
        values, Wv, vp, bv, BNUM * SLEN, HID, HID, HID, HID, 1.0f, 0, 0, 0);

    // 3) KM = keys * M = (1/32) * keys * Mt^T-as-B  (NT, split)
    //    NT needs B[n,k] = M[k,n] = Mt[n,k]/32 -> pass B = Mt, alpha = 1/32.
    g_nt_s<<<dim3(HID / TN, (BNUM * SLEN) / TM, 1), 256, GEMM_SMEM>>>(
        keys, mt, km, nullptr, BNUM * SLEN, HID, HID, HID, HID, 0.03125f,
        0, 0, 0);

    // 4) raw scores St[b,s,q] = (1/32) * KM[b,s,:] . queries[b,q,:]  (NT, split)
    g_nt_s<<<dim3(QLEN / TN, SLEN / TM, BNUM), 256, GEMM_SMEM>>>(
        km, queries, st, nullptr, SLEN, QLEN, HID, HID, HID, 0.03125f,
        (size_t)SLEN * HID, (size_t)QLEN * HID, (size_t)SLEN * QLEN);

    // 5) softmax over s -> attn [B,S,Q] (output layout, no transpose)
    {
        dim3 g(QLEN / 256, BNUM, SLEN / 256);
        softmax_p1<<<g, 256>>>(st);
        softmax_p2<<<g, 256>>>(st, attn);
    }

    // 6) ctx[b,q,h] = sum_s attn[b,s,q] * Vp[b,s,h]  (TN, plain fp16)
    g_tn_p<<<dim3(HID / TN, QLEN / TM, BNUM), 256, GEMM_SMEM>>>(
        attn, vp, ctx, nullptr, QLEN, HID, SLEN, QLEN, HID, 1.0f,
        (size_t)SLEN * QLEN, (size_t)SLEN * HID, (size_t)QLEN * HID);
}

// round 6
// speedup vs baseline: 4.6919x; 1.1557x over previous
#include <cuda_runtime.h>
#include <cuda_fp16.h>
#include <cstdint>

#define HID   1024
#define BNUM  8
#define SLEN  2048
#define QLEN  2048

// ---------------- scratch: fp16 operand planes (allocation-free) -----------
__device__ __half g_Qh[(size_t)BNUM * QLEN * HID];
__device__ __half g_Ql[(size_t)BNUM * QLEN * HID];
__device__ __half g_Kh[(size_t)BNUM * SLEN * HID];
__device__ __half g_Kl[(size_t)BNUM * SLEN * HID];
__device__ __half g_Vh[(size_t)BNUM * SLEN * HID];
__device__ __half g_Vl[(size_t)BNUM * SLEN * HID];
__device__ __half g_Wqh[(size_t)HID * HID];
__device__ __half g_Wql[(size_t)HID * HID];
__device__ __half g_Wkh[(size_t)HID * HID];
__device__ __half g_Wkl[(size_t)HID * HID];
__device__ __half g_Wvh[(size_t)HID * HID];
__device__ __half g_Mth[(size_t)HID * HID];          // 32 * Wq^T Wk (hi)
__device__ __half g_KMh[(size_t)BNUM * SLEN * HID];  // keys*M (hi)
__device__ __half g_Vph[(size_t)BNUM * SLEN * HID];  // V proj (hi)
__device__ __half g_Ph [(size_t)BNUM * SLEN * QLEN]; // attn fp16
__device__ float  g_part[(size_t)BNUM * 16 * QLEN];  // col-sum partials
__device__ float  g_vrow[(size_t)BNUM * SLEN];       // keys * (Wk^T bq)
__device__ float  g_vec[HID];
__device__ int    g_flag;

// ---------------- geometry ----------------
#define TM   128
#define TN   128
#define TKF  32
#define SLOT 10240         // one plane-tile slot (max of NT 10240 / TN 8704)
#define PNT  80            // NT tile row pitch (64B data + 16B pad)
#define PTR  272           // TRANS tile row pitch (256B data + 16B pad)

// ---------------- PTX helpers ----------------
__device__ __forceinline__ uint32_t smem_u32(const void* p) {
    uint32_t a;
    asm("{ .reg .u64 t; cvta.to.shared.u64 t, %1; cvt.u32.u64 %0, t; }"
        : "=r"(a) : "l"(p));
    return a;
}
__device__ __forceinline__ void cp16(uint32_t s, const void* g) {
    asm volatile("cp.async.cg.shared.global [%0], [%1], 16;"
                 :: "r"(s), "l"(g));
}
__device__ __forceinline__ void cp_commit() {
    asm volatile("cp.async.commit_group;" ::: "memory");
}
template <int N_>
__device__ __forceinline__ void cp_wait() {
    asm volatile("cp.async.wait_group %0;" :: "n"(N_) : "memory");
}
__device__ __forceinline__ void ldsm4(uint32_t* r, uint32_t addr) {
    asm volatile("ldmatrix.sync.aligned.m8n8.x4.shared.b16 {%0,%1,%2,%3}, [%4];"
                 : "=r"(r[0]), "=r"(r[1]), "=r"(r[2]), "=r"(r[3]) : "r"(addr));
}
__device__ __forceinline__ void ldsm4t(uint32_t* r, uint32_t addr) {
    asm volatile("ldmatrix.sync.aligned.m8n8.x4.trans.shared.b16 {%0,%1,%2,%3}, [%4];"
                 : "=r"(r[0]), "=r"(r[1]), "=r"(r[2]), "=r"(r[3]) : "r"(addr));
}
__device__ __forceinline__ void mma16816(float* c, const uint32_t* a,
                                         const uint32_t* b) {
    asm volatile(
        "mma.sync.aligned.m16n8k16.row.col.f32.f16.f16.f32 "
        "{%0,%1,%2,%3}, {%4,%5,%6,%7}, {%8,%9}, {%0,%1,%2,%3};"
        : "+f"(c[0]), "+f"(c[1]), "+f"(c[2]), "+f"(c[3])
        : "r"(a[0]), "r"(a[1]), "r"(a[2]), "r"(a[3]), "r"(b[0]), "r"(b[1]));
}

// ---------------------------------------------------------------------------
// Unified fp16 tensor-core GEMM over pre-converted half planes.
// NT (TRANS=0): C[m,n] = alpha*sum_k A[m,k]*B[n,k], A:[M,K], B:[N,K]
// TN (TRANS=1): C[m,n] = alpha*sum_k A[k,m]*B[k,n], A:[K,M], B:[K,N]
// ASPL: A has a lo-residual plane (adds al*bh MMA).
// BSPL: B has a lo-residual plane (adds ah*bl MMA).
// EPI: 0 = f32 out (+bias); 1 = half out (+bias); 2 = exp epilogue
//      (adds g_vrow[row], writes exp to f32 out, col-sum partials to g_part).
// ---------------------------------------------------------------------------
template <bool TRANS, bool ASPL, bool BSPL, int EPI>
__device__ __forceinline__ void gbody(
    const __half* __restrict__ Ah, const __half* __restrict__ Al,
    const __half* __restrict__ Bh, const __half* __restrict__ Bl,
    float* __restrict__ Cf, __half* __restrict__ Ch,
    const float* __restrict__ bias,
    int M, int N, int K, int ldA, int ldB, float alpha,
    size_t sA, size_t sB, size_t sC)
{
    constexpr int NPA = ASPL ? 2 : 1;
    constexpr int NP  = NPA + (BSPL ? 2 : 1);
    constexpr int STG = NP * SLOT;

    extern __shared__ char sm[];
    const uint32_t sb = smem_u32(sm);

    const int tid  = threadIdx.x;
    const int lane = tid & 31;
    const int w    = tid >> 5;
    const int wm   = w & 1;
    const int wn   = w >> 1;
    const int g    = lane >> 2;
    const int t    = lane & 3;

    const size_t zz = blockIdx.z;
    const __half* Ahb = Ah + zz * sA;
    const __half* Alb = ASPL ? Al + zz * sA : nullptr;
    const __half* Bhb = Bh + zz * sB;
    const __half* Blb = BSPL ? Bl + zz * sB : nullptr;
    const int bm = blockIdx.y * TM;
    const int bn = blockIdx.x * TN;

    // fragment address components
    const int a_r   = ((lane >> 3) & 1) * 8 + (lane & 7);
    const int a_c8  = (lane >> 4) * 8;
    const int b_r   = (lane >> 4) * 8 + (lane & 7);
    const int b_c8  = ((lane >> 3) & 1) * 8;
    const int at_r  = (lane >> 4) * 8 + (lane & 7);
    const int at_c8 = ((lane >> 3) & 1) * 8;
    const int bt_r  = ((lane >> 3) & 1) * 8 + (lane & 7);
    const int bt_c8 = (lane >> 4) * 8;

    float acc[4][4][4];
#pragma unroll
    for (int i = 0; i < 4; i++)
#pragma unroll
        for (int j = 0; j < 4; j++)
#pragma unroll
            for (int e = 0; e < 4; e++) acc[i][j][e] = 0.0f;

    const int NK = K / TKF;

    auto issue = [&](int kt, int p) {
        const uint32_t st = sb + p * STG;
        if (!TRANS) {
#pragma unroll
            for (int j = 0; j < 2; j++) {
                const int idx = tid * 2 + j;
                const int r = idx >> 2, c = idx & 3;
                const uint32_t so = (uint32_t)(r * PNT + c * 16);
                const size_t goA = (size_t)(bm + r) * ldA + kt * TKF + c * 8;
                const size_t goB = (size_t)(bn + r) * ldB + kt * TKF + c * 8;
                cp16(st + so, Ahb + goA);
                if (ASPL) cp16(st + SLOT + so, Alb + goA);
                cp16(st + NPA * SLOT + so, Bhb + goB);
                if (BSPL) cp16(st + (NPA + 1) * SLOT + so, Blb + goB);
            }
        } else {
#pragma unroll
            for (int j = 0; j < 2; j++) {
                const int idx = tid * 2 + j;
                const int r = idx >> 4, c = idx & 15;
                const uint32_t so = (uint32_t)(r * PTR + c * 16);
                const size_t goA = (size_t)(kt * TKF + r) * ldA + bm + c * 8;
                const size_t goB = (size_t)(kt * TKF + r) * ldB + bn + c * 8;
                cp16(st + so, Ahb + goA);
                if (ASPL) cp16(st + SLOT + so, Alb + goA);
                cp16(st + NPA * SLOT + so, Bhb + goB);
                if (BSPL) cp16(st + (NPA + 1) * SLOT + so, Blb + goB);
            }
        }
    };

    issue(0, 0);
    cp_commit();

    for (int kt = 0; kt < NK; kt++) {
        const int p = kt & 1;
        if (kt + 1 < NK) {
            issue(kt + 1, p ^ 1);
            cp_commit();
            cp_wait<1>();
        } else {
            cp_wait<0>();
        }
        __syncthreads();

        const uint32_t sa_hi = sb + p * STG;
        const uint32_t sa_lo = sa_hi + SLOT;
        const uint32_t sb_hi = sa_hi + NPA * SLOT;
        const uint32_t sb_lo = sb_hi + SLOT;

#pragma unroll
        for (int ks = 0; ks < 2; ks++) {
            const int k0 = ks * 16;

            uint32_t bh[8], bl[8];
#pragma unroll
            for (int j = 0; j < 2; j++) {
                uint32_t addr;
                if (!TRANS) {
                    addr = (uint32_t)((wn * 32 + j * 16 + b_r) * PNT +
                                      (k0 + b_c8) * 2);
                    ldsm4(bh + 4 * j, sb_hi + addr);
                    if (BSPL) ldsm4(bl + 4 * j, sb_lo + addr);
                } else {
                    addr = (uint32_t)((k0 + bt_r) * PTR +
                                      (wn * 32 + j * 16 + bt_c8) * 2);
                    ldsm4t(bh + 4 * j, sb_hi + addr);
                    if (BSPL) ldsm4t(bl + 4 * j, sb_lo + addr);
                }
            }

            uint32_t ah[4][4], al[4][4];
#pragma unroll
            for (int mf = 0; mf < 4; mf++) {
                uint32_t addr;
                if (!TRANS) {
                    addr = (uint32_t)((wm * 64 + mf * 16 + a_r) * PNT +
                                      (k0 + a_c8) * 2);
                    ldsm4(ah[mf], sa_hi + addr);
                    if (ASPL) ldsm4(al[mf], sa_lo + addr);
                } else {
                    addr = (uint32_t)((k0 + at_r) * PTR +
                                      (wm * 64 + mf * 16 + at_c8) * 2);
                    ldsm4t(ah[mf], sa_hi + addr);
                    if (ASPL) ldsm4t(al[mf], sa_lo + addr);
                }
            }

#pragma unroll
            for (int mf = 0; mf < 4; mf++)
#pragma unroll
                for (int nf = 0; nf < 4; nf++) {
                    mma16816(acc[mf][nf], ah[mf], bh + 2 * nf);
                    if (ASPL) mma16816(acc[mf][nf], al[mf], bh + 2 * nf);
                    if (BSPL) mma16816(acc[mf][nf], ah[mf], bl + 2 * nf);
                }
        }
        __syncthreads();
    }

    // ---------------- epilogues ----------------
    if (EPI == 2) {
        // exp + unnormalized attn + column-sum partials (deterministic)
        float* Cb = Cf + zz * sC;
        const float* vr = g_vrow + zz * SLEN;
        float cs[8];
#pragma unroll
        for (int j = 0; j < 8; j++) cs[j] = 0.0f;

#pragma unroll
        for (int mf = 0; mf < 4; mf++) {
            const int row0 = bm + wm * 64 + mf * 16 + g;
            const int row1 = row0 + 8;
            const float v0 = vr[row0], v1 = vr[row1];
#pragma unroll
            for (int nf = 0; nf < 4; nf++) {
                const int col = bn + wn * 32 + nf * 8 + 2 * t;
                float e00 = __expf(alpha * acc[mf][nf][0] + v0);
                float e01 = __expf(alpha * acc[mf][nf][1] + v0);
                float e10 = __expf(alpha * acc[mf][nf][2] + v1);
                float e11 = __expf(alpha * acc[mf][nf][3] + v1);
                *(float2*)(Cb + (size_t)row0 * N + col) = make_float2(e00, e01);
                *(float2*)(Cb + (size_t)row1 * N + col) = make_float2(e10, e11);
                cs[nf * 2 + 0] += e00 + e10;
                cs[nf * 2 + 1] += e01 + e11;
            }
        }
        // reduce over g (lanes xor 4,8,16), then across the two wm warps
        float* red = (float*)sm;  // 256 floats
#pragma unroll
        for (int j = 0; j < 8; j++) {
#pragma unroll
            for (int o = 4; o <= 16; o <<= 1)
                cs[j] += __shfl_xor_sync(0xFFFFFFFFu, cs[j], o);
        }
        if (lane < 4) {
#pragma unroll
            for (int nf = 0; nf < 4; nf++) {
                red[wm * 128 + wn * 32 + nf * 8 + 2 * t + 0] = cs[nf * 2 + 0];
                red[wm * 128 + wn * 32 + nf * 8 + 2 * t + 1] = cs[nf * 2 + 1];
            }
        }
        __syncthreads();
        if (tid < 128) {
            g_part[((zz * 16) + blockIdx.y) * QLEN + bn + tid] =
                red[tid] + red[128 + tid];
        }
    } else {
#pragma unroll
        for (int mf = 0; mf < 4; mf++) {
            const int row0 = bm + wm * 64 + mf * 16 + g;
            const int row1 = row0 + 8;
#pragma unroll
            for (int nf = 0; nf < 4; nf++) {
                const int col = bn + wn * 32 + nf * 8 + 2 * t;
                float bx = 0.0f, by = 0.0f;
                if (bias != nullptr) { bx = bias[col]; by = bias[col + 1]; }
                float o0x = alpha * acc[mf][nf][0] + bx;
                float o0y = alpha * acc[mf][nf][1] + by;
                float o1x = alpha * acc[mf][nf][2] + bx;
                float o1y = alpha * acc[mf][nf][3] + by;
                if (EPI == 0) {
                    float* Cb = Cf + zz * sC;
                    *(float2*)(Cb + (size_t)row0 * N + col) = make_float2(o0x, o0y);
                    *(float2*)(Cb + (size_t)row1 * N + col) = make_float2(o1x, o1y);
                } else {
                    __half* Cb = Ch + zz * sC;
                    *(__half2*)(Cb + (size_t)row0 * N + col) =
                        __floats2half2_rn(o0x, o0y);
                    *(__half2*)(Cb + (size_t)row1 * N + col) =
                        __floats2half2_rn(o1x, o1y);
                }
            }
        }
    }
}

// instantiations
extern "C" __global__ void __launch_bounds__(256)
k_mt(const __half* Ah, const __half* Al, const __half* Bh, const __half* Bl,
     float* Cf, __half* Ch, const float* bias,
     int M, int N, int K, int ldA, int ldB, float alpha,
     size_t sA, size_t sB, size_t sC)
{ gbody<true, true, true, 1>(Ah, Al, Bh, Bl, Cf, Ch, bias, M, N, K, ldA, ldB,
                             alpha, sA, sB, sC); }

extern "C" __global__ void __launch_bounds__(256)
k_asp(const __half* Ah, const __half* Al, const __half* Bh, const __half* Bl,
      float* Cf, __half* Ch, const float* bias,
      int M, int N, int K, int ldA, int ldB, float alpha,
      size_t sA, size_t sB, size_t sC)
{ gbody<false, true, false, 1>(Ah, Al, Bh, Bl, Cf, Ch, bias, M, N, K, ldA, ldB,
                               alpha, sA, sB, sC); }

extern "C" __global__ void __launch_bounds__(256)
k_sc(const __half* Ah, const __half* Al, const __half* Bh, const __half* Bl,
     float* Cf, __half* Ch, const float* bias,
     int M, int N, int K, int ldA, int ldB, float alpha,
     size_t sA, size_t sB, size_t sC)
{ gbody<false, false, true, 2>(Ah, Al, Bh, Bl, Cf, Ch, bias, M, N, K, ldA, ldB,
                               alpha, sA, sB, sC); }

extern "C" __global__ void __launch_bounds__(256)
k_ctx(const __half* Ah, const __half* Al, const __half* Bh, const __half* Bl,
      float* Cf, __half* Ch, const float* bias,
      int M, int N, int K, int ldA, int ldB, float alpha,
      size_t sA, size_t sB, size_t sC)
{ gbody<true, false, false, 0>(Ah, Al, Bh, Bl, Cf, Ch, bias, M, N, K, ldA, ldB,
                               alpha, sA, sB, sC); }

// ---------------- f32 -> half(hi[,lo]) conversion ----------------
__global__ void __launch_bounds__(256)
cvt_split_k(const float4* __restrict__ in, uint2* __restrict__ hi,
            uint2* __restrict__ lo, int n4)
{
    for (int i = blockIdx.x * 256 + threadIdx.x; i < n4; i += gridDim.x * 256) {
        float4 v = in[i];
        __half2 h0 = __floats2half2_rn(v.x, v.y);
        __half2 h1 = __floats2half2_rn(v.z, v.w);
        hi[i] = make_uint2(*(uint32_t*)&h0, *(uint32_t*)&h1);
        float2 f0 = __half22float2(h0), f1 = __half22float2(h1);
        __half2 l0 = __floats2half2_rn(v.x - f0.x, v.y - f0.y);
        __half2 l1 = __floats2half2_rn(v.z - f1.x, v.w - f1.y);
        lo[i] = make_uint2(*(uint32_t*)&l0, *(uint32_t*)&l1);
    }
}
__global__ void __launch_bounds__(256)
cvt_hi_k(const float4* __restrict__ in, uint2* __restrict__ hi, int n4)
{
    for (int i = blockIdx.x * 256 + threadIdx.x; i < n4; i += gridDim.x * 256) {
        float4 v = in[i];
        __half2 h0 = __floats2half2_rn(v.x, v.y);
        __half2 h1 = __floats2half2_rn(v.z, v.w);
        hi[i] = make_uint2(*(uint32_t*)&h0, *(uint32_t*)&h1);
    }
}

// ---------------- bias rank-1 correction (general-bq path) ----------------
__global__ void bias_flag_k(const float* __restrict__ bq) {
    int any = 0;
    for (int i = threadIdx.x; i < HID; i += 256) any |= (bq[i] != 0.0f);
    int r = __syncthreads_or(any);
    if (threadIdx.x == 0) g_flag = r ? 1 : 0;
}
__global__ void vec_k(const float* __restrict__ Wk, const float* __restrict__ bq) {
    int i = blockIdx.x * 256 + threadIdx.x;
    float s = 0.0f;
    if (g_flag) {
        for (int o = 0; o < HID; o++) s += Wk[(size_t)o * HID + i] * bq[o];
    }
    g_vec[i] = s;
}
__global__ void vrow_k(const float* __restrict__ keys) {
    int r = blockIdx.x * 256 + threadIdx.x;
    float s = 0.0f;
    if (g_flag) {
        const float* kr = keys + (size_t)r * HID;
        for (int i = 0; i < HID; i++) s += kr[i] * g_vec[i];
    }
    g_vrow[r] = s;
}

// ---------------- normalize attn (f32 in place) + emit fp16 copy ----------
__global__ void __launch_bounds__(256)
scale_attn_k(float* __restrict__ attn, __half* __restrict__ ph)
{
    const int b = blockIdx.y, sc = blockIdx.z;
    const int q = blockIdx.x * 256 + threadIdx.x;
    float tot = 0.0f;
#pragma unroll
    for (int j = 0; j < 16; j++)
        tot += g_part[((size_t)b * 16 + j) * QLEN + q];
    const float inv = 1.0f / tot;
    const size_t base = ((size_t)b * SLEN + sc * 256) * QLEN + q;
#pragma unroll 4
    for (int i = 0; i < 256; i++) {
        float v = attn[base + (size_t)i * QLEN] * inv;
        attn[base + (size_t)i * QLEN] = v;
        ph[base + (size_t)i * QLEN] = __float2half(v);
    }
}

// ---------------- launcher ----------------
extern "C" void kernel_launch(void* const* d_in, const int* in_sizes, int n_in,
                              void* d_out, int out_size)
{
    const float* queries = (const float*)d_in[0];
    const float* keys    = (const float*)d_in[1];
    const float* values  = (const float*)d_in[2];
    const float* Wq      = (const float*)d_in[3];
    const float* bq      = (const float*)d_in[4];
    const float* Wk      = (const float*)d_in[5];
    // d_in[6] = bk: enters scores only via per-q constants -> cancels in softmax
    const float* Wv      = (const float*)d_in[7];
    const float* bv      = (const float*)d_in[8];

    float* ctx  = (float*)d_out;                                // [B,Q,H]
    float* attn = (float*)d_out + (size_t)BNUM * QLEN * HID;    // [B,S,Q]

    __half *qh, *ql, *kh, *kl, *vh, *vl, *wqh, *wql, *wkh, *wkl, *wvh;
    __half *mth, *kmh, *vph, *ph;
    cudaGetSymbolAddress((void**)&qh, g_Qh);
    cudaGetSymbolAddress((void**)&ql, g_Ql);
    cudaGetSymbolAddress((void**)&kh, g_Kh);
    cudaGetSymbolAddress((void**)&kl, g_Kl);
    cudaGetSymbolAddress((void**)&vh, g_Vh);
    cudaGetSymbolAddress((void**)&vl, g_Vl);
    cudaGetSymbolAddress((void**)&wqh, g_Wqh);
    cudaGetSymbolAddress((void**)&wql, g_Wql);
    cudaGetSymbolAddress((void**)&wkh, g_Wkh);
    cudaGetSymbolAddress((void**)&wkl, g_Wkl);
    cudaGetSymbolAddress((void**)&wvh, g_Wvh);
    cudaGetSymbolAddress((void**)&mth, g_Mth);
    cudaGetSymbolAddress((void**)&kmh, g_KMh);
    cudaGetSymbolAddress((void**)&vph, g_Vph);
    cudaGetSymbolAddress((void**)&ph, g_Ph);

    static bool attr_done = false;
    if (!attr_done) {
        cudaFuncSetAttribute(k_mt,  cudaFuncAttributeMaxDynamicSharedMemorySize, 2 * 4 * SLOT);
        cudaFuncSetAttribute(k_asp, cudaFuncAttributeMaxDynamicSharedMemorySize, 2 * 3 * SLOT);
        cudaFuncSetAttribute(k_sc,  cudaFuncAttributeMaxDynamicSharedMemorySize, 2 * 3 * SLOT);
        cudaFuncSetAttribute(k_ctx, cudaFuncAttributeMaxDynamicSharedMemorySize, 2 * 2 * SLOT);
        attr_done = true;
    }

    const int nBig4 = (BNUM * SLEN * HID) / 4;   // 4.19M float4s
    const int nW4   = (HID * HID) / 4;

    // 0) bias rank-1 chain (zero-work when bq == 0; keeps bq generality)
    bias_flag_k<<<1, 256>>>(bq);
    vec_k<<<HID / 256, 256>>>(Wk, bq);
    vrow_k<<<(BNUM * SLEN) / 256, 256>>>(keys);

    // 1) pre-convert operands to half planes
    cvt_split_k<<<2048, 256>>>((const float4*)queries, (uint2*)qh, (uint2*)ql, nBig4);
    cvt_split_k<<<2048, 256>>>((const float4*)keys,    (uint2*)kh, (uint2*)kl, nBig4);
    cvt_split_k<<<2048, 256>>>((const float4*)values,  (uint2*)vh, (uint2*)vl, nBig4);
    cvt_split_k<<<1024, 256>>>((const float4*)Wq, (uint2*)wqh, (uint2*)wql, nW4);
    cvt_split_k<<<1024, 256>>>((const float4*)Wk, (uint2*)wkh, (uint2*)wkl, nW4);
    cvt_hi_k<<<1024, 256>>>((const float4*)Wv, (uint2*)wvh, nW4);

    // 2) Mt = 32 * Wq^T Wk  (TN, full split, half out)
    k_mt<<<dim3(8, 8, 1), 256, 2 * 4 * SLOT>>>(
        wqh, wql, wkh, wkl, nullptr, mth, nullptr,
        HID, HID, HID, HID, HID, 32.0f, 0, 0, 0);

    // 3) Vp = values*Wv^T + bv  (NT, A-split, half out)
    k_asp<<<dim3(HID / TN, (BNUM * SLEN) / TM, 1), 256, 2 * 3 * SLOT>>>(
        vh, vl, wvh, nullptr, nullptr, vph, bv,
        BNUM * SLEN, HID, HID, HID, HID, 1.0f, 0, 0, 0);

    // 4) KM = keys*M = (1/32)*keys*Mt^T-as-B  (NT, A-split, half out)
    k_asp<<<dim3(HID / TN, (BNUM * SLEN) / TM, 1), 256, 2 * 3 * SLOT>>>(
        kh, kl, mth, nullptr, nullptr, kmh, nullptr,
        BNUM * SLEN, HID, HID, HID, HID, 0.03125f, 0, 0, 0);

    // 5) attn_unnorm[b,s,q] = exp((1/32)*KM[b,s,:].q[b,q,:] + vrow) + partials
    k_sc<<<dim3(QLEN / TN, SLEN / TM, BNUM), 256, 2 * 3 * SLOT>>>(
        kmh, nullptr, qh, ql, attn, nullptr, nullptr,
        SLEN, QLEN, HID, HID, HID, 0.03125f,
        (size_t)SLEN * HID, (size_t)QLEN * HID, (size_t)SLEN * QLEN);

    // 6) normalize -> attn f32 (output) + attn fp16 (for ctx)
    scale_attn_k<<<dim3(QLEN / 256, BNUM, SLEN / 256), 256>>>(attn, ph);

    // 7) ctx[b,q,h] = sum_s attn[b,s,q]*Vp[b,s,h]  (TN, plain fp16)
    k_ctx<<<dim3(HID / TN, QLEN / TM, BNUM), 256, 2 * 2 * SLOT>>>(
        ph, nullptr, vph, nullptr, ctx, nullptr, nullptr,
        QLEN, HID, SLEN, QLEN, HID, 1.0f,
        (size_t)SLEN * QLEN, (size_t)SLEN * HID, (size_t)QLEN * HID);
}

// round 7
// speedup vs baseline: 6.0899x; 1.2980x over previous
#include <cuda_runtime.h>
#include <cuda_fp16.h>
#include <cstdint>

#define HID   1024
#define BNUM  8
#define SLEN  2048
#define QLEN  2048

// ---------------- scratch: fp16 operand planes (allocation-free) -----------
__device__ __half g_Qh[(size_t)BNUM * QLEN * HID];
__device__ __half g_Kh[(size_t)BNUM * SLEN * HID];
__device__ __half g_Vh[(size_t)BNUM * SLEN * HID];
__device__ __half g_Wqh[(size_t)HID * HID];
__device__ __half g_Wql[(size_t)HID * HID];
__device__ __half g_Wkh[(size_t)HID * HID];
__device__ __half g_Wkl[(size_t)HID * HID];
__device__ __half g_Wvh[(size_t)HID * HID];
__device__ __half g_Mth[(size_t)HID * HID];          // 32 * Wq^T Wk (hi)
__device__ __half g_KMh[(size_t)BNUM * SLEN * HID];  // keys*M (hi)
__device__ __half g_Vph[(size_t)BNUM * SLEN * HID];  // V proj (hi)
__device__ __half g_Ph [(size_t)BNUM * SLEN * QLEN]; // attn fp16
__device__ float  g_part[(size_t)BNUM * 16 * QLEN];  // col-sum partials
__device__ float  g_vrow[(size_t)BNUM * SLEN];       // keys * (Wk^T bq)
__device__ float  g_vec[HID];
__device__ int    g_flag;

// ---------------- geometry ----------------
#define TM   128
#define TN   128
#define TKF  32
#define SLOT 10240         // one plane-tile slot (max of NT 10240 / TN 8704)
#define PNT  80            // NT tile row pitch (64B data + 16B pad)
#define PTR  272           // TRANS tile row pitch (256B data + 16B pad)

// ---------------- PTX helpers ----------------
__device__ __forceinline__ uint32_t smem_u32(const void* p) {
    uint32_t a;
    asm("{ .reg .u64 t; cvta.to.shared.u64 t, %1; cvt.u32.u64 %0, t; }"
        : "=r"(a) : "l"(p));
    return a;
}
__device__ __forceinline__ void cp16(uint32_t s, const void* g) {
    asm volatile("cp.async.cg.shared.global [%0], [%1], 16;"
                 :: "r"(s), "l"(g));
}
__device__ __forceinline__ void cp_commit() {
    asm volatile("cp.async.commit_group;" ::: "memory");
}
template <int N_>
__device__ __forceinline__ void cp_wait() {
    asm volatile("cp.async.wait_group %0;" :: "n"(N_) : "memory");
}
__device__ __forceinline__ void ldsm4(uint32_t* r, uint32_t addr) {
    asm volatile("ldmatrix.sync.aligned.m8n8.x4.shared.b16 {%0,%1,%2,%3}, [%4];"
                 : "=r"(r[0]), "=r"(r[1]), "=r"(r[2]), "=r"(r[3]) : "r"(addr));
}
__device__ __forceinline__ void ldsm4t(uint32_t* r, uint32_t addr) {
    asm volatile("ldmatrix.sync.aligned.m8n8.x4.trans.shared.b16 {%0,%1,%2,%3}, [%4];"
                 : "=r"(r[0]), "=r"(r[1]), "=r"(r[2]), "=r"(r[3]) : "r"(addr));
}
__device__ __forceinline__ void mma16816(float* c, const uint32_t* a,
                                         const uint32_t* b) {
    asm volatile(
        "mma.sync.aligned.m16n8k16.row.col.f32.f16.f16.f32 "
        "{%0,%1,%2,%3}, {%4,%5,%6,%7}, {%8,%9}, {%0,%1,%2,%3};"
        : "+f"(c[0]), "+f"(c[1]), "+f"(c[2]), "+f"(c[3])
        : "r"(a[0]), "r"(a[1]), "r"(a[2]), "r"(a[3]), "r"(b[0]), "r"(b[1]));
}

// ---------------------------------------------------------------------------
// Unified fp16 tensor-core GEMM over pre-converted half planes.
// NT (TRANS=0): C[m,n] = alpha*sum_k A[m,k]*B[n,k], A:[M,K], B:[N,K]
// TN (TRANS=1): C[m,n] = alpha*sum_k A[k,m]*B[k,n], A:[K,M], B:[K,N]
// ASPL/BSPL: lo-residual planes (extra MMA each).
// EPI: 0 = f32 out (+bias); 1 = half out (+bias); 2 = exp epilogue
//      (adds g_vrow[row], writes exp to f32 out, col-sum partials to g_part).
// STAGES: cp.async pipeline depth (one __syncthreads per k-iter).
// ---------------------------------------------------------------------------
template <bool TRANS, bool ASPL, bool BSPL, int EPI, int STAGES>
__device__ __forceinline__ void gbody(
    const __half* __restrict__ Ah, const __half* __restrict__ Al,
    const __half* __restrict__ Bh, const __half* __restrict__ Bl,
    float* __restrict__ Cf, __half* __restrict__ Ch,
    const float* __restrict__ bias,
    int M, int N, int K, int ldA, int ldB, float alpha,
    size_t sA, size_t sB, size_t sC)
{
    constexpr int NPA = ASPL ? 2 : 1;
    constexpr int NP  = NPA + (BSPL ? 2 : 1);
    constexpr int STG = NP * SLOT;

    extern __shared__ char sm[];
    const uint32_t sb = smem_u32(sm);

    const int tid  = threadIdx.x;
    const int lane = tid & 31;
    const int w    = tid >> 5;
    const int wm   = w & 1;
    const int wn   = w >> 1;
    const int g    = lane >> 2;
    const int t    = lane & 3;

    const size_t zz = blockIdx.z;
    const __half* Ahb = Ah + zz * sA;
    const __half* Alb = ASPL ? Al + zz * sA : nullptr;
    const __half* Bhb = Bh + zz * sB;
    const __half* Blb = BSPL ? Bl + zz * sB : nullptr;
    const int bm = blockIdx.y * TM;
    const int bn = blockIdx.x * TN;

    // fragment address components
    const int a_r   = ((lane >> 3) & 1) * 8 + (lane & 7);
    const int a_c8  = (lane >> 4) * 8;
    const int b_r   = (lane >> 4) * 8 + (lane & 7);
    const int b_c8  = ((lane >> 3) & 1) * 8;
    const int at_r  = (lane >> 4) * 8 + (lane & 7);
    const int at_c8 = ((lane >> 3) & 1) * 8;
    const int bt_r  = ((lane >> 3) & 1) * 8 + (lane & 7);
    const int bt_c8 = (lane >> 4) * 8;

    float acc[4][4][4];
#pragma unroll
    for (int i = 0; i < 4; i++)
#pragma unroll
        for (int j = 0; j < 4; j++)
#pragma unroll
            for (int e = 0; e < 4; e++) acc[i][j][e] = 0.0f;

    const int NK = K / TKF;

    auto issue = [&](int kt, int p) {
        const uint32_t st = sb + p * STG;
        if (!TRANS) {
#pragma unroll
            for (int j = 0; j < 2; j++) {
                const int idx = tid * 2 + j;
                const int r = idx >> 2, c = idx & 3;
                const uint32_t so = (uint32_t)(r * PNT + c * 16);
                const size_t goA = (size_t)(bm + r) * ldA + kt * TKF + c * 8;
                const size_t goB = (size_t)(bn + r) * ldB + kt * TKF + c * 8;
                cp16(st + so, Ahb + goA);
                if (ASPL) cp16(st + SLOT + so, Alb + goA);
                cp16(st + NPA * SLOT + so, Bhb + goB);
                if (BSPL) cp16(st + (NPA + 1) * SLOT + so, Blb + goB);
            }
        } else {
#pragma unroll
            for (int j = 0; j < 2; j++) {
                const int idx = tid * 2 + j;
                const int r = idx >> 4, c = idx & 15;
                const uint32_t so = (uint32_t)(r * PTR + c * 16);
                const size_t goA = (size_t)(kt * TKF + r) * ldA + bm + c * 8;
                const size_t goB = (size_t)(kt * TKF + r) * ldB + bn + c * 8;
                cp16(st + so, Ahb + goA);
                if (ASPL) cp16(st + SLOT + so, Alb + goA);
                cp16(st + NPA * SLOT + so, Bhb + goB);
                if (BSPL) cp16(st + (NPA + 1) * SLOT + so, Blb + goB);
            }
        }
    };

    // prologue: fill STAGES-1 buffers, one commit group per tile
#pragma unroll
    for (int s = 0; s < STAGES - 1; s++) {
        if (s < NK) issue(s, s);
        cp_commit();
    }

    for (int kt = 0; kt < NK; kt++) {
        const int p = kt % STAGES;

        cp_wait<STAGES - 2>();   // tile kt resident
        __syncthreads();         // also guards reuse of buffer being refilled

        // refill the buffer freed at the previous iteration
        if (kt + STAGES - 1 < NK) issue(kt + STAGES - 1, (kt + STAGES - 1) % STAGES);
        cp_commit();             // keep group numbering aligned (may be empty)

        const uint32_t sa_hi = sb + p * STG;
        const uint32_t sa_lo = sa_hi + SLOT;
        const uint32_t sb_hi = sa_hi + NPA * SLOT;
        const uint32_t sb_lo = sb_hi + SLOT;

#pragma unroll
        for (int ks = 0; ks < 2; ks++) {
            const int k0 = ks * 16;

            uint32_t bh[8], bl[8];
#pragma unroll
            for (int j = 0; j < 2; j++) {
                uint32_t addr;
                if (!TRANS) {
                    addr = (uint32_t)((wn * 32 + j * 16 + b_r) * PNT +
                                      (k0 + b_c8) * 2);
                    ldsm4(bh + 4 * j, sb_hi + addr);
                    if (BSPL) ldsm4(bl + 4 * j, sb_lo + addr);
                } else {
                    addr = (uint32_t)((k0 + bt_r) * PTR +
                                      (wn * 32 + j * 16 + bt_c8) * 2);
                    ldsm4t(bh + 4 * j, sb_hi + addr);
                    if (BSPL) ldsm4t(bl + 4 * j, sb_lo + addr);
                }
            }

            uint32_t ah[4][4], al[4][4];
#pragma unroll
            for (int mf = 0; mf < 4; mf++) {
                uint32_t addr;
                if (!TRANS) {
                    addr = (uint32_t)((wm * 64 + mf * 16 + a_r) * PNT +
                                      (k0 + a_c8) * 2);
                    ldsm4(ah[mf], sa_hi + addr);
                    if (ASPL) ldsm4(al[mf], sa_lo + addr);
                } else {
                    addr = (uint32_t)((k0 + at_r) * PTR +
                                      (wm * 64 + mf * 16 + at_c8) * 2);
                    ldsm4t(ah[mf], sa_hi + addr);
                    if (ASPL) ldsm4t(al[mf], sa_lo + addr);
                }
            }

#pragma unroll
            for (int mf = 0; mf < 4; mf++)
#pragma unroll
                for (int nf = 0; nf < 4; nf++) {
                    mma16816(acc[mf][nf], ah[mf], bh + 2 * nf);
                    if (ASPL) mma16816(acc[mf][nf], al[mf], bh + 2 * nf);
                    if (BSPL) mma16816(acc[mf][nf], ah[mf], bl + 2 * nf);
                }
        }
        // no trailing sync: next iteration's sync (after cp_wait) guards reuse
    }

    // ---------------- epilogues ----------------
    if (EPI == 2) {
        __syncthreads();  // smem 'red' reuses pipeline buffers
        float* Cb = Cf + zz * sC;
        const float* vr = g_vrow + zz * SLEN;
        float cs[8];
#pragma unroll
        for (int j = 0; j < 8; j++) cs[j] = 0.0f;

#pragma unroll
        for (int mf = 0; mf < 4; mf++) {
            const int row0 = bm + wm * 64 + mf * 16 + g;
            const int row1 = row0 + 8;
            const float v0 = vr[row0], v1 = vr[row1];
#pragma unroll
            for (int nf = 0; nf < 4; nf++) {
                const int col = bn + wn * 32 + nf * 8 + 2 * t;
                float e00 = __expf(alpha * acc[mf][nf][0] + v0);
                float e01 = __expf(alpha * acc[mf][nf][1] + v0);
                float e10 = __expf(alpha * acc[mf][nf][2] + v1);
                float e11 = __expf(alpha * acc[mf][nf][3] + v1);
                *(float2*)(Cb + (size_t)row0 * N + col) = make_float2(e00, e01);
                *(float2*)(Cb + (size_t)row1 * N + col) = make_float2(e10, e11);
                cs[nf * 2 + 0] += e00 + e10;
                cs[nf * 2 + 1] += e01 + e11;
            }
        }
        float* red = (float*)sm;  // 256 floats
#pragma unroll
        for (int j = 0; j < 8; j++) {
#pragma unroll
            for (int o = 4; o <= 16; o <<= 1)
                cs[j] += __shfl_xor_sync(0xFFFFFFFFu, cs[j], o);
        }
        if (lane < 4) {
#pragma unroll
            for (int nf = 0; nf < 4; nf++) {
                red[wm * 128 + wn * 32 + nf * 8 + 2 * t + 0] = cs[nf * 2 + 0];
                red[wm * 128 + wn * 32 + nf * 8 + 2 * t + 1] = cs[nf * 2 + 1];
            }
        }
        __syncthreads();
        if (tid < 128) {
            g_part[((zz * 16) + blockIdx.y) * QLEN + bn + tid] =
                red[tid] + red[128 + tid];
        }
    } else {
#pragma unroll
        for (int mf = 0; mf < 4; mf++) {
            const int row0 = bm + wm * 64 + mf * 16 + g;
            const int row1 = row0 + 8;
#pragma unroll
            for (int nf = 0; nf < 4; nf++) {
                const int col = bn + wn * 32 + nf * 8 + 2 * t;
                float bx = 0.0f, by = 0.0f;
                if (bias != nullptr) { bx = bias[col]; by = bias[col + 1]; }
                float o0x = alpha * acc[mf][nf][0] + bx;
                float o0y = alpha * acc[mf][nf][1] + by;
                float o1x = alpha * acc[mf][nf][2] + bx;
                float o1y = alpha * acc[mf][nf][3] + by;
                if (EPI == 0) {
                    float* Cb = Cf + zz * sC;
                    *(float2*)(Cb + (size_t)row0 * N + col) = make_float2(o0x, o0y);
                    *(float2*)(Cb + (size_t)row1 * N + col) = make_float2(o1x, o1y);
                } else {
                    __half* Cb = Ch + zz * sC;
                    *(__half2*)(Cb + (size_t)row0 * N + col) =
                        __floats2half2_rn(o0x, o0y);
                    *(__half2*)(Cb + (size_t)row1 * N + col) =
                        __floats2half2_rn(o1x, o1y);
                }
            }
        }
    }
}

// instantiations
extern "C" __global__ void __launch_bounds__(256)
k_mt(const __half* Ah, const __half* Al, const __half* Bh, const __half* Bl,
     float* Cf, __half* Ch, const float* bias,
     int M, int N, int K, int ldA, int ldB, float alpha,
     size_t sA, size_t sB, size_t sC)
{ gbody<true, true, true, 1, 2>(Ah, Al, Bh, Bl, Cf, Ch, bias, M, N, K, ldA, ldB,
                                alpha, sA, sB, sC); }

extern "C" __global__ void __launch_bounds__(256)
k_nth(const __half* Ah, const __half* Al, const __half* Bh, const __half* Bl,
      float* Cf, __half* Ch, const float* bias,
      int M, int N, int K, int ldA, int ldB, float alpha,
      size_t sA, size_t sB, size_t sC)
{ gbody<false, false, false, 1, 3>(Ah, Al, Bh, Bl, Cf, Ch, bias, M, N, K, ldA,
                                   ldB, alpha, sA, sB, sC); }

extern "C" __global__ void __launch_bounds__(256)
k_sc(const __half* Ah, const __half* Al, const __half* Bh, const __half* Bl,
     float* Cf, __half* Ch, const float* bias,
     int M, int N, int K, int ldA, int ldB, float alpha,
     size_t sA, size_t sB, size_t sC)
{ gbody<false, false, false, 2, 3>(Ah, Al, Bh, Bl, Cf, Ch, bias, M, N, K, ldA,
                                   ldB, alpha, sA, sB, sC); }

extern "C" __global__ void __launch_bounds__(256)
k_ctx(const __half* Ah, const __half* Al, const __half* Bh, const __half* Bl,
      float* Cf, __half* Ch, const float* bias,
      int M, int N, int K, int ldA, int ldB, float alpha,
      size_t sA, size_t sB, size_t sC)
{ gbody<true, false, false, 0, 3>(Ah, Al, Bh, Bl, Cf, Ch, bias, M, N, K, ldA,
                                  ldB, alpha, sA, sB, sC); }

// ---------------- f32 -> half(hi[,lo]) conversion ----------------
__global__ void __launch_bounds__(256)
cvt_split_k(const float4* __restrict__ in, uint2* __restrict__ hi,
            uint2* __restrict__ lo, int n4)
{
    for (int i = blockIdx.x * 256 + threadIdx.x; i < n4; i += gridDim.x * 256) {
        float4 v = in[i];
        __half2 h0 = __floats2half2_rn(v.x, v.y);
        __half2 h1 = __floats2half2_rn(v.z, v.w);
        hi[i] = make_uint2(*(uint32_t*)&h0, *(uint32_t*)&h1);
        float2 f0 = __half22float2(h0), f1 = __half22float2(h1);
        __half2 l0 = __floats2half2_rn(v.x - f0.x, v.y - f0.y);
        __half2 l1 = __floats2half2_rn(v.z - f1.x, v.w - f1.y);
        lo[i] = make_uint2(*(uint32_t*)&l0, *(uint32_t*)&l1);
    }
}
__global__ void __launch_bounds__(256)
cvt_hi_k(const float4* __restrict__ in, uint2* __restrict__ hi, int n4)
{
    for (int i = blockIdx.x * 256 + threadIdx.x; i < n4; i += gridDim.x * 256) {
        float4 v = in[i];
        __half2 h0 = __floats2half2_rn(v.x, v.y);
        __half2 h1 = __floats2half2_rn(v.z, v.w);
        hi[i] = make_uint2(*(uint32_t*)&h0, *(uint32_t*)&h1);
    }
}

// ---------------- bias rank-1 correction (general-bq path) ----------------
__global__ void bias_flag_k(const float* __restrict__ bq) {
    int any = 0;
    for (int i = threadIdx.x; i < HID; i += 256) any |= (bq[i] != 0.0f);
    int r = __syncthreads_or(any);
    if (threadIdx.x == 0) g_flag = r ? 1 : 0;
}
__global__ void vec_k(const float* __restrict__ Wk, const float* __restrict__ bq) {
    int i = blockIdx.x * 256 + threadIdx.x;
    float s = 0.0f;
    if (g_flag) {
        for (int o = 0; o < HID; o++) s += Wk[(size_t)o * HID + i] * bq[o];
    }
    g_vec[i] = s;
}
__global__ void vrow_k(const float* __restrict__ keys) {
    int r = blockIdx.x * 256 + threadIdx.x;
    float s = 0.0f;
    if (g_flag) {
        const float* kr = keys + (size_t)r * HID;
        for (int i = 0; i < HID; i++) s += kr[i] * g_vec[i];
    }
    g_vrow[r] = s;
}

// ---------------- normalize attn (f32 in place) + emit fp16 copy ----------
__global__ void __launch_bounds__(256)
scale_attn_k(float* __restrict__ attn, __half* __restrict__ ph)
{
    const int b = blockIdx.y, sc = blockIdx.z;
    const int q = blockIdx.x * 256 + threadIdx.x;
    float tot = 0.0f;
#pragma unroll
    for (int j = 0; j < 16; j++)
        tot += g_part[((size_t)b * 16 + j) * QLEN + q];
    const float inv = 1.0f / tot;
    const size_t base = ((size_t)b * SLEN + sc * 256) * QLEN + q;
#pragma unroll 4
    for (int i = 0; i < 256; i++) {
        float v = attn[base + (size_t)i * QLEN] * inv;
        attn[base + (size_t)i * QLEN] = v;
        ph[base + (size_t)i * QLEN] = __float2half(v);
    }
}

// ---------------- launcher ----------------
extern "C" void kernel_launch(void* const* d_in, const int* in_sizes, int n_in,
                              void* d_out, int out_size)
{
    const float* queries = (const float*)d_in[0];
    const float* keys    = (const float*)d_in[1];
    const float* values  = (const float*)d_in[2];
    const float* Wq      = (const float*)d_in[3];
    const float* bq      = (const float*)d_in[4];
    const float* Wk      = (const float*)d_in[5];
    // d_in[6] = bk: enters scores only via per-q constants -> cancels in softmax
    const float* Wv      = (const float*)d_in[7];
    const float* bv      = (const float*)d_in[8];

    float* ctx  = (float*)d_out;                                // [B,Q,H]
    float* attn = (float*)d_out + (size_t)BNUM * QLEN * HID;    // [B,S,Q]

    __half *qh, *kh, *vh, *wqh, *wql, *wkh, *wkl, *wvh;
    __half *mth, *kmh, *vph, *ph;
    cudaGetSymbolAddress((void**)&qh, g_Qh);
    cudaGetSymbolAddress((void**)&kh, g_Kh);
    cudaGetSymbolAddress((void**)&vh, g_Vh);
    cudaGetSymbolAddress((void**)&wqh, g_Wqh);
    cudaGetSymbolAddress((void**)&wql, g_Wql);
    cudaGetSymbolAddress((void**)&wkh, g_Wkh);
    cudaGetSymbolAddress((void**)&wkl, g_Wkl);
    cudaGetSymbolAddress((void**)&wvh, g_Wvh);
    cudaGetSymbolAddress((void**)&mth, g_Mth);
    cudaGetSymbolAddress((void**)&kmh, g_KMh);
    cudaGetSymbolAddress((void**)&vph, g_Vph);
    cudaGetSymbolAddress((void**)&ph, g_Ph);

    static bool attr_done = false;
    if (!attr_done) {
        cudaFuncSetAttribute(k_mt,  cudaFuncAttributeMaxDynamicSharedMemorySize, 2 * 4 * SLOT);
        cudaFuncSetAttribute(k_nth, cudaFuncAttributeMaxDynamicSharedMemorySize, 3 * 2 * SLOT);
        cudaFuncSetAttribute(k_sc,  cudaFuncAttributeMaxDynamicSharedMemorySize, 3 * 2 * SLOT);
        cudaFuncSetAttribute(k_ctx, cudaFuncAttributeMaxDynamicSharedMemorySize, 3 * 2 * SLOT);
        attr_done = true;
    }

    const int nBig4 = (BNUM * SLEN * HID) / 4;
    const int nW4   = (HID * HID) / 4;

    // 0) bias rank-1 chain (zero-work when bq == 0; keeps bq generality)
    bias_flag_k<<<1, 256>>>(bq);
    vec_k<<<HID / 256, 256>>>(Wk, bq);
    vrow_k<<<(BNUM * SLEN) / 256, 256>>>(keys);

    // 1) weight conversions (Wq/Wk split for exact Mt; Wv hi-only)
    cvt_split_k<<<1024, 256>>>((const float4*)Wq, (uint2*)wqh, (uint2*)wql, nW4);
    cvt_split_k<<<1024, 256>>>((const float4*)Wk, (uint2*)wkh, (uint2*)wkl, nW4);
    cvt_hi_k<<<1024, 256>>>((const float4*)Wv, (uint2*)wvh, nW4);

    // 2) Mt = 32 * Wq^T Wk  (TN, full split, half out)
    k_mt<<<dim3(8, 8, 1), 256, 2 * 4 * SLOT>>>(
        wqh, wql, wkh, wkl, nullptr, mth, nullptr,
        HID, HID, HID, HID, HID, 32.0f, 0, 0, 0);

    // 3) activation conversions (hi-only)
    cvt_hi_k<<<2048, 256>>>((const float4*)queries, (uint2*)qh, nBig4);
    cvt_hi_k<<<2048, 256>>>((const float4*)keys,    (uint2*)kh, nBig4);
    cvt_hi_k<<<2048, 256>>>((const float4*)values,  (uint2*)vh, nBig4);

    // 4) Vp = values*Wv^T + bv  (NT plain, half out)
    k_nth<<<dim3(HID / TN, (BNUM * SLEN) / TM, 1), 256, 3 * 2 * SLOT>>>(
        vh, nullptr, wvh, nullptr, nullptr, vph, bv,
        BNUM * SLEN, HID, HID, HID, HID, 1.0f, 0, 0, 0);

    // 5) KM = keys*M = (1/32)*keys*Mt^T-as-B  (NT plain, half out)
    k_nth<<<dim3(HID / TN, (BNUM * SLEN) / TM, 1), 256, 3 * 2 * SLOT>>>(
        kh, nullptr, mth, nullptr, nullptr, kmh, nullptr,
        BNUM * SLEN, HID, HID, HID, HID, 0.03125f, 0, 0, 0);

    // 6) attn_unnorm[b,s,q] = exp((1/32)*KM[b,s,:].q[b,q,:] + vrow) + partials
    k_sc<<<dim3(QLEN / TN, SLEN / TM, BNUM), 256, 3 * 2 * SLOT>>>(
        kmh, nullptr, qh, nullptr, attn, nullptr, nullptr,
        SLEN, QLEN, HID, HID, HID, 0.03125f,
        (size_t)SLEN * HID, (size_t)QLEN * HID, (size_t)SLEN * QLEN);

    // 7) normalize -> attn f32 (output) + attn fp16 (for ctx)
    scale_attn_k<<<dim3(QLEN / 256, BNUM, SLEN / 256), 256>>>(attn, ph);

    // 8) ctx[b,q,h] = sum_s attn[b,s,q]*Vp[b,s,h]  (TN plain, f32 out)
    k_ctx<<<dim3(HID / TN, QLEN / TM, BNUM), 256, 3 * 2 * SLOT>>>(
        ph, nullptr, vph, nullptr, ctx, nullptr, nullptr,
        QLEN, HID, SLEN, QLEN, HID, 1.0f,
        (size_t)SLEN * QLEN, (size_t)SLEN * HID, (size_t)QLEN * HID);
}

// round 8
// speedup vs baseline: 7.2281x; 1.1869x over previous
#include <cuda_runtime.h>
#include <cuda_fp16.h>
#include <cstdint>

#define HID   1024
#define BNUM  8
#define SLEN  2048
#define QLEN  2048

// ---------------- scratch: fp16 operand planes (allocation-free) -----------
__device__ __half g_Qh[(size_t)BNUM * QLEN * HID];
__device__ __half g_Kh[(size_t)BNUM * SLEN * HID];
__device__ __half g_Vh[(size_t)BNUM * SLEN * HID];
__device__ __half g_Wqh[(size_t)HID * HID];
__device__ __half g_Wql[(size_t)HID * HID];
__device__ __half g_Wkh[(size_t)HID * HID];
__device__ __half g_Wkl[(size_t)HID * HID];
__device__ __half g_Wvh[(size_t)HID * HID];
__device__ __half g_Mth[(size_t)HID * HID];          // 32 * Wq^T Wk (hi)
__device__ __half g_KMh[(size_t)BNUM * SLEN * HID];  // keys*M (hi)
__device__ __half g_Vph[(size_t)BNUM * SLEN * HID];  // V proj (hi)
__device__ __half g_Ph [(size_t)BNUM * SLEN * QLEN]; // exp(scores) f16 (unnorm)
__device__ float  g_part[(size_t)BNUM * 16 * QLEN];  // col-sum partials
__device__ float  g_inv [(size_t)BNUM * QLEN];       // 1 / col sums
__device__ float  g_vrow[(size_t)BNUM * SLEN];       // keys * (Wk^T bq)
__device__ float  g_vec[HID];
__device__ int    g_flag;

// ---------------- geometry ----------------
#define TM   128
#define TN   128
#define TKF  32
#define SLOT 10240         // one plane-tile slot (max of NT 10240 / TN 8704)
#define PNT  80            // NT tile row pitch (64B data + 16B pad)
#define PTR  272           // TRANS tile row pitch (256B data + 16B pad)

// ---------------- PTX helpers ----------------
__device__ __forceinline__ uint32_t smem_u32(const void* p) {
    uint32_t a;
    asm("{ .reg .u64 t; cvta.to.shared.u64 t, %1; cvt.u32.u64 %0, t; }"
        : "=r"(a) : "l"(p));
    return a;
}
__device__ __forceinline__ void cp16(uint32_t s, const void* g) {
    asm volatile("cp.async.cg.shared.global [%0], [%1], 16;"
                 :: "r"(s), "l"(g));
}
__device__ __forceinline__ void cp_commit() {
    asm volatile("cp.async.commit_group;" ::: "memory");
}
template <int N_>
__device__ __forceinline__ void cp_wait() {
    asm volatile("cp.async.wait_group %0;" :: "n"(N_) : "memory");
}
__device__ __forceinline__ void ldsm4(uint32_t* r, uint32_t addr) {
    asm volatile("ldmatrix.sync.aligned.m8n8.x4.shared.b16 {%0,%1,%2,%3}, [%4];"
                 : "=r"(r[0]), "=r"(r[1]), "=r"(r[2]), "=r"(r[3]) : "r"(addr));
}
__device__ __forceinline__ void ldsm4t(uint32_t* r, uint32_t addr) {
    asm volatile("ldmatrix.sync.aligned.m8n8.x4.trans.shared.b16 {%0,%1,%2,%3}, [%4];"
                 : "=r"(r[0]), "=r"(r[1]), "=r"(r[2]), "=r"(r[3]) : "r"(addr));
}
__device__ __forceinline__ void mma16816(float* c, const uint32_t* a,
                                         const uint32_t* b) {
    asm volatile(
        "mma.sync.aligned.m16n8k16.row.col.f32.f16.f16.f32 "
        "{%0,%1,%2,%3}, {%4,%5,%6,%7}, {%8,%9}, {%0,%1,%2,%3};"
        : "+f"(c[0]), "+f"(c[1]), "+f"(c[2]), "+f"(c[3])
        : "r"(a[0]), "r"(a[1]), "r"(a[2]), "r"(a[3]), "r"(b[0]), "r"(b[1]));
}

// ---------------------------------------------------------------------------
// Unified fp16 tensor-core GEMM over pre-converted half planes.
// NT (TRANS=0): C[m,n] = alpha*sum_k A[m,k]*B[n,k], A:[M,K], B:[N,K]
// TN (TRANS=1): C[m,n] = alpha*sum_k A[k,m]*B[k,n], A:[K,M], B:[K,N]
// ASPL/BSPL: lo-residual planes (extra MMA each).
// EPI: 0 = f32 out (+bias) [optionally * rowsc[row]];
//      1 = half out (+bias);
//      2 = exp epilogue: writes f16 exp to Ch, col-sum partials to g_part.
// STAGES: cp.async pipeline depth (one __syncthreads per k-iter).
// ---------------------------------------------------------------------------
template <bool TRANS, bool ASPL, bool BSPL, int EPI, int STAGES>
__device__ __forceinline__ void gbody(
    const __half* __restrict__ Ah, const __half* __restrict__ Al,
    const __half* __restrict__ Bh, const __half* __restrict__ Bl,
    float* __restrict__ Cf, __half* __restrict__ Ch,
    const float* __restrict__ bias, const float* __restrict__ rowsc,
    int M, int N, int K, int ldA, int ldB, float alpha,
    size_t sA, size_t sB, size_t sC)
{
    constexpr int NPA = ASPL ? 2 : 1;
    constexpr int NP  = NPA + (BSPL ? 2 : 1);
    constexpr int STG = NP * SLOT;

    extern __shared__ char sm[];
    const uint32_t sb = smem_u32(sm);

    const int tid  = threadIdx.x;
    const int lane = tid & 31;
    const int w    = tid >> 5;
    const int wm   = w & 1;
    const int wn   = w >> 1;
    const int g    = lane >> 2;
    const int t    = lane & 3;

    const size_t zz = blockIdx.z;
    const __half* Ahb = Ah + zz * sA;
    const __half* Alb = ASPL ? Al + zz * sA : nullptr;
    const __half* Bhb = Bh + zz * sB;
    const __half* Blb = BSPL ? Bl + zz * sB : nullptr;
    const int bm = blockIdx.y * TM;
    const int bn = blockIdx.x * TN;

    // fragment address components
    const int a_r   = ((lane >> 3) & 1) * 8 + (lane & 7);
    const int a_c8  = (lane >> 4) * 8;
    const int b_r   = (lane >> 4) * 8 + (lane & 7);
    const int b_c8  = ((lane >> 3) & 1) * 8;
    const int at_r  = (lane >> 4) * 8 + (lane & 7);
    const int at_c8 = ((lane >> 3) & 1) * 8;
    const int bt_r  = ((lane >> 3) & 1) * 8 + (lane & 7);
    const int bt_c8 = (lane >> 4) * 8;

    float acc[4][4][4];
#pragma unroll
    for (int i = 0; i < 4; i++)
#pragma unroll
        for (int j = 0; j < 4; j++)
#pragma unroll
            for (int e = 0; e < 4; e++) acc[i][j][e] = 0.0f;

    const int NK = K / TKF;

    auto issue = [&](int kt, int p) {
        const uint32_t st = sb + p * STG;
        if (!TRANS) {
#pragma unroll
            for (int j = 0; j < 2; j++) {
                const int idx = tid * 2 + j;
                const int r = idx >> 2, c = idx & 3;
                const uint32_t so = (uint32_t)(r * PNT + c * 16);
                const size_t goA = (size_t)(bm + r) * ldA + kt * TKF + c * 8;
                const size_t goB = (size_t)(bn + r) * ldB + kt * TKF + c * 8;
                cp16(st + so, Ahb + goA);
                if (ASPL) cp16(st + SLOT + so, Alb + goA);
                cp16(st + NPA * SLOT + so, Bhb + goB);
                if (BSPL) cp16(st + (NPA + 1) * SLOT + so, Blb + goB);
            }
        } else {
#pragma unroll
            for (int j = 0; j < 2; j++) {
                const int idx = tid * 2 + j;
                const int r = idx >> 4, c = idx & 15;
                const uint32_t so = (uint32_t)(r * PTR + c * 16);
                const size_t goA = (size_t)(kt * TKF + r) * ldA + bm + c * 8;
                const size_t goB = (size_t)(kt * TKF + r) * ldB + bn + c * 8;
                cp16(st + so, Ahb + goA);
                if (ASPL) cp16(st + SLOT + so, Alb + goA);
                cp16(st + NPA * SLOT + so, Bhb + goB);
                if (BSPL) cp16(st + (NPA + 1) * SLOT + so, Blb + goB);
            }
        }
    };

    // prologue: fill STAGES-1 buffers, one commit group per tile
#pragma unroll
    for (int s = 0; s < STAGES - 1; s++) {
        if (s < NK) issue(s, s);
        cp_commit();
    }

    for (int kt = 0; kt < NK; kt++) {
        const int p = kt % STAGES;

        cp_wait<STAGES - 2>();   // tile kt resident
        __syncthreads();         // also guards reuse of buffer being refilled

        if (kt + STAGES - 1 < NK) issue(kt + STAGES - 1, (kt + STAGES - 1) % STAGES);
        cp_commit();             // keep group numbering aligned (may be empty)

        const uint32_t sa_hi = sb + p * STG;
        const uint32_t sa_lo = sa_hi + SLOT;
        const uint32_t sb_hi = sa_hi + NPA * SLOT;
        const uint32_t sb_lo = sb_hi + SLOT;

#pragma unroll
        for (int ks = 0; ks < 2; ks++) {
            const int k0 = ks * 16;

            uint32_t bh[8], bl[8];
#pragma unroll
            for (int j = 0; j < 2; j++) {
                uint32_t addr;
                if (!TRANS) {
                    addr = (uint32_t)((wn * 32 + j * 16 + b_r) * PNT +
                                      (k0 + b_c8) * 2);
                    ldsm4(bh + 4 * j, sb_hi + addr);
                    if (BSPL) ldsm4(bl + 4 * j, sb_lo + addr);
                } else {
                    addr = (uint32_t)((k0 + bt_r) * PTR +
                                      (wn * 32 + j * 16 + bt_c8) * 2);
                    ldsm4t(bh + 4 * j, sb_hi + addr);
                    if (BSPL) ldsm4t(bl + 4 * j, sb_lo + addr);
                }
            }

            uint32_t ah[4][4], al[4][4];
#pragma unroll
            for (int mf = 0; mf < 4; mf++) {
                uint32_t addr;
                if (!TRANS) {
                    addr = (uint32_t)((wm * 64 + mf * 16 + a_r) * PNT +
                                      (k0 + a_c8) * 2);
                    ldsm4(ah[mf], sa_hi + addr);
                    if (ASPL) ldsm4(al[mf], sa_lo + addr);
                } else {
                    addr = (uint32_t)((k0 + at_r) * PTR +
                                      (wm * 64 + mf * 16 + at_c8) * 2);
                    ldsm4t(ah[mf], sa_hi + addr);
                    if (ASPL) ldsm4t(al[mf], sa_lo + addr);
                }
            }

#pragma unroll
            for (int mf = 0; mf < 4; mf++)
#pragma unroll
                for (int nf = 0; nf < 4; nf++) {
                    mma16816(acc[mf][nf], ah[mf], bh + 2 * nf);
                    if (ASPL) mma16816(acc[mf][nf], al[mf], bh + 2 * nf);
                    if (BSPL) mma16816(acc[mf][nf], ah[mf], bl + 2 * nf);
                }
        }
        // no trailing sync: next iteration's sync (after cp_wait) guards reuse
    }

    // ---------------- epilogues ----------------
    if (EPI == 2) {
        __syncthreads();  // smem 'red' reuses pipeline buffers
        __half* Cb = Ch + zz * sC;
        const float* vr = g_vrow + zz * SLEN;
        float cs[8];
#pragma unroll
        for (int j = 0; j < 8; j++) cs[j] = 0.0f;

#pragma unroll
        for (int mf = 0; mf < 4; mf++) {
            const int row0 = bm + wm * 64 + mf * 16 + g;
            const int row1 = row0 + 8;
            const float v0 = vr[row0], v1 = vr[row1];
#pragma unroll
            for (int nf = 0; nf < 4; nf++) {
                const int col = bn + wn * 32 + nf * 8 + 2 * t;
                float e00 = __expf(alpha * acc[mf][nf][0] + v0);
                float e01 = __expf(alpha * acc[mf][nf][1] + v0);
                float e10 = __expf(alpha * acc[mf][nf][2] + v1);
                float e11 = __expf(alpha * acc[mf][nf][3] + v1);
                *(__half2*)(Cb + (size_t)row0 * N + col) =
                    __floats2half2_rn(e00, e01);
                *(__half2*)(Cb + (size_t)row1 * N + col) =
                    __floats2half2_rn(e10, e11);
                cs[nf * 2 + 0] += e00 + e10;
                cs[nf * 2 + 1] += e01 + e11;
            }
        }
        float* red = (float*)sm;  // 256 floats
#pragma unroll
        for (int j = 0; j < 8; j++) {
#pragma unroll
            for (int o = 4; o <= 16; o <<= 1)
                cs[j] += __shfl_xor_sync(0xFFFFFFFFu, cs[j], o);
        }
        if (lane < 4) {
#pragma unroll
            for (int nf = 0; nf < 4; nf++) {
                red[wm * 128 + wn * 32 + nf * 8 + 2 * t + 0] = cs[nf * 2 + 0];
                red[wm * 128 + wn * 32 + nf * 8 + 2 * t + 1] = cs[nf * 2 + 1];
            }
        }
        __syncthreads();
        if (tid < 128) {
            g_part[((zz * 16) + blockIdx.y) * QLEN + bn + tid] =
                red[tid] + red[128 + tid];
        }
    } else {
#pragma unroll
        for (int mf = 0; mf < 4; mf++) {
            const int row0 = bm + wm * 64 + mf * 16 + g;
            const int row1 = row0 + 8;
            float s0 = 1.0f, s1 = 1.0f;
            if (rowsc != nullptr) {
                s0 = rowsc[zz * M + row0];
                s1 = rowsc[zz * M + row1];
            }
#pragma unroll
            for (int nf = 0; nf < 4; nf++) {
                const int col = bn + wn * 32 + nf * 8 + 2 * t;
                float bx = 0.0f, by = 0.0f;
                if (bias != nullptr) { bx = bias[col]; by = bias[col + 1]; }
                float o0x = s0 * (alpha * acc[mf][nf][0]) + bx;
                float o0y = s0 * (alpha * acc[mf][nf][1]) + by;
                float o1x = s1 * (alpha * acc[mf][nf][2]) + bx;
                float o1y = s1 * (alpha * acc[mf][nf][3]) + by;
                if (EPI == 0) {
                    float* Cb = Cf + zz * sC;
                    *(float2*)(Cb + (size_t)row0 * N + col) = make_float2(o0x, o0y);
                    *(float2*)(Cb + (size_t)row1 * N + col) = make_float2(o1x, o1y);
                } else {
                    __half* Cb = Ch + zz * sC;
                    *(__half2*)(Cb + (size_t)row0 * N + col) =
                        __floats2half2_rn(o0x, o0y);
                    *(__half2*)(Cb + (size_t)row1 * N + col) =
                        __floats2half2_rn(o1x, o1y);
                }
            }
        }
    }
}

// instantiations
extern "C" __global__ void __launch_bounds__(256)
k_mt(const __half* Ah, const __half* Al, const __half* Bh, const __half* Bl,
     float* Cf, __half* Ch, const float* bias, const float* rowsc,
     int M, int N, int K, int ldA, int ldB, float alpha,
     size_t sA, size_t sB, size_t sC)
{ gbody<true, true, true, 1, 2>(Ah, Al, Bh, Bl, Cf, Ch, bias, rowsc,
                                M, N, K, ldA, ldB, alpha, sA, sB, sC); }

extern "C" __global__ void __launch_bounds__(256, 2)
k_nth(const __half* Ah, const __half* Al, const __half* Bh, const __half* Bl,
      float* Cf, __half* Ch, const float* bias, const float* rowsc,
      int M, int N, int K, int ldA, int ldB, float alpha,
      size_t sA, size_t sB, size_t sC)
{ gbody<false, false, false, 1, 3>(Ah, Al, Bh, Bl, Cf, Ch, bias, rowsc,
                                   M, N, K, ldA, ldB, alpha, sA, sB, sC); }

extern "C" __global__ void __launch_bounds__(256, 2)
k_sc(const __half* Ah, const __half* Al, const __half* Bh, const __half* Bl,
     float* Cf, __half* Ch, const float* bias, const float* rowsc,
     int M, int N, int K, int ldA, int ldB, float alpha,
     size_t sA, size_t sB, size_t sC)
{ gbody<false, false, false, 2, 3>(Ah, Al, Bh, Bl, Cf, Ch, bias, rowsc,
                                   M, N, K, ldA, ldB, alpha, sA, sB, sC); }

extern "C" __global__ void __launch_bounds__(256, 2)
k_ctx(const __half* Ah, const __half* Al, const __half* Bh, const __half* Bl,
      float* Cf, __half* Ch, const float* bias, const float* rowsc,
      int M, int N, int K, int ldA, int ldB, float alpha,
      size_t sA, size_t sB, size_t sC)
{ gbody<true, false, false, 0, 3>(Ah, Al, Bh, Bl, Cf, Ch, bias, rowsc,
                                  M, N, K, ldA, ldB, alpha, sA, sB, sC); }

// ---------------- f32 -> half(hi[,lo]) conversion ----------------
__global__ void __launch_bounds__(256)
cvt_split_k(const float4* __restrict__ in, uint2* __restrict__ hi,
            uint2* __restrict__ lo, int n4)
{
    for (int i = blockIdx.x * 256 + threadIdx.x; i < n4; i += gridDim.x * 256) {
        float4 v = in[i];
        __half2 h0 = __floats2half2_rn(v.x, v.y);
        __half2 h1 = __floats2half2_rn(v.z, v.w);
        hi[i] = make_uint2(*(uint32_t*)&h0, *(uint32_t*)&h1);
        float2 f0 = __half22float2(h0), f1 = __half22float2(h1);
        __half2 l0 = __floats2half2_rn(v.x - f0.x, v.y - f0.y);
        __half2 l1 = __floats2half2_rn(v.z - f1.x, v.w - f1.y);
        lo[i] = make_uint2(*(uint32_t*)&l0, *(uint32_t*)&l1);
    }
}
__global__ void __launch_bounds__(256)
cvt_hi_k(const float4* __restrict__ in, uint2* __restrict__ hi, int n4)
{
    for (int i = blockIdx.x * 256 + threadIdx.x; i < n4; i += gridDim.x * 256) {
        float4 v = in[i];
        __half2 h0 = __floats2half2_rn(v.x, v.y);
        __half2 h1 = __floats2half2_rn(v.z, v.w);
        hi[i] = make_uint2(*(uint32_t*)&h0, *(uint32_t*)&h1);
    }
}

// ---------------- bias rank-1 correction (general-bq path) ----------------
__global__ void bias_flag_k(const float* __restrict__ bq) {
    int any = 0;
    for (int i = threadIdx.x; i < HID; i += 256) any |= (bq[i] != 0.0f);
    int r = __syncthreads_or(any);
    if (threadIdx.x == 0) g_flag = r ? 1 : 0;
}
__global__ void vec_k(const float* __restrict__ Wk, const float* __restrict__ bq) {
    int i = blockIdx.x * 256 + threadIdx.x;
    float s = 0.0f;
    if (g_flag) {
        for (int o = 0; o < HID; o++) s += Wk[(size_t)o * HID + i] * bq[o];
    }
    g_vec[i] = s;
}
__global__ void vrow_k(const float* __restrict__ keys) {
    int r = blockIdx.x * 256 + threadIdx.x;
    float s = 0.0f;
    if (g_flag) {
        const float* kr = keys + (size_t)r * HID;
        for (int i = 0; i < HID; i++) s += kr[i] * g_vec[i];
    }
    g_vrow[r] = s;
}

// ---------------- inv sums, then attn = Ph * inv (f32 output) --------------
__global__ void __launch_bounds__(256) inv_k()
{
    const int i = blockIdx.x * 256 + threadIdx.x;   // b*QLEN + q
    const int b = i >> 11, q = i & (QLEN - 1);
    float tot = 0.0f;
#pragma unroll
    for (int j = 0; j < 16; j++)
        tot += g_part[((size_t)b * 16 + j) * QLEN + q];
    g_inv[i] = 1.0f / tot;
}
__global__ void __launch_bounds__(256)
norm_k(const uint2* __restrict__ ph, float4* __restrict__ attn)
{
    const int n = (BNUM * SLEN * QLEN) / 4;
    for (int i = blockIdx.x * 256 + threadIdx.x; i < n; i += gridDim.x * 256) {
        uint2 u = ph[i];                         // 4 halves
        const int e0 = i * 4;
        const int q  = e0 & (QLEN - 1);          // QLEN multiple of 4
        const int b  = e0 >> 22;                 // / (SLEN*QLEN)
        float4 inv = *(const float4*)(g_inv + ((size_t)b << 11) + q);
        __half2 h0 = *(__half2*)&u.x;
        __half2 h1 = *(__half2*)&u.y;
        float2 f0 = __half22float2(h0), f1 = __half22float2(h1);
        float4 o;
        o.x = f0.x * inv.x; o.y = f0.y * inv.y;
        o.z = f1.x * inv.z; o.w = f1.y * inv.w;
        attn[i] = o;
    }
}

// ---------------- launcher ----------------
extern "C" void kernel_launch(void* const* d_in, const int* in_sizes, int n_in,
                              void* d_out, int out_size)
{
    const float* queries = (const float*)d_in[0];
    const float* keys    = (const float*)d_in[1];
    const float* values  = (const float*)d_in[2];
    const float* Wq      = (const float*)d_in[3];
    const float* bq      = (const float*)d_in[4];
    const float* Wk      = (const float*)d_in[5];
    // d_in[6] = bk: enters scores only via per-q constants -> cancels in softmax
    const float* Wv      = (const float*)d_in[7];
    const float* bv      = (const float*)d_in[8];

    float* ctx  = (float*)d_out;                                // [B,Q,H]
    float* attn = (float*)d_out + (size_t)BNUM * QLEN * HID;    // [B,S,Q]

    __half *qh, *kh, *vh, *wqh, *wql, *wkh, *wkl, *wvh;
    __half *mth, *kmh, *vph, *ph;
    float  *invp;
    cudaGetSymbolAddress((void**)&qh, g_Qh);
    cudaGetSymbolAddress((void**)&kh, g_Kh);
    cudaGetSymbolAddress((void**)&vh, g_Vh);
    cudaGetSymbolAddress((void**)&wqh, g_Wqh);
    cudaGetSymbolAddress((void**)&wql, g_Wql);
    cudaGetSymbolAddress((void**)&wkh, g_Wkh);
    cudaGetSymbolAddress((void**)&wkl, g_Wkl);
    cudaGetSymbolAddress((void**)&wvh, g_Wvh);
    cudaGetSymbolAddress((void**)&mth, g_Mth);
    cudaGetSymbolAddress((void**)&kmh, g_KMh);
    cudaGetSymbolAddress((void**)&vph, g_Vph);
    cudaGetSymbolAddress((void**)&ph, g_Ph);
    cudaGetSymbolAddress((void**)&invp, g_inv);

    static bool attr_done = false;
    if (!attr_done) {
        cudaFuncSetAttribute(k_mt,  cudaFuncAttributeMaxDynamicSharedMemorySize, 2 * 4 * SLOT);
        cudaFuncSetAttribute(k_nth, cudaFuncAttributeMaxDynamicSharedMemorySize, 3 * 2 * SLOT);
        cudaFuncSetAttribute(k_sc,  cudaFuncAttributeMaxDynamicSharedMemorySize, 3 * 2 * SLOT);
        cudaFuncSetAttribute(k_ctx, cudaFuncAttributeMaxDynamicSharedMemorySize, 3 * 2 * SLOT);
        attr_done = true;
    }

    const int nBig4 = (BNUM * SLEN * HID) / 4;
    const int nW4   = (HID * HID) / 4;

    // 0) bias rank-1 chain (zero-work when bq == 0; keeps bq generality)
    bias_flag_k<<<1, 256>>>(bq);
    vec_k<<<HID / 256, 256>>>(Wk, bq);
    vrow_k<<<(BNUM * SLEN) / 256, 256>>>(keys);

    // 1) weight conversions (Wq/Wk split for exact Mt; Wv hi-only)
    cvt_split_k<<<1024, 256>>>((const float4*)Wq, (uint2*)wqh, (uint2*)wql, nW4);
    cvt_split_k<<<1024, 256>>>((const float4*)Wk, (uint2*)wkh, (uint2*)wkl, nW4);
    cvt_hi_k<<<1024, 256>>>((const float4*)Wv, (uint2*)wvh, nW4);

    // 2) Mt = 32 * Wq^T Wk  (TN, full split, half out)
    k_mt<<<dim3(8, 8, 1), 256, 2 * 4 * SLOT>>>(
        wqh, wql, wkh, wkl, nullptr, mth, nullptr, nullptr,
        HID, HID, HID, HID, HID, 32.0f, 0, 0, 0);

    // 3) activation conversions (hi-only)
    cvt_hi_k<<<2048, 256>>>((const float4*)queries, (uint2*)qh, nBig4);
    cvt_hi_k<<<2048, 256>>>((const float4*)keys,    (uint2*)kh, nBig4);
    cvt_hi_k<<<2048, 256>>>((const float4*)values,  (uint2*)vh, nBig4);

    // 4) Vp = values*Wv^T + bv  (NT plain, half out)
    k_nth<<<dim3(HID / TN, (BNUM * SLEN) / TM, 1), 256, 3 * 2 * SLOT>>>(
        vh, nullptr, wvh, nullptr, nullptr, vph, bv, nullptr,
        BNUM * SLEN, HID, HID, HID, HID, 1.0f, 0, 0, 0);

    // 5) KM = keys*M = (1/32)*keys*Mt^T-as-B  (NT plain, half out)
    k_nth<<<dim3(HID / TN, (BNUM * SLEN) / TM, 1), 256, 3 * 2 * SLOT>>>(
        kh, nullptr, mth, nullptr, nullptr, kmh, nullptr, nullptr,
        BNUM * SLEN, HID, HID, HID, HID, 0.03125f, 0, 0, 0);

    // 6) Ph[b,s,q] = f16(exp((1/32)*KM.q + vrow)) + col-sum partials
    k_sc<<<dim3(QLEN / TN, SLEN / TM, BNUM), 256, 3 * 2 * SLOT>>>(
        kmh, nullptr, qh, nullptr, nullptr, ph, nullptr, nullptr,
        SLEN, QLEN, HID, HID, HID, 0.03125f,
        (size_t)SLEN * HID, (size_t)QLEN * HID, (size_t)SLEN * QLEN);

    // 7) per-q inverse sums, then attn f32 output = Ph * inv
    inv_k<<<(BNUM * QLEN) / 256, 256>>>();
    norm_k<<<2048, 256>>>((const uint2*)ph, (float4*)attn);

    // 8) ctx[b,q,h] = inv[q] * sum_s Ph[b,s,q]*Vp[b,s,h]  (TN plain, f32 out,
    //    row-scaled epilogue: normalization commutes with the GEMM)
    k_ctx<<<dim3(HID / TN, QLEN / TM, BNUM), 256, 3 * 2 * SLOT>>>(
        ph, nullptr, vph, nullptr, ctx, nullptr, nullptr, invp,
        QLEN, HID, SLEN, QLEN, HID, 1.0f,
        (size_t)SLEN * QLEN, (size_t)SLEN * HID, (size_t)QLEN * HID);
}

// round 9
// speedup vs baseline: 7.3021x; 1.0102x over previous
#include <cuda_runtime.h>
#include <cuda_fp16.h>
#include <cstdint>

#define HID   1024
#define BNUM  8
#define SLEN  2048
#define QLEN  2048

// ---------------- scratch: fp16 operand planes (allocation-free) -----------
__device__ __half g_Qh[(size_t)BNUM * QLEN * HID];
__device__ __half g_Kh[(size_t)BNUM * SLEN * HID];
__device__ __half g_Vh[(size_t)BNUM * SLEN * HID];
__device__ __half g_Wqh[(size_t)HID * HID];
__device__ __half g_Wql[(size_t)HID * HID];
__device__ __half g_Wkh[(size_t)HID * HID];
__device__ __half g_Wkl[(size_t)HID * HID];
__device__ __half g_Wvh[(size_t)HID * HID];
__device__ __half g_Mth[(size_t)HID * HID];          // 32 * Wq^T Wk (hi)
__device__ __half g_KMh[(size_t)BNUM * SLEN * HID];  // keys*M (hi)
__device__ __half g_Vph[(size_t)BNUM * SLEN * HID];  // V proj (hi)
__device__ __half g_Ph [(size_t)BNUM * SLEN * QLEN]; // exp(scores) f16 (unnorm)
__device__ float  g_part[(size_t)BNUM * 16 * QLEN];  // col-sum partials
__device__ float  g_inv [(size_t)BNUM * QLEN];       // 1 / col sums
__device__ float  g_vrow[(size_t)BNUM * SLEN];       // keys * (Wk^T bq)
__device__ float  g_vec[HID];
__device__ int    g_flag;

// ---------------- geometry ----------------
#define TM   128
#define TN   128
#define TKF  32
#define SLOT 10240         // one plane-tile slot (max of NT 10240 / TN 8704)
#define PNT  80            // NT tile row pitch (64B data + 16B pad)
#define PTR  272           // TRANS tile row pitch (256B data + 16B pad)

// ---------------- PTX helpers ----------------
__device__ __forceinline__ uint32_t smem_u32(const void* p) {
    uint32_t a;
    asm("{ .reg .u64 t; cvta.to.shared.u64 t, %1; cvt.u32.u64 %0, t; }"
        : "=r"(a) : "l"(p));
    return a;
}
__device__ __forceinline__ void cp16(uint32_t s, const void* g) {
    asm volatile("cp.async.cg.shared.global [%0], [%1], 16;"
                 :: "r"(s), "l"(g));
}
__device__ __forceinline__ void cp_commit() {
    asm volatile("cp.async.commit_group;" ::: "memory");
}
template <int N_>
__device__ __forceinline__ void cp_wait() {
    asm volatile("cp.async.wait_group %0;" :: "n"(N_) : "memory");
}
__device__ __forceinline__ void ldsm4(uint32_t* r, uint32_t addr) {
    asm volatile("ldmatrix.sync.aligned.m8n8.x4.shared.b16 {%0,%1,%2,%3}, [%4];"
                 : "=r"(r[0]), "=r"(r[1]), "=r"(r[2]), "=r"(r[3]) : "r"(addr));
}
__device__ __forceinline__ void ldsm4t(uint32_t* r, uint32_t addr) {
    asm volatile("ldmatrix.sync.aligned.m8n8.x4.trans.shared.b16 {%0,%1,%2,%3}, [%4];"
                 : "=r"(r[0]), "=r"(r[1]), "=r"(r[2]), "=r"(r[3]) : "r"(addr));
}
__device__ __forceinline__ void mma16816(float* c, const uint32_t* a,
                                         const uint32_t* b) {
    asm volatile(
        "mma.sync.aligned.m16n8k16.row.col.f32.f16.f16.f32 "
        "{%0,%1,%2,%3}, {%4,%5,%6,%7}, {%8,%9}, {%0,%1,%2,%3};"
        : "+f"(c[0]), "+f"(c[1]), "+f"(c[2]), "+f"(c[3])
        : "r"(a[0]), "r"(a[1]), "r"(a[2]), "r"(a[3]), "r"(b[0]), "r"(b[1]));
}

// ---------------------------------------------------------------------------
// Unified fp16 tensor-core GEMM over pre-converted half planes.
// NT (TRANS=0): C[m,n] = alpha*sum_k A[m,k]*B[n,k], A:[M,K], B:[N,K]
// TN (TRANS=1): C[m,n] = alpha*sum_k A[k,m]*B[k,n], A:[K,M], B:[K,N]
// ASPL/BSPL: lo-residual planes (extra MMA each).
// EPI: 0 = f32 out (+bias) [optionally * rowsc[row]];
//      1 = half out (+bias);
//      2 = exp epilogue: writes f16 exp to Ch, col-sum partials to g_part.
// STAGES: cp.async pipeline depth (one __syncthreads per k-iter).
// ---------------------------------------------------------------------------
template <bool TRANS, bool ASPL, bool BSPL, int EPI, int STAGES>
__device__ __forceinline__ void gbody(
    const __half* __restrict__ Ah, const __half* __restrict__ Al,
    const __half* __restrict__ Bh, const __half* __restrict__ Bl,
    float* __restrict__ Cf, __half* __restrict__ Ch,
    const float* __restrict__ bias, const float* __restrict__ rowsc,
    int M, int N, int K, int ldA, int ldB, float alpha,
    size_t sA, size_t sB, size_t sC)
{
    constexpr int NPA = ASPL ? 2 : 1;
    constexpr int NP  = NPA + (BSPL ? 2 : 1);
    constexpr int STG = NP * SLOT;

    extern __shared__ char sm[];
    const uint32_t sb = smem_u32(sm);

    const int tid  = threadIdx.x;
    const int lane = tid & 31;
    const int w    = tid >> 5;
    const int wm   = w & 1;
    const int wn   = w >> 1;
    const int g    = lane >> 2;
    const int t    = lane & 3;

    const size_t zz = blockIdx.z;
    const __half* Ahb = Ah + zz * sA;
    const __half* Alb = ASPL ? Al + zz * sA : nullptr;
    const __half* Bhb = Bh + zz * sB;
    const __half* Blb = BSPL ? Bl + zz * sB : nullptr;
    const int bm = blockIdx.y * TM;
    const int bn = blockIdx.x * TN;

    // fragment address components
    const int a_r   = ((lane >> 3) & 1) * 8 + (lane & 7);
    const int a_c8  = (lane >> 4) * 8;
    const int b_r   = (lane >> 4) * 8 + (lane & 7);
    const int b_c8  = ((lane >> 3) & 1) * 8;
    const int at_r  = (lane >> 4) * 8 + (lane & 7);
    const int at_c8 = ((lane >> 3) & 1) * 8;
    const int bt_r  = ((lane >> 3) & 1) * 8 + (lane & 7);
    const int bt_c8 = (lane >> 4) * 8;

    float acc[4][4][4];
#pragma unroll
    for (int i = 0; i < 4; i++)
#pragma unroll
        for (int j = 0; j < 4; j++)
#pragma unroll
            for (int e = 0; e < 4; e++) acc[i][j][e] = 0.0f;

    const int NK = K / TKF;

    auto issue = [&](int kt, int p) {
        const uint32_t st = sb + p * STG;
        if (!TRANS) {
#pragma unroll
            for (int j = 0; j < 2; j++) {
                const int idx = tid * 2 + j;
                const int r = idx >> 2, c = idx & 3;
                const uint32_t so = (uint32_t)(r * PNT + c * 16);
                const size_t goA = (size_t)(bm + r) * ldA + kt * TKF + c * 8;
                const size_t goB = (size_t)(bn + r) * ldB + kt * TKF + c * 8;
                cp16(st + so, Ahb + goA);
                if (ASPL) cp16(st + SLOT + so, Alb + goA);
                cp16(st + NPA * SLOT + so, Bhb + goB);
                if (BSPL) cp16(st + (NPA + 1) * SLOT + so, Blb + goB);
            }
        } else {
#pragma unroll
            for (int j = 0; j < 2; j++) {
                const int idx = tid * 2 + j;
                const int r = idx >> 4, c = idx & 15;
                const uint32_t so = (uint32_t)(r * PTR + c * 16);
                const size_t goA = (size_t)(kt * TKF + r) * ldA + bm + c * 8;
                const size_t goB = (size_t)(kt * TKF + r) * ldB + bn + c * 8;
                cp16(st + so, Ahb + goA);
                if (ASPL) cp16(st + SLOT + so, Alb + goA);
                cp16(st + NPA * SLOT + so, Bhb + goB);
                if (BSPL) cp16(st + (NPA + 1) * SLOT + so, Blb + goB);
            }
        }
    };

    // prologue: fill STAGES-1 buffers, one commit group per tile
#pragma unroll
    for (int s = 0; s < STAGES - 1; s++) {
        if (s < NK) issue(s, s);
        cp_commit();
    }

    for (int kt = 0; kt < NK; kt++) {
        const int p = kt % STAGES;

        cp_wait<STAGES - 2>();   // tile kt resident
        __syncthreads();         // also guards reuse of buffer being refilled

        if (kt + STAGES - 1 < NK) issue(kt + STAGES - 1, (kt + STAGES - 1) % STAGES);
        cp_commit();             // keep group numbering aligned (may be empty)

        const uint32_t sa_hi = sb + p * STG;
        const uint32_t sa_lo = sa_hi + SLOT;
        const uint32_t sb_hi = sa_hi + NPA * SLOT;
        const uint32_t sb_lo = sb_hi + SLOT;

#pragma unroll
        for (int ks = 0; ks < 2; ks++) {
            const int k0 = ks * 16;

            uint32_t bh[8], bl[8];
#pragma unroll
            for (int j = 0; j < 2; j++) {
                uint32_t addr;
                if (!TRANS) {
                    addr = (uint32_t)((wn * 32 + j * 16 + b_r) * PNT +
                                      (k0 + b_c8) * 2);
                    ldsm4(bh + 4 * j, sb_hi + addr);
                    if (BSPL) ldsm4(bl + 4 * j, sb_lo + addr);
                } else {
                    addr = (uint32_t)((k0 + bt_r) * PTR +
                                      (wn * 32 + j * 16 + bt_c8) * 2);
                    ldsm4t(bh + 4 * j, sb_hi + addr);
                    if (BSPL) ldsm4t(bl + 4 * j, sb_lo + addr);
                }
            }

            uint32_t ah[4][4], al[4][4];
#pragma unroll
            for (int mf = 0; mf < 4; mf++) {
                uint32_t addr;
                if (!TRANS) {
                    addr = (uint32_t)((wm * 64 + mf * 16 + a_r) * PNT +
                                      (k0 + a_c8) * 2);
                    ldsm4(ah[mf], sa_hi + addr);
                    if (ASPL) ldsm4(al[mf], sa_lo + addr);
                } else {
                    addr = (uint32_t)((k0 + at_r) * PTR +
                                      (wm * 64 + mf * 16 + at_c8) * 2);
                    ldsm4t(ah[mf], sa_hi + addr);
                    if (ASPL) ldsm4t(al[mf], sa_lo + addr);
                }
            }

#pragma unroll
            for (int mf = 0; mf < 4; mf++)
#pragma unroll
                for (int nf = 0; nf < 4; nf++) {
                    mma16816(acc[mf][nf], ah[mf], bh + 2 * nf);
                    if (ASPL) mma16816(acc[mf][nf], al[mf], bh + 2 * nf);
                    if (BSPL) mma16816(acc[mf][nf], ah[mf], bl + 2 * nf);
                }
        }
        // no trailing sync: next iteration's sync (after cp_wait) guards reuse
    }

    // ---------------- epilogues ----------------
    if (EPI == 2) {
        __syncthreads();  // smem 'red' reuses pipeline buffers
        __half* Cb = Ch + zz * sC;
        const float* vr = g_vrow + zz * SLEN;
        float cs[8];
#pragma unroll
        for (int j = 0; j < 8; j++) cs[j] = 0.0f;

#pragma unroll
        for (int mf = 0; mf < 4; mf++) {
            const int row0 = bm + wm * 64 + mf * 16 + g;
            const int row1 = row0 + 8;
            const float v0 = vr[row0], v1 = vr[row1];
#pragma unroll
            for (int nf = 0; nf < 4; nf++) {
                const int col = bn + wn * 32 + nf * 8 + 2 * t;
                float e00 = __expf(alpha * acc[mf][nf][0] + v0);
                float e01 = __expf(alpha * acc[mf][nf][1] + v0);
                float e10 = __expf(alpha * acc[mf][nf][2] + v1);
                float e11 = __expf(alpha * acc[mf][nf][3] + v1);
                *(__half2*)(Cb + (size_t)row0 * N + col) =
                    __floats2half2_rn(e00, e01);
                *(__half2*)(Cb + (size_t)row1 * N + col) =
                    __floats2half2_rn(e10, e11);
                cs[nf * 2 + 0] += e00 + e10;
                cs[nf * 2 + 1] += e01 + e11;
            }
        }
        float* red = (float*)sm;  // 256 floats
#pragma unroll
        for (int j = 0; j < 8; j++) {
#pragma unroll
            for (int o = 4; o <= 16; o <<= 1)
                cs[j] += __shfl_xor_sync(0xFFFFFFFFu, cs[j], o);
        }
        if (lane < 4) {
#pragma unroll
            for (int nf = 0; nf < 4; nf++) {
                red[wm * 128 + wn * 32 + nf * 8 + 2 * t + 0] = cs[nf * 2 + 0];
                red[wm * 128 + wn * 32 + nf * 8 + 2 * t + 1] = cs[nf * 2 + 1];
            }
        }
        __syncthreads();
        if (tid < 128) {
            g_part[((zz * 16) + blockIdx.y) * QLEN + bn + tid] =
                red[tid] + red[128 + tid];
        }
    } else {
#pragma unroll
        for (int mf = 0; mf < 4; mf++) {
            const int row0 = bm + wm * 64 + mf * 16 + g;
            const int row1 = row0 + 8;
            float s0 = 1.0f, s1 = 1.0f;
            if (rowsc != nullptr) {
                s0 = rowsc[zz * M + row0];
                s1 = rowsc[zz * M + row1];
            }
#pragma unroll
            for (int nf = 0; nf < 4; nf++) {
                const int col = bn + wn * 32 + nf * 8 + 2 * t;
                float bx = 0.0f, by = 0.0f;
                if (bias != nullptr) { bx = bias[col]; by = bias[col + 1]; }
                float o0x = s0 * (alpha * acc[mf][nf][0]) + bx;
                float o0y = s0 * (alpha * acc[mf][nf][1]) + by;
                float o1x = s1 * (alpha * acc[mf][nf][2]) + bx;
                float o1y = s1 * (alpha * acc[mf][nf][3]) + by;
                if (EPI == 0) {
                    float* Cb = Cf + zz * sC;
                    *(float2*)(Cb + (size_t)row0 * N + col) = make_float2(o0x, o0y);
                    *(float2*)(Cb + (size_t)row1 * N + col) = make_float2(o1x, o1y);
                } else {
                    __half* Cb = Ch + zz * sC;
                    *(__half2*)(Cb + (size_t)row0 * N + col) =
                        __floats2half2_rn(o0x, o0y);
                    *(__half2*)(Cb + (size_t)row1 * N + col) =
                        __floats2half2_rn(o1x, o1y);
                }
            }
        }
    }
}

// ---------------- instantiations ----------------
extern "C" __global__ void __launch_bounds__(256)
k_mt(const __half* Ah, const __half* Al, const __half* Bh, const __half* Bl,
     float* Cf, __half* Ch, const float* bias, const float* rowsc,
     int M, int N, int K, int ldA, int ldB, float alpha,
     size_t sA, size_t sB, size_t sC)
{ gbody<true, true, true, 1, 2>(Ah, Al, Bh, Bl, Cf, Ch, bias, rowsc,
                                M, N, K, ldA, ldB, alpha, sA, sB, sC); }

// merged Vp + KM: blockIdx.z selects the problem (strides are 0, so the
// zz-based batch offset inside gbody is a no-op)
extern "C" __global__ void __launch_bounds__(256, 2)
k_proj2(const float* bv)
{
    if (blockIdx.z == 0)
        gbody<false, false, false, 1, 4>(
            g_Vh, nullptr, g_Wvh, nullptr, nullptr, g_Vph, bv, nullptr,
            BNUM * SLEN, HID, HID, HID, HID, 1.0f, 0, 0, 0);
    else
        gbody<false, false, false, 1, 4>(
            g_Kh, nullptr, g_Mth, nullptr, nullptr, g_KMh, nullptr, nullptr,
            BNUM * SLEN, HID, HID, HID, HID, 0.03125f, 0, 0, 0);
}

extern "C" __global__ void __launch_bounds__(256, 2)
k_sc(const __half* Ah, const __half* Al, const __half* Bh, const __half* Bl,
     float* Cf, __half* Ch, const float* bias, const float* rowsc,
     int M, int N, int K, int ldA, int ldB, float alpha,
     size_t sA, size_t sB, size_t sC)
{ gbody<false, false, false, 2, 4>(Ah, Al, Bh, Bl, Cf, Ch, bias, rowsc,
                                   M, N, K, ldA, ldB, alpha, sA, sB, sC); }

extern "C" __global__ void __launch_bounds__(256, 2)
k_ctx(const __half* Ah, const __half* Al, const __half* Bh, const __half* Bl,
      float* Cf, __half* Ch, const float* bias, const float* rowsc,
      int M, int N, int K, int ldA, int ldB, float alpha,
      size_t sA, size_t sB, size_t sC)
{ gbody<true, false, false, 0, 4>(Ah, Al, Bh, Bl, Cf, Ch, bias, rowsc,
                                  M, N, K, ldA, ldB, alpha, sA, sB, sC); }

// ---------------- f32 -> half conversions ----------------
__global__ void __launch_bounds__(256)
cvt_split_k(const float4* __restrict__ in, uint2* __restrict__ hi,
            uint2* __restrict__ lo, int n4)
{
    for (int i = blockIdx.x * 256 + threadIdx.x; i < n4; i += gridDim.x * 256) {
        float4 v = in[i];
        __half2 h0 = __floats2half2_rn(v.x, v.y);
        __half2 h1 = __floats2half2_rn(v.z, v.w);
        hi[i] = make_uint2(*(uint32_t*)&h0, *(uint32_t*)&h1);
        float2 f0 = __half22float2(h0), f1 = __half22float2(h1);
        __half2 l0 = __floats2half2_rn(v.x - f0.x, v.y - f0.y);
        __half2 l1 = __floats2half2_rn(v.z - f1.x, v.w - f1.y);
        lo[i] = make_uint2(*(uint32_t*)&l0, *(uint32_t*)&l1);
    }
}
__global__ void __launch_bounds__(256)
cvt_hi_k(const float4* __restrict__ in, uint2* __restrict__ hi, int n4)
{
    for (int i = blockIdx.x * 256 + threadIdx.x; i < n4; i += gridDim.x * 256) {
        float4 v = in[i];
        __half2 h0 = __floats2half2_rn(v.x, v.y);
        __half2 h1 = __floats2half2_rn(v.z, v.w);
        hi[i] = make_uint2(*(uint32_t*)&h0, *(uint32_t*)&h1);
    }
}
// merged q/k/v hi-conversion: blockIdx.z picks the tensor
extern "C" __global__ void __launch_bounds__(256)
cvt3_k(const float4* __restrict__ q, const float4* __restrict__ k,
       const float4* __restrict__ v, int n4)
{
    const float4* in = (blockIdx.z == 0) ? q : (blockIdx.z == 1) ? k : v;
    uint2* out = (blockIdx.z == 0) ? (uint2*)g_Qh
               : (blockIdx.z == 1) ? (uint2*)g_Kh : (uint2*)g_Vh;
    for (int i = blockIdx.x * 256 + threadIdx.x; i < n4; i += gridDim.x * 256) {
        float4 x = in[i];
        __half2 h0 = __floats2half2_rn(x.x, x.y);
        __half2 h1 = __floats2half2_rn(x.z, x.w);
        out[i] = make_uint2(*(uint32_t*)&h0, *(uint32_t*)&h1);
    }
}

// ---------------- bias rank-1 correction (general-bq path) ----------------
__global__ void bias_flag_k(const float* __restrict__ bq) {
    int any = 0;
    for (int i = threadIdx.x; i < HID; i += 256) any |= (bq[i] != 0.0f);
    int r = __syncthreads_or(any);
    if (threadIdx.x == 0) g_flag = r ? 1 : 0;
}
__global__ void vec_k(const float* __restrict__ Wk, const float* __restrict__ bq) {
    int i = blockIdx.x * 256 + threadIdx.x;
    float s = 0.0f;
    if (g_flag) {
        for (int o = 0; o < HID; o++) s += Wk[(size_t)o * HID + i] * bq[o];
    }
    g_vec[i] = s;
}
__global__ void vrow_k(const float* __restrict__ keys) {
    int r = blockIdx.x * 256 + threadIdx.x;
    float s = 0.0f;
    if (g_flag) {
        const float* kr = keys + (size_t)r * HID;
        for (int i = 0; i < HID; i++) s += kr[i] * g_vec[i];
    }
    g_vrow[r] = s;
}

// ---------------- inv sums, then attn = Ph * inv (f32 output) --------------
__global__ void __launch_bounds__(256) inv_k()
{
    const int i = blockIdx.x * 256 + threadIdx.x;   // b*QLEN + q
    const int b = i >> 11, q = i & (QLEN - 1);
    float tot = 0.0f;
#pragma unroll
    for (int j = 0; j < 16; j++)
        tot += g_part[((size_t)b * 16 + j) * QLEN + q];
    g_inv[i] = 1.0f / tot;
}
__global__ void __launch_bounds__(256)
norm_k(const uint2* __restrict__ ph, float4* __restrict__ attn)
{
    const int n = (BNUM * SLEN * QLEN) / 4;
    for (int i = blockIdx.x * 256 + threadIdx.x; i < n; i += gridDim.x * 256) {
        uint2 u = ph[i];                         // 4 halves
        const int e0 = i * 4;
        const int q  = e0 & (QLEN - 1);          // QLEN multiple of 4
        const int b  = e0 >> 22;                 // / (SLEN*QLEN)
        float4 inv = *(const float4*)(g_inv + ((size_t)b << 11) + q);
        __half2 h0 = *(__half2*)&u.x;
        __half2 h1 = *(__half2*)&u.y;
        float2 f0 = __half22float2(h0), f1 = __half22float2(h1);
        float4 o;
        o.x = f0.x * inv.x; o.y = f0.y * inv.y;
        o.z = f1.x * inv.z; o.w = f1.y * inv.w;
        attn[i] = o;
    }
}

// ---------------- launcher ----------------
extern "C" void kernel_launch(void* const* d_in, const int* in_sizes, int n_in,
                              void* d_out, int out_size)
{
    const float* queries = (const float*)d_in[0];
    const float* keys    = (const float*)d_in[1];
    const float* values  = (const float*)d_in[2];
    const float* Wq      = (const float*)d_in[3];
    const float* bq      = (const float*)d_in[4];
    const float* Wk      = (const float*)d_in[5];
    // d_in[6] = bk: enters scores only via per-q constants -> cancels in softmax
    const float* Wv      = (const float*)d_in[7];
    const float* bv      = (const float*)d_in[8];

    float* ctx  = (float*)d_out;                                // [B,Q,H]
    float* attn = (float*)d_out + (size_t)BNUM * QLEN * HID;    // [B,S,Q]

    __half *qh, *wqh, *wql, *wkh, *wkl, *wvh, *mth, *kmh, *vph, *ph;
    float  *invp;
    cudaGetSymbolAddress((void**)&qh, g_Qh);
    cudaGetSymbolAddress((void**)&wqh, g_Wqh);
    cudaGetSymbolAddress((void**)&wql, g_Wql);
    cudaGetSymbolAddress((void**)&wkh, g_Wkh);
    cudaGetSymbolAddress((void**)&wkl, g_Wkl);
    cudaGetSymbolAddress((void**)&wvh, g_Wvh);
    cudaGetSymbolAddress((void**)&mth, g_Mth);
    cudaGetSymbolAddress((void**)&kmh, g_KMh);
    cudaGetSymbolAddress((void**)&vph, g_Vph);
    cudaGetSymbolAddress((void**)&ph, g_Ph);
    cudaGetSymbolAddress((void**)&invp, g_inv);

    static bool attr_done = false;
    if (!attr_done) {
        cudaFuncSetAttribute(k_mt,    cudaFuncAttributeMaxDynamicSharedMemorySize, 2 * 4 * SLOT);
        cudaFuncSetAttribute(k_proj2, cudaFuncAttributeMaxDynamicSharedMemorySize, 4 * 2 * SLOT);
        cudaFuncSetAttribute(k_sc,    cudaFuncAttributeMaxDynamicSharedMemorySize, 4 * 2 * SLOT);
        cudaFuncSetAttribute(k_ctx,   cudaFuncAttributeMaxDynamicSharedMemorySize, 4 * 2 * SLOT);
        attr_done = true;
    }

    const int nBig4 = (BNUM * SLEN * HID) / 4;
    const int nW4   = (HID * HID) / 4;

    // 0) bias rank-1 chain (zero-work when bq == 0; keeps bq generality)
    bias_flag_k<<<1, 256>>>(bq);
    vec_k<<<HID / 256, 256>>>(Wk, bq);
    vrow_k<<<(BNUM * SLEN) / 256, 256>>>(keys);

    // 1) weight conversions (Wq/Wk split for exact Mt; Wv hi-only)
    cvt_split_k<<<1024, 256>>>((const float4*)Wq, (uint2*)wqh, (uint2*)wql, nW4);
    cvt_split_k<<<1024, 256>>>((const float4*)Wk, (uint2*)wkh, (uint2*)wkl, nW4);
    cvt_hi_k<<<1024, 256>>>((const float4*)Wv, (uint2*)wvh, nW4);

    // 2) Mt = 32 * Wq^T Wk  (TN, full split, half out)
    k_mt<<<dim3(8, 8, 1), 256, 2 * 4 * SLOT>>>(
        wqh, wql, wkh, wkl, nullptr, mth, nullptr, nullptr,
        HID, HID, HID, HID, HID, 32.0f, 0, 0, 0);

    // 3) activation conversions (hi-only), one merged launch
    cvt3_k<<<dim3(2048, 1, 3), 256>>>((const float4*)queries,
                                      (const float4*)keys,
                                      (const float4*)values, nBig4);

    // 4+5) merged Vp (z=0) and KM (z=1)
    k_proj2<<<dim3(HID / TN, (BNUM * SLEN) / TM, 2), 256, 4 * 2 * SLOT>>>(bv);

    // 6) Ph[b,s,q] = f16(exp((1/32)*KM.q + vrow)) + col-sum partials
    k_sc<<<dim3(QLEN / TN, SLEN / TM, BNUM), 256, 4 * 2 * SLOT>>>(
        kmh, nullptr, qh, nullptr, nullptr, ph, nullptr, nullptr,
        SLEN, QLEN, HID, HID, HID, 0.03125f,
        (size_t)SLEN * HID, (size_t)QLEN * HID, (size_t)SLEN * QLEN);

    // 7) per-q inverse sums
    inv_k<<<(BNUM * QLEN) / 256, 256>>>();

    // 8) ctx[b,q,h] = inv[q] * sum_s Ph[b,s,q]*Vp[b,s,h]  (TN plain, f32 out,
    //    row-scaled epilogue: normalization commutes with the GEMM)
    k_ctx<<<dim3(HID / TN, QLEN / TM, BNUM), 256, 4 * 2 * SLOT>>>(
        ph, nullptr, vph, nullptr, ctx, nullptr, nullptr, invp,
        QLEN, HID, SLEN, QLEN, HID, 1.0f,
        (size_t)SLEN * QLEN, (size_t)SLEN * HID, (size_t)QLEN * HID);

    // 9) attn f32 output = Ph * inv
    norm_k<<<2048, 256>>>((const uint2*)ph, (float4*)attn);
}

// round 10
// speedup vs baseline: 7.4578x; 1.0213x over previous
#include <cuda_runtime.h>
#include <cuda_fp16.h>
#include <cstdint>

#define HID   1024
#define BNUM  8
#define SLEN  2048
#define QLEN  2048

// ---------------- scratch: fp16 operand planes (allocation-free) -----------
__device__ __half g_Qh[(size_t)BNUM * QLEN * HID];
__device__ __half g_Kh[(size_t)BNUM * SLEN * HID];
__device__ __half g_Vh[(size_t)BNUM * SLEN * HID];
__device__ __half g_Wqh[(size_t)HID * HID];
__device__ __half g_Wql[(size_t)HID * HID];
__device__ __half g_Wkh[(size_t)HID * HID];
__device__ __half g_Wkl[(size_t)HID * HID];
__device__ __half g_Wvh[(size_t)HID * HID];
__device__ __half g_Mth[(size_t)HID * HID];          // 32 * Wq^T Wk (hi)
__device__ float  g_MtP[(size_t)4 * HID * HID];      // Mt k-split partials
__device__ __half g_KMh[(size_t)BNUM * SLEN * HID];  // keys*M (hi)
__device__ __half g_Vph[(size_t)BNUM * SLEN * HID];  // V proj (hi)
__device__ __half g_Ph [(size_t)BNUM * SLEN * QLEN]; // exp(scores) f16 (unnorm)
__device__ float  g_part[(size_t)BNUM * 16 * QLEN];  // col-sum partials
__device__ float  g_inv [(size_t)BNUM * QLEN];       // 1 / col sums
__device__ float  g_vrow[(size_t)BNUM * SLEN];       // keys * (Wk^T bq)
__device__ float  g_vec[HID];
__device__ int    g_flag;

// ---------------- geometry ----------------
#define TM   128
#define TN   128
#define TKF  32
#define SLOT 10240         // one plane-tile slot (max of NT 10240 / TN 8704)
#define PNT  80            // NT tile row pitch (64B data + 16B pad)
#define PTR  272           // TRANS tile row pitch (256B data + 16B pad)

// ---------------- PTX helpers ----------------
__device__ __forceinline__ uint32_t smem_u32(const void* p) {
    uint32_t a;
    asm("{ .reg .u64 t; cvta.to.shared.u64 t, %1; cvt.u32.u64 %0, t; }"
        : "=r"(a) : "l"(p));
    return a;
}
__device__ __forceinline__ void cp16(uint32_t s, const void* g) {
    asm volatile("cp.async.cg.shared.global [%0], [%1], 16;"
                 :: "r"(s), "l"(g));
}
__device__ __forceinline__ void cp_commit() {
    asm volatile("cp.async.commit_group;" ::: "memory");
}
template <int N_>
__device__ __forceinline__ void cp_wait() {
    asm volatile("cp.async.wait_group %0;" :: "n"(N_) : "memory");
}
__device__ __forceinline__ void ldsm4(uint32_t* r, uint32_t addr) {
    asm volatile("ldmatrix.sync.aligned.m8n8.x4.shared.b16 {%0,%1,%2,%3}, [%4];"
                 : "=r"(r[0]), "=r"(r[1]), "=r"(r[2]), "=r"(r[3]) : "r"(addr));
}
__device__ __forceinline__ void ldsm4t(uint32_t* r, uint32_t addr) {
    asm volatile("ldmatrix.sync.aligned.m8n8.x4.trans.shared.b16 {%0,%1,%2,%3}, [%4];"
                 : "=r"(r[0]), "=r"(r[1]), "=r"(r[2]), "=r"(r[3]) : "r"(addr));
}
__device__ __forceinline__ void mma16816(float* c, const uint32_t* a,
                                         const uint32_t* b) {
    asm volatile(
        "mma.sync.aligned.m16n8k16.row.col.f32.f16.f16.f32 "
        "{%0,%1,%2,%3}, {%4,%5,%6,%7}, {%8,%9}, {%0,%1,%2,%3};"
        : "+f"(c[0]), "+f"(c[1]), "+f"(c[2]), "+f"(c[3])
        : "r"(a[0]), "r"(a[1]), "r"(a[2]), "r"(a[3]), "r"(b[0]), "r"(b[1]));
}

// ---------------------------------------------------------------------------
// Unified fp16 tensor-core GEMM over pre-converted half planes.
// NT (TRANS=0): C[m,n] = alpha*sum_k A[m,k]*B[n,k], A:[M,K], B:[N,K]
// TN (TRANS=1): C[m,n] = alpha*sum_k A[k,m]*B[k,n], A:[K,M], B:[K,N]
// ASPL/BSPL: lo-residual planes (extra MMA each).
// EPI: 0 = f32 out (+bias) [optionally * rowsc[row]];
//      1 = half out (+bias);
//      2 = exp epilogue: writes f16 exp to Ch, col-sum partials to g_part.
// STAGES: cp.async pipeline depth (one __syncthreads per k-iter).
// ZZ: batch / k-split index (usually blockIdx.z).
// ---------------------------------------------------------------------------
template <bool TRANS, bool ASPL, bool BSPL, int EPI, int STAGES>
__device__ __forceinline__ void gbody(
    const __half* __restrict__ Ah, const __half* __restrict__ Al,
    const __half* __restrict__ Bh, const __half* __restrict__ Bl,
    float* __restrict__ Cf, __half* __restrict__ Ch,
    const float* __restrict__ bias, const float* __restrict__ rowsc,
    int M, int N, int K, int ldA, int ldB, float alpha,
    size_t sA, size_t sB, size_t sC, int zz_in)
{
    constexpr int NPA = ASPL ? 2 : 1;
    constexpr int NP  = NPA + (BSPL ? 2 : 1);
    constexpr int STG = NP * SLOT;

    extern __shared__ char sm[];
    const uint32_t sb = smem_u32(sm);

    const int tid  = threadIdx.x;
    const int lane = tid & 31;
    const int w    = tid >> 5;
    const int wm   = w & 1;
    const int wn   = w >> 1;
    const int g    = lane >> 2;
    const int t    = lane & 3;

    const size_t zz = zz_in;
    const __half* Ahb = Ah + zz * sA;
    const __half* Alb = ASPL ? Al + zz * sA : nullptr;
    const __half* Bhb = Bh + zz * sB;
    const __half* Blb = BSPL ? Bl + zz * sB : nullptr;
    const int bm = blockIdx.y * TM;
    const int bn = blockIdx.x * TN;

    // fragment address components
    const int a_r   = ((lane >> 3) & 1) * 8 + (lane & 7);
    const int a_c8  = (lane >> 4) * 8;
    const int b_r   = (lane >> 4) * 8 + (lane & 7);
    const int b_c8  = ((lane >> 3) & 1) * 8;
    const int at_r  = (lane >> 4) * 8 + (lane & 7);
    const int at_c8 = ((lane >> 3) & 1) * 8;
    const int bt_r  = ((lane >> 3) & 1) * 8 + (lane & 7);
    const int bt_c8 = (lane >> 4) * 8;

    float acc[4][4][4];
#pragma unroll
    for (int i = 0; i < 4; i++)
#pragma unroll
        for (int j = 0; j < 4; j++)
#pragma unroll
            for (int e = 0; e < 4; e++) acc[i][j][e] = 0.0f;

    const int NK = K / TKF;

    auto issue = [&](int kt, int p) {
        const uint32_t st = sb + p * STG;
        if (!TRANS) {
#pragma unroll
            for (int j = 0; j < 2; j++) {
                const int idx = tid * 2 + j;
                const int r = idx >> 2, c = idx & 3;
                const uint32_t so = (uint32_t)(r * PNT + c * 16);
                const size_t goA = (size_t)(bm + r) * ldA + kt * TKF + c * 8;
                const size_t goB = (size_t)(bn + r) * ldB + kt * TKF + c * 8;
                cp16(st + so, Ahb + goA);
                if (ASPL) cp16(st + SLOT + so, Alb + goA);
                cp16(st + NPA * SLOT + so, Bhb + goB);
                if (BSPL) cp16(st + (NPA + 1) * SLOT + so, Blb + goB);
            }
        } else {
#pragma unroll
            for (int j = 0; j < 2; j++) {
                const int idx = tid * 2 + j;
                const int r = idx >> 4, c = idx & 15;
                const uint32_t so = (uint32_t)(r * PTR + c * 16);
                const size_t goA = (size_t)(kt * TKF + r) * ldA + bm + c * 8;
                const size_t goB = (size_t)(kt * TKF + r) * ldB + bn + c * 8;
                cp16(st + so, Ahb + goA);
                if (ASPL) cp16(st + SLOT + so, Alb + goA);
                cp16(st + NPA * SLOT + so, Bhb + goB);
                if (BSPL) cp16(st + (NPA + 1) * SLOT + so, Blb + goB);
            }
        }
    };

    // prologue: fill STAGES-1 buffers, one commit group per tile
#pragma unroll
    for (int s = 0; s < STAGES - 1; s++) {
        if (s < NK) issue(s, s);
        cp_commit();
    }

    for (int kt = 0; kt < NK; kt++) {
        const int p = kt % STAGES;

        cp_wait<STAGES - 2>();   // tile kt resident
        __syncthreads();         // also guards reuse of buffer being refilled

        if (kt + STAGES - 1 < NK) issue(kt + STAGES - 1, (kt + STAGES - 1) % STAGES);
        cp_commit();             // keep group numbering aligned (may be empty)

        const uint32_t sa_hi = sb + p * STG;
        const uint32_t sa_lo = sa_hi + SLOT;
        const uint32_t sb_hi = sa_hi + NPA * SLOT;
        const uint32_t sb_lo = sb_hi + SLOT;

#pragma unroll
        for (int ks = 0; ks < 2; ks++) {
            const int k0 = ks * 16;

            uint32_t bh[8], bl[8];
#pragma unroll
            for (int j = 0; j < 2; j++) {
                uint32_t addr;
                if (!TRANS) {
                    addr = (uint32_t)((wn * 32 + j * 16 + b_r) * PNT +
                                      (k0 + b_c8) * 2);
                    ldsm4(bh + 4 * j, sb_hi + addr);
                    if (BSPL) ldsm4(bl + 4 * j, sb_lo + addr);
                } else {
                    addr = (uint32_t)((k0 + bt_r) * PTR +
                                      (wn * 32 + j * 16 + bt_c8) * 2);
                    ldsm4t(bh + 4 * j, sb_hi + addr);
                    if (BSPL) ldsm4t(bl + 4 * j, sb_lo + addr);
                }
            }

            uint32_t ah[4][4], al[4][4];
#pragma unroll
            for (int mf = 0; mf < 4; mf++) {
                uint32_t addr;
                if (!TRANS) {
                    addr = (uint32_t)((wm * 64 + mf * 16 + a_r) * PNT +
                                      (k0 + a_c8) * 2);
                    ldsm4(ah[mf], sa_hi + addr);
                    if (ASPL) ldsm4(al[mf], sa_lo + addr);
                } else {
                    addr = (uint32_t)((k0 + at_r) * PTR +
                                      (wm * 64 + mf * 16 + at_c8) * 2);
                    ldsm4t(ah[mf], sa_hi + addr);
                    if (ASPL) ldsm4t(al[mf], sa_lo + addr);
                }
            }

#pragma unroll
            for (int mf = 0; mf < 4; mf++)
#pragma unroll
                for (int nf = 0; nf < 4; nf++) {
                    mma16816(acc[mf][nf], ah[mf], bh + 2 * nf);
                    if (ASPL) mma16816(acc[mf][nf], al[mf], bh + 2 * nf);
                    if (BSPL) mma16816(acc[mf][nf], ah[mf], bl + 2 * nf);
                }
        }
        // no trailing sync: next iteration's sync (after cp_wait) guards reuse
    }

    // ---------------- epilogues ----------------
    if (EPI == 2) {
        __syncthreads();  // smem 'red' reuses pipeline buffers
        __half* Cb = Ch + zz * sC;
        const float* vr = g_vrow + zz * SLEN;
        float cs[8];
#pragma unroll
        for (int j = 0; j < 8; j++) cs[j] = 0.0f;

#pragma unroll
        for (int mf = 0; mf < 4; mf++) {
            const int row0 = bm + wm * 64 + mf * 16 + g;
            const int row1 = row0 + 8;
            const float v0 = vr[row0], v1 = vr[row1];
#pragma unroll
            for (int nf = 0; nf < 4; nf++) {
                const int col = bn + wn * 32 + nf * 8 + 2 * t;
                float e00 = __expf(alpha * acc[mf][nf][0] + v0);
                float e01 = __expf(alpha * acc[mf][nf][1] + v0);
                float e10 = __expf(alpha * acc[mf][nf][2] + v1);
                float e11 = __expf(alpha * acc[mf][nf][3] + v1);
                *(__half2*)(Cb + (size_t)row0 * N + col) =
                    __floats2half2_rn(e00, e01);
                *(__half2*)(Cb + (size_t)row1 * N + col) =
                    __floats2half2_rn(e10, e11);
                cs[nf * 2 + 0] += e00 + e10;
                cs[nf * 2 + 1] += e01 + e11;
            }
        }
        float* red = (float*)sm;  // 256 floats
#pragma unroll
        for (int j = 0; j < 8; j++) {
#pragma unroll
            for (int o = 4; o <= 16; o <<= 1)
                cs[j] += __shfl_xor_sync(0xFFFFFFFFu, cs[j], o);
        }
        if (lane < 4) {
#pragma unroll
            for (int nf = 0; nf < 4; nf++) {
                red[wm * 128 + wn * 32 + nf * 8 + 2 * t + 0] = cs[nf * 2 + 0];
                red[wm * 128 + wn * 32 + nf * 8 + 2 * t + 1] = cs[nf * 2 + 1];
            }
        }
        __syncthreads();
        if (tid < 128) {
            g_part[((zz * 16) + blockIdx.y) * QLEN + bn + tid] =
                red[tid] + red[128 + tid];
        }
    } else {
#pragma unroll
        for (int mf = 0; mf < 4; mf++) {
            const int row0 = bm + wm * 64 + mf * 16 + g;
            const int row1 = row0 + 8;
            float s0 = 1.0f, s1 = 1.0f;
            if (rowsc != nullptr) {
                s0 = rowsc[zz * M + row0];
                s1 = rowsc[zz * M + row1];
            }
#pragma unroll
            for (int nf = 0; nf < 4; nf++) {
                const int col = bn + wn * 32 + nf * 8 + 2 * t;
                float bx = 0.0f, by = 0.0f;
                if (bias != nullptr) { bx = bias[col]; by = bias[col + 1]; }
                float o0x = s0 * (alpha * acc[mf][nf][0]) + bx;
                float o0y = s0 * (alpha * acc[mf][nf][1]) + by;
                float o1x = s1 * (alpha * acc[mf][nf][2]) + bx;
                float o1y = s1 * (alpha * acc[mf][nf][3]) + by;
                if (EPI == 0) {
                    float* Cb = Cf + zz * sC;
                    *(float2*)(Cb + (size_t)row0 * N + col) = make_float2(o0x, o0y);
                    *(float2*)(Cb + (size_t)row1 * N + col) = make_float2(o1x, o1y);
                } else {
                    __half* Cb = Ch + zz * sC;
                    *(__half2*)(Cb + (size_t)row0 * N + col) =
                        __floats2half2_rn(o0x, o0y);
                    *(__half2*)(Cb + (size_t)row1 * N + col) =
                        __floats2half2_rn(o1x, o1y);
                }
            }
        }
    }
}

// ---------------- instantiations ----------------
// Mt with 4-way k-split: blockIdx.z picks the K chunk; f32 partials out.
extern "C" __global__ void __launch_bounds__(256)
k_mt4()
{
    gbody<true, true, true, 0, 2>(
        g_Wqh, g_Wql, g_Wkh, g_Wkl, g_MtP, nullptr, nullptr, nullptr,
        HID, HID, HID / 4, HID, HID, 32.0f,
        (size_t)(HID / 4) * HID,      // A k-chunk offset ([K,M] row-major)
        (size_t)(HID / 4) * HID,      // B k-chunk offset
        (size_t)HID * HID,            // partial-buffer stride
        blockIdx.z);
}

// reduce 4 Mt partials -> half
extern "C" __global__ void __launch_bounds__(256)
mt_red_k()
{
    const int i = blockIdx.x * 256 + threadIdx.x;   // float4 index, 262144 total
    const float4* p = (const float4*)g_MtP;
    const int n4 = (HID * HID) / 4;
    float4 s = p[i];
#pragma unroll
    for (int j = 1; j < 4; j++) {
        float4 t = p[i + j * n4];
        s.x += t.x; s.y += t.y; s.z += t.z; s.w += t.w;
    }
    __half2 h0 = __floats2half2_rn(s.x, s.y);
    __half2 h1 = __floats2half2_rn(s.z, s.w);
    ((uint2*)g_Mth)[i] = make_uint2(*(uint32_t*)&h0, *(uint32_t*)&h1);
}

// merged Vp + KM: blockIdx.z selects the problem
extern "C" __global__ void __launch_bounds__(256, 2)
k_proj2(const float* bv)
{
    if (blockIdx.z == 0)
        gbody<false, false, false, 1, 4>(
            g_Vh, nullptr, g_Wvh, nullptr, nullptr, g_Vph, bv, nullptr,
            BNUM * SLEN, HID, HID, HID, HID, 1.0f, 0, 0, 0, 0);
    else
        gbody<false, false, false, 1, 4>(
            g_Kh, nullptr, g_Mth, nullptr, nullptr, g_KMh, nullptr, nullptr,
            BNUM * SLEN, HID, HID, HID, HID, 0.03125f, 0, 0, 0, 0);
}

extern "C" __global__ void __launch_bounds__(256, 2)
k_sc(const __half* Ah, const __half* Bh, __half* Ch,
     int M, int N, int K, float alpha, size_t sA, size_t sB, size_t sC)
{ gbody<false, false, false, 2, 4>(Ah, nullptr, Bh, nullptr, nullptr, Ch,
                                   nullptr, nullptr, M, N, K, K, K, alpha,
                                   sA, sB, sC, blockIdx.z); }

// merged ctx GEMM (z<8) + attn normalization (z>=8)
extern "C" __global__ void __launch_bounds__(256, 2)
k_ctxn(float* __restrict__ ctx, float* __restrict__ attn)
{
    if (blockIdx.z < 8) {
        gbody<true, false, false, 0, 4>(
            g_Ph, nullptr, g_Vph, nullptr, ctx, nullptr, nullptr, g_inv,
            QLEN, HID, SLEN, QLEN, HID, 1.0f,
            (size_t)SLEN * QLEN, (size_t)SLEN * HID, (size_t)QLEN * HID,
            blockIdx.z);
    } else {
        // norm: attn[b,s,q] = Ph[b,s,q] * inv[b,q]
        const int cid = ((int)blockIdx.z - 8) * 128 + blockIdx.y * 8 + blockIdx.x;
        const uint2* ph4 = (const uint2*)g_Ph;
        float4* out = (float4*)attn;
        const int base = cid * 8192 + threadIdx.x;   // 1024 CTAs * 8192 f4
#pragma unroll 4
        for (int j = 0; j < 32; j++) {
            const int i = base + j * 256;
            uint2 u = ph4[i];
            const int e0 = i * 4;
            const int q  = e0 & (QLEN - 1);
            const int b  = e0 >> 22;
            float4 inv = *(const float4*)(g_inv + ((size_t)b << 11) + q);
            __half2 h0 = *(__half2*)&u.x;
            __half2 h1 = *(__half2*)&u.y;
            float2 f0 = __half22float2(h0), f1 = __half22float2(h1);
            float4 o;
            o.x = f0.x * inv.x; o.y = f0.y * inv.y;
            o.z = f1.x * inv.z; o.w = f1.y * inv.w;
            out[i] = o;
        }
    }
}

// ---------------- f32 -> half conversions ----------------
// merged weight conversion: z=0 Wq(split), z=1 Wk(split), z=2 Wv(hi)
extern "C" __global__ void __launch_bounds__(256)
cvtw_k(const float4* __restrict__ Wq, const float4* __restrict__ Wk,
       const float4* __restrict__ Wv)
{
    const int n4 = (HID * HID) / 4;
    const int z = blockIdx.z;
    const float4* in = (z == 0) ? Wq : (z == 1) ? Wk : Wv;
    uint2* hi = (z == 0) ? (uint2*)g_Wqh : (z == 1) ? (uint2*)g_Wkh
                                                    : (uint2*)g_Wvh;
    uint2* lo = (z == 0) ? (uint2*)g_Wql : (uint2*)g_Wkl;
    for (int i = blockIdx.x * 256 + threadIdx.x; i < n4; i += gridDim.x * 256) {
        float4 v = in[i];
        __half2 h0 = __floats2half2_rn(v.x, v.y);
        __half2 h1 = __floats2half2_rn(v.z, v.w);
        hi[i] = make_uint2(*(uint32_t*)&h0, *(uint32_t*)&h1);
        if (z < 2) {
            float2 f0 = __half22float2(h0), f1 = __half22float2(h1);
            __half2 l0 = __floats2half2_rn(v.x - f0.x, v.y - f0.y);
            __half2 l1 = __floats2half2_rn(v.z - f1.x, v.w - f1.y);
            lo[i] = make_uint2(*(uint32_t*)&l0, *(uint32_t*)&l1);
        }
    }
}
// merged q/k/v hi-conversion: blockIdx.z picks the tensor
extern "C" __global__ void __launch_bounds__(256)
cvt3_k(const float4* __restrict__ q, const float4* __restrict__ k,
       const float4* __restrict__ v, int n4)
{
    const float4* in = (blockIdx.z == 0) ? q : (blockIdx.z == 1) ? k : v;
    uint2* out = (blockIdx.z == 0) ? (uint2*)g_Qh
               : (blockIdx.z == 1) ? (uint2*)g_Kh : (uint2*)g_Vh;
    for (int i = blockIdx.x * 256 + threadIdx.x; i < n4; i += gridDim.x * 256) {
        float4 x = in[i];
        __half2 h0 = __floats2half2_rn(x.x, x.y);
        __half2 h1 = __floats2half2_rn(x.z, x.w);
        out[i] = make_uint2(*(uint32_t*)&h0, *(uint32_t*)&h1);
    }
}

// ---------------- bias rank-1 correction (general-bq path) ----------------
__global__ void bias_flag_k(const float* __restrict__ bq) {
    int any = 0;
    for (int i = threadIdx.x; i < HID; i += 256) any |= (bq[i] != 0.0f);
    int r = __syncthreads_or(any);
    if (threadIdx.x == 0) g_flag = r ? 1 : 0;
}
__global__ void vec_k(const float* __restrict__ Wk, const float* __restrict__ bq) {
    int i = blockIdx.x * 256 + threadIdx.x;
    float s = 0.0f;
    if (g_flag) {
        for (int o = 0; o < HID; o++) s += Wk[(size_t)o * HID + i] * bq[o];
    }
    g_vec[i] = s;
}
__global__ void vrow_k(const float* __restrict__ keys) {
    int r = blockIdx.x * 256 + threadIdx.x;
    float s = 0.0f;
    if (g_flag) {
        const float* kr = keys + (size_t)r * HID;
        for (int i = 0; i < HID; i++) s += kr[i] * g_vec[i];
    }
    g_vrow[r] = s;
}

// ---------------- per-q inverse sums ----------------
__global__ void __launch_bounds__(256) inv_k()
{
    const int i = blockIdx.x * 256 + threadIdx.x;   // b*QLEN + q
    const int b = i >> 11, q = i & (QLEN - 1);
    float tot = 0.0f;
#pragma unroll
    for (int j = 0; j < 16; j++)
        tot += g_part[((size_t)b * 16 + j) * QLEN + q];
    g_inv[i] = 1.0f / tot;
}

// ---------------- launcher ----------------
extern "C" void kernel_launch(void* const* d_in, const int* in_sizes, int n_in,
                              void* d_out, int out_size)
{
    const float* queries = (const float*)d_in[0];
    const float* keys    = (const float*)d_in[1];
    const float* values  = (const float*)d_in[2];
    const float* Wq      = (const float*)d_in[3];
    const float* bq      = (const float*)d_in[4];
    const float* Wk      = (const float*)d_in[5];
    // d_in[6] = bk: enters scores only via per-q constants -> cancels in softmax
    const float* Wv      = (const float*)d_in[7];
    const float* bv      = (const float*)d_in[8];

    float* ctx  = (float*)d_out;                                // [B,Q,H]
    float* attn = (float*)d_out + (size_t)BNUM * QLEN * HID;    // [B,S,Q]

    __half *qh, *kmh, *ph;
    cudaGetSymbolAddress((void**)&qh, g_Qh);
    cudaGetSymbolAddress((void**)&kmh, g_KMh);
    cudaGetSymbolAddress((void**)&ph, g_Ph);

    static bool attr_done = false;
    if (!attr_done) {
        cudaFuncSetAttribute(k_mt4,   cudaFuncAttributeMaxDynamicSharedMemorySize, 2 * 4 * SLOT);
        cudaFuncSetAttribute(k_proj2, cudaFuncAttributeMaxDynamicSharedMemorySize, 4 * 2 * SLOT);
        cudaFuncSetAttribute(k_sc,    cudaFuncAttributeMaxDynamicSharedMemorySize, 4 * 2 * SLOT);
        cudaFuncSetAttribute(k_ctxn,  cudaFuncAttributeMaxDynamicSharedMemorySize, 4 * 2 * SLOT);
        attr_done = true;
    }

    const int nBig4 = (BNUM * SLEN * HID) / 4;

    // 0) bias rank-1 chain (zero-work when bq == 0; keeps bq generality)
    bias_flag_k<<<1, 256>>>(bq);
    vec_k<<<HID / 256, 256>>>(Wk, bq);
    vrow_k<<<(BNUM * SLEN) / 256, 256>>>(keys);

    // 1) weight conversions, one merged launch
    cvtw_k<<<dim3(256, 1, 3), 256>>>((const float4*)Wq, (const float4*)Wk,
                                     (const float4*)Wv);

    // 2) Mt = 32 * Wq^T Wk, 4-way k-split (256 CTAs) + reduce to half
    k_mt4<<<dim3(8, 8, 4), 256, 2 * 4 * SLOT>>>();
    mt_red_k<<<(HID * HID / 4) / 256, 256>>>();

    // 3) activation conversions (hi-only), one merged launch
    cvt3_k<<<dim3(2048, 1, 3), 256>>>((const float4*)queries,
                                      (const float4*)keys,
                                      (const float4*)values, nBig4);

    // 4+5) merged Vp (z=0) and KM (z=1)
    k_proj2<<<dim3(HID / TN, (BNUM * SLEN) / TM, 2), 256, 4 * 2 * SLOT>>>(bv);

    // 6) Ph[b,s,q] = f16(exp((1/32)*KM.q + vrow)) + col-sum partials
    k_sc<<<dim3(QLEN / TN, SLEN / TM, BNUM), 256, 4 * 2 * SLOT>>>(
        kmh, qh, ph, SLEN, QLEN, HID, 0.03125f,
        (size_t)SLEN * HID, (size_t)QLEN * HID, (size_t)SLEN * QLEN);

    // 7) per-q inverse sums
    inv_k<<<(BNUM * QLEN) / 256, 256>>>();

    // 8) merged: ctx GEMM (z<8, row-scaled by inv) + attn normalization (z>=8)
    k_ctxn<<<dim3(HID / TN, QLEN / TM, 16), 256, 4 * 2 * SLOT>>>(ctx, attn);
}

// round 11
// speedup vs baseline: 7.6030x; 1.0195x over previous
#include <cuda_runtime.h>
#include <cuda_fp16.h>
#include <cstdint>

#define HID   1024
#define BNUM  8
#define SLEN  2048
#define QLEN  2048

// ---------------- scratch: fp16 operand planes (allocation-free) -----------
__device__ __half g_Qh[(size_t)BNUM * QLEN * HID];
__device__ __half g_Kh[(size_t)BNUM * SLEN * HID];
__device__ __half g_Vh[(size_t)BNUM * SLEN * HID];
__device__ __half g_Wqh[(size_t)HID * HID];
__device__ __half g_Wql[(size_t)HID * HID];
__device__ __half g_Wkh[(size_t)HID * HID];
__device__ __half g_Wkl[(size_t)HID * HID];
__device__ __half g_Wvh[(size_t)HID * HID];
__device__ __half g_Mth[(size_t)HID * HID];          // 32 * Wq^T Wk (hi)
__device__ float  g_MtP[(size_t)4 * HID * HID];      // Mt k-split partials
__device__ __half g_KMh[(size_t)BNUM * SLEN * HID];  // keys*M (hi)
__device__ __half g_Vph[(size_t)BNUM * SLEN * HID];  // V proj (hi)
__device__ __half g_Ph [(size_t)BNUM * SLEN * QLEN]; // exp(scores) f16 (unnorm)
__device__ float  g_part[(size_t)BNUM * 16 * QLEN];  // col-sum partials
__device__ float  g_inv [(size_t)BNUM * QLEN];       // 1 / col sums
__device__ float  g_vrow[(size_t)BNUM * SLEN];       // keys * (Wk^T bq)
__device__ float  g_vec[HID];
__device__ int    g_flag;

// ---------------- geometry ----------------
#define TM   128
#define TN   128
#define TKF  32
#define SLOT 10240         // one plane-tile slot (max of NT 10240 / TN 8704)
#define PNT  80            // NT tile row pitch (64B data + 16B pad)
#define PTR  272           // TRANS tile row pitch (256B data + 16B pad)

// ---------------- PTX helpers ----------------
__device__ __forceinline__ uint32_t smem_u32(const void* p) {
    uint32_t a;
    asm("{ .reg .u64 t; cvta.to.shared.u64 t, %1; cvt.u32.u64 %0, t; }"
        : "=r"(a) : "l"(p));
    return a;
}
__device__ __forceinline__ void cp16(uint32_t s, const void* g) {
    asm volatile("cp.async.cg.shared.global [%0], [%1], 16;"
                 :: "r"(s), "l"(g));
}
__device__ __forceinline__ void cp_commit() {
    asm volatile("cp.async.commit_group;" ::: "memory");
}
template <int N_>
__device__ __forceinline__ void cp_wait() {
    asm volatile("cp.async.wait_group %0;" :: "n"(N_) : "memory");
}
__device__ __forceinline__ void ldsm4(uint32_t* r, uint32_t addr) {
    asm volatile("ldmatrix.sync.aligned.m8n8.x4.shared.b16 {%0,%1,%2,%3}, [%4];"
                 : "=r"(r[0]), "=r"(r[1]), "=r"(r[2]), "=r"(r[3]) : "r"(addr));
}
__device__ __forceinline__ void ldsm4t(uint32_t* r, uint32_t addr) {
    asm volatile("ldmatrix.sync.aligned.m8n8.x4.trans.shared.b16 {%0,%1,%2,%3}, [%4];"
                 : "=r"(r[0]), "=r"(r[1]), "=r"(r[2]), "=r"(r[3]) : "r"(addr));
}
__device__ __forceinline__ void mma16816(float* c, const uint32_t* a,
                                         const uint32_t* b) {
    asm volatile(
        "mma.sync.aligned.m16n8k16.row.col.f32.f16.f16.f32 "
        "{%0,%1,%2,%3}, {%4,%5,%6,%7}, {%8,%9}, {%0,%1,%2,%3};"
        : "+f"(c[0]), "+f"(c[1]), "+f"(c[2]), "+f"(c[3])
        : "r"(a[0]), "r"(a[1]), "r"(a[2]), "r"(a[3]), "r"(b[0]), "r"(b[1]));
}

// ---------------------------------------------------------------------------
// Unified fp16 tensor-core GEMM over pre-converted half planes.
// NT (TRANS=0): C[m,n] = alpha*sum_k A[m,k]*B[n,k], A:[M,K], B:[N,K]
// TN (TRANS=1): C[m,n] = alpha*sum_k A[k,m]*B[k,n], A:[K,M], B:[K,N]
// ASPL/BSPL: lo-residual planes (extra MMA each).
// EPI: 0 = f32 out (+bias) [optionally * rowsc[row]];
//      1 = half out (+bias);
//      2 = exp epilogue: writes f16 exp to Ch, col-sum partials to g_part.
// STAGES: cp.async pipeline depth (one __syncthreads per k-iter).
// ---------------------------------------------------------------------------
template <bool TRANS, bool ASPL, bool BSPL, int EPI, int STAGES>
__device__ __forceinline__ void gbody(
    const __half* __restrict__ Ah, const __half* __restrict__ Al,
    const __half* __restrict__ Bh, const __half* __restrict__ Bl,
    float* __restrict__ Cf, __half* __restrict__ Ch,
    const float* __restrict__ bias, const float* __restrict__ rowsc,
    int M, int N, int K, int ldA, int ldB, float alpha,
    size_t sA, size_t sB, size_t sC, int zz_in)
{
    constexpr int NPA = ASPL ? 2 : 1;
    constexpr int NP  = NPA + (BSPL ? 2 : 1);
    constexpr int STG = NP * SLOT;

    extern __shared__ char sm[];
    const uint32_t sb = smem_u32(sm);

    const int tid  = threadIdx.x;
    const int lane = tid & 31;
    const int w    = tid >> 5;
    const int wm   = w & 1;
    const int wn   = w >> 1;
    const int g    = lane >> 2;
    const int t    = lane & 3;

    const size_t zz = zz_in;
    const __half* Ahb = Ah + zz * sA;
    const __half* Alb = ASPL ? Al + zz * sA : nullptr;
    const __half* Bhb = Bh + zz * sB;
    const __half* Blb = BSPL ? Bl + zz * sB : nullptr;
    const int bm = blockIdx.y * TM;
    const int bn = blockIdx.x * TN;

    // fragment address components
    const int a_r   = ((lane >> 3) & 1) * 8 + (lane & 7);
    const int a_c8  = (lane >> 4) * 8;
    const int b_r   = (lane >> 4) * 8 + (lane & 7);
    const int b_c8  = ((lane >> 3) & 1) * 8;
    const int at_r  = (lane >> 4) * 8 + (lane & 7);
    const int at_c8 = ((lane >> 3) & 1) * 8;
    const int bt_r  = ((lane >> 3) & 1) * 8 + (lane & 7);
    const int bt_c8 = (lane >> 4) * 8;

    float acc[4][4][4];
#pragma unroll
    for (int i = 0; i < 4; i++)
#pragma unroll
        for (int j = 0; j < 4; j++)
#pragma unroll
            for (int e = 0; e < 4; e++) acc[i][j][e] = 0.0f;

    const int NK = K / TKF;

    auto issue = [&](int kt, int p) {
        const uint32_t st = sb + p * STG;
        if (!TRANS) {
#pragma unroll
            for (int j = 0; j < 2; j++) {
                const int idx = tid * 2 + j;
                const int r = idx >> 2, c = idx & 3;
                const uint32_t so = (uint32_t)(r * PNT + c * 16);
                const size_t goA = (size_t)(bm + r) * ldA + kt * TKF + c * 8;
                const size_t goB = (size_t)(bn + r) * ldB + kt * TKF + c * 8;
                cp16(st + so, Ahb + goA);
                if (ASPL) cp16(st + SLOT + so, Alb + goA);
                cp16(st + NPA * SLOT + so, Bhb + goB);
                if (BSPL) cp16(st + (NPA + 1) * SLOT + so, Blb + goB);
            }
        } else {
#pragma unroll
            for (int j = 0; j < 2; j++) {
                const int idx = tid * 2 + j;
                const int r = idx >> 4, c = idx & 15;
                const uint32_t so = (uint32_t)(r * PTR + c * 16);
                const size_t goA = (size_t)(kt * TKF + r) * ldA + bm + c * 8;
                const size_t goB = (size_t)(kt * TKF + r) * ldB + bn + c * 8;
                cp16(st + so, Ahb + goA);
                if (ASPL) cp16(st + SLOT + so, Alb + goA);
                cp16(st + NPA * SLOT + so, Bhb + goB);
                if (BSPL) cp16(st + (NPA + 1) * SLOT + so, Blb + goB);
            }
        }
    };

    // prologue: fill STAGES-1 buffers, one commit group per tile
#pragma unroll
    for (int s = 0; s < STAGES - 1; s++) {
        if (s < NK) issue(s, s);
        cp_commit();
    }

    for (int kt = 0; kt < NK; kt++) {
        const int p = kt % STAGES;

        cp_wait<STAGES - 2>();   // tile kt resident
        __syncthreads();         // also guards reuse of buffer being refilled

        if (kt + STAGES - 1 < NK) issue(kt + STAGES - 1, (kt + STAGES - 1) % STAGES);
        cp_commit();             // keep group numbering aligned (may be empty)

        const uint32_t sa_hi = sb + p * STG;
        const uint32_t sa_lo = sa_hi + SLOT;
        const uint32_t sb_hi = sa_hi + NPA * SLOT;
        const uint32_t sb_lo = sb_hi + SLOT;

#pragma unroll
        for (int ks = 0; ks < 2; ks++) {
            const int k0 = ks * 16;

            uint32_t bh[8], bl[8];
#pragma unroll
            for (int j = 0; j < 2; j++) {
                uint32_t addr;
                if (!TRANS) {
                    addr = (uint32_t)((wn * 32 + j * 16 + b_r) * PNT +
                                      (k0 + b_c8) * 2);
                    ldsm4(bh + 4 * j, sb_hi + addr);
                    if (BSPL) ldsm4(bl + 4 * j, sb_lo + addr);
                } else {
                    addr = (uint32_t)((k0 + bt_r) * PTR +
                                      (wn * 32 + j * 16 + bt_c8) * 2);
                    ldsm4t(bh + 4 * j, sb_hi + addr);
                    if (BSPL) ldsm4t(bl + 4 * j, sb_lo + addr);
                }
            }

            uint32_t ah[4][4], al[4][4];
#pragma unroll
            for (int mf = 0; mf < 4; mf++) {
                uint32_t addr;
                if (!TRANS) {
                    addr = (uint32_t)((wm * 64 + mf * 16 + a_r) * PNT +
                                      (k0 + a_c8) * 2);
                    ldsm4(ah[mf], sa_hi + addr);
                    if (ASPL) ldsm4(al[mf], sa_lo + addr);
                } else {
                    addr = (uint32_t)((k0 + at_r) * PTR +
                                      (wm * 64 + mf * 16 + at_c8) * 2);
                    ldsm4t(ah[mf], sa_hi + addr);
                    if (ASPL) ldsm4t(al[mf], sa_lo + addr);
                }
            }

#pragma unroll
            for (int mf = 0; mf < 4; mf++)
#pragma unroll
                for (int nf = 0; nf < 4; nf++) {
                    mma16816(acc[mf][nf], ah[mf], bh + 2 * nf);
                    if (ASPL) mma16816(acc[mf][nf], al[mf], bh + 2 * nf);
                    if (BSPL) mma16816(acc[mf][nf], ah[mf], bl + 2 * nf);
                }
        }
        // no trailing sync: next iteration's sync (after cp_wait) guards reuse
    }

    // ---------------- epilogues ----------------
    if (EPI == 2) {
        __syncthreads();  // smem 'red' reuses pipeline buffers
        __half* Cb = Ch + zz * sC;
        const float* vr = g_vrow + zz * SLEN;
        float cs[8];
#pragma unroll
        for (int j = 0; j < 8; j++) cs[j] = 0.0f;

#pragma unroll
        for (int mf = 0; mf < 4; mf++) {
            const int row0 = bm + wm * 64 + mf * 16 + g;
            const int row1 = row0 + 8;
            const float v0 = vr[row0], v1 = vr[row1];
#pragma unroll
            for (int nf = 0; nf < 4; nf++) {
                const int col = bn + wn * 32 + nf * 8 + 2 * t;
                float e00 = __expf(alpha * acc[mf][nf][0] + v0);
                float e01 = __expf(alpha * acc[mf][nf][1] + v0);
                float e10 = __expf(alpha * acc[mf][nf][2] + v1);
                float e11 = __expf(alpha * acc[mf][nf][3] + v1);
                *(__half2*)(Cb + (size_t)row0 * N + col) =
                    __floats2half2_rn(e00, e01);
                *(__half2*)(Cb + (size_t)row1 * N + col) =
                    __floats2half2_rn(e10, e11);
                cs[nf * 2 + 0] += e00 + e10;
                cs[nf * 2 + 1] += e01 + e11;
            }
        }
        float* red = (float*)sm;  // 256 floats
#pragma unroll
        for (int j = 0; j < 8; j++) {
#pragma unroll
            for (int o = 4; o <= 16; o <<= 1)
                cs[j] += __shfl_xor_sync(0xFFFFFFFFu, cs[j], o);
        }
        if (lane < 4) {
#pragma unroll
            for (int nf = 0; nf < 4; nf++) {
                red[wm * 128 + wn * 32 + nf * 8 + 2 * t + 0] = cs[nf * 2 + 0];
                red[wm * 128 + wn * 32 + nf * 8 + 2 * t + 1] = cs[nf * 2 + 1];
            }
        }
        __syncthreads();
        if (tid < 128) {
            g_part[((zz * 16) + blockIdx.y) * QLEN + bn + tid] =
                red[tid] + red[128 + tid];
        }
    } else {
#pragma unroll
        for (int mf = 0; mf < 4; mf++) {
            const int row0 = bm + wm * 64 + mf * 16 + g;
            const int row1 = row0 + 8;
            float s0 = 1.0f, s1 = 1.0f;
            if (rowsc != nullptr) {
                s0 = rowsc[zz * M + row0];
                s1 = rowsc[zz * M + row1];
            }
#pragma unroll
            for (int nf = 0; nf < 4; nf++) {
                const int col = bn + wn * 32 + nf * 8 + 2 * t;
                float bx = 0.0f, by = 0.0f;
                if (bias != nullptr) { bx = bias[col]; by = bias[col + 1]; }
                float o0x = s0 * (alpha * acc[mf][nf][0]) + bx;
                float o0y = s0 * (alpha * acc[mf][nf][1]) + by;
                float o1x = s1 * (alpha * acc[mf][nf][2]) + bx;
                float o1y = s1 * (alpha * acc[mf][nf][3]) + by;
                if (EPI == 0) {
                    float* Cb = Cf + zz * sC;
                    *(float2*)(Cb + (size_t)row0 * N + col) = make_float2(o0x, o0y);
                    *(float2*)(Cb + (size_t)row1 * N + col) = make_float2(o1x, o1y);
                } else {
                    __half* Cb = Ch + zz * sC;
                    *(__half2*)(Cb + (size_t)row0 * N + col) =
                        __floats2half2_rn(o0x, o0y);
                    *(__half2*)(Cb + (size_t)row1 * N + col) =
                        __floats2half2_rn(o1x, o1y);
                }
            }
        }
    }
}

// ---------------- instantiations ----------------
// Mt with 4-way k-split: blockIdx.z picks the K chunk; f32 partials out.
extern "C" __global__ void __launch_bounds__(256)
k_mt4()
{
    gbody<true, true, true, 0, 2>(
        g_Wqh, g_Wql, g_Wkh, g_Wkl, g_MtP, nullptr, nullptr, nullptr,
        HID, HID, HID / 4, HID, HID, 32.0f,
        (size_t)(HID / 4) * HID,      // A k-chunk offset ([K,M] row-major)
        (size_t)(HID / 4) * HID,      // B k-chunk offset
        (size_t)HID * HID,            // partial-buffer stride
        blockIdx.z);
}

// reduce 4 Mt partials -> half
extern "C" __global__ void __launch_bounds__(256)
mt_red_k()
{
    const int i = blockIdx.x * 256 + threadIdx.x;   // float4 index, 262144 total
    const float4* p = (const float4*)g_MtP;
    const int n4 = (HID * HID) / 4;
    float4 s = p[i];
#pragma unroll
    for (int j = 1; j < 4; j++) {
        float4 t = p[i + j * n4];
        s.x += t.x; s.y += t.y; s.z += t.z; s.w += t.w;
    }
    __half2 h0 = __floats2half2_rn(s.x, s.y);
    __half2 h1 = __floats2half2_rn(s.z, s.w);
    ((uint2*)g_Mth)[i] = make_uint2(*(uint32_t*)&h0, *(uint32_t*)&h1);
}

// merged Vp + KM: blockIdx.z selects the problem
extern "C" __global__ void __launch_bounds__(256, 2)
k_proj2(const float* bv)
{
    if (blockIdx.z == 0)
        gbody<false, false, false, 1, 4>(
            g_Vh, nullptr, g_Wvh, nullptr, nullptr, g_Vph, bv, nullptr,
            BNUM * SLEN, HID, HID, HID, HID, 1.0f, 0, 0, 0, 0);
    else
        gbody<false, false, false, 1, 4>(
            g_Kh, nullptr, g_Mth, nullptr, nullptr, g_KMh, nullptr, nullptr,
            BNUM * SLEN, HID, HID, HID, HID, 0.03125f, 0, 0, 0, 0);
}

extern "C" __global__ void __launch_bounds__(256, 2)
k_sc(const __half* Ah, const __half* Bh, __half* Ch,
     int M, int N, int K, float alpha, size_t sA, size_t sB, size_t sC)
{ gbody<false, false, false, 2, 4>(Ah, nullptr, Bh, nullptr, nullptr, Ch,
                                   nullptr, nullptr, M, N, K, K, K, alpha,
                                   sA, sB, sC, blockIdx.z); }

// merged ctx GEMM (z<8) + attn normalization (z>=8)
extern "C" __global__ void __launch_bounds__(256, 2)
k_ctxn(float* __restrict__ ctx, float* __restrict__ attn)
{
    if (blockIdx.z < 8) {
        gbody<true, false, false, 0, 4>(
            g_Ph, nullptr, g_Vph, nullptr, ctx, nullptr, nullptr, g_inv,
            QLEN, HID, SLEN, QLEN, HID, 1.0f,
            (size_t)SLEN * QLEN, (size_t)SLEN * HID, (size_t)QLEN * HID,
            blockIdx.z);
    } else {
        // norm: attn[b,s,q] = Ph[b,s,q] * inv[b,q]
        const int cid = ((int)blockIdx.z - 8) * 128 + blockIdx.y * 8 + blockIdx.x;
        const uint2* ph4 = (const uint2*)g_Ph;
        float4* out = (float4*)attn;
        const int base = cid * 8192 + threadIdx.x;   // 1024 CTAs * 8192 f4
#pragma unroll 4
        for (int j = 0; j < 32; j++) {
            const int i = base + j * 256;
            uint2 u = ph4[i];
            const int e0 = i * 4;
            const int q  = e0 & (QLEN - 1);
            const int b  = e0 >> 22;
            float4 inv = *(const float4*)(g_inv + ((size_t)b << 11) + q);
            __half2 h0 = *(__half2*)&u.x;
            __half2 h1 = *(__half2*)&u.y;
            float2 f0 = __half22float2(h0), f1 = __half22float2(h1);
            float4 o;
            o.x = f0.x * inv.x; o.y = f0.y * inv.y;
            o.z = f1.x * inv.z; o.w = f1.y * inv.w;
            out[i] = o;
        }
    }
}

// ---------------- f32 -> half conversions ----------------
// merged weight conversion: z=0 Wq(split), z=1 Wk(split), z=2 Wv(hi)
extern "C" __global__ void __launch_bounds__(256)
cvtw_k(const float4* __restrict__ Wq, const float4* __restrict__ Wk,
       const float4* __restrict__ Wv)
{
    const int n4 = (HID * HID) / 4;
    const int z = blockIdx.z;
    const float4* in = (z == 0) ? Wq : (z == 1) ? Wk : Wv;
    uint2* hi = (z == 0) ? (uint2*)g_Wqh : (z == 1) ? (uint2*)g_Wkh
                                                    : (uint2*)g_Wvh;
    uint2* lo = (z == 0) ? (uint2*)g_Wql : (uint2*)g_Wkl;
    for (int i = blockIdx.x * 256 + threadIdx.x; i < n4; i += gridDim.x * 256) {
        float4 v = in[i];
        __half2 h0 = __floats2half2_rn(v.x, v.y);
        __half2 h1 = __floats2half2_rn(v.z, v.w);
        hi[i] = make_uint2(*(uint32_t*)&h0, *(uint32_t*)&h1);
        if (z < 2) {
            float2 f0 = __half22float2(h0), f1 = __half22float2(h1);
            __half2 l0 = __floats2half2_rn(v.x - f0.x, v.y - f0.y);
            __half2 l1 = __floats2half2_rn(v.z - f1.x, v.w - f1.y);
            lo[i] = make_uint2(*(uint32_t*)&l0, *(uint32_t*)&l1);
        }
    }
}
// merged q/k/v hi-conversion: blockIdx.z picks the tensor
extern "C" __global__ void __launch_bounds__(256)
cvt3_k(const float4* __restrict__ q, const float4* __restrict__ k,
       const float4* __restrict__ v, int n4)
{
    const float4* in = (blockIdx.z == 0) ? q : (blockIdx.z == 1) ? k : v;
    uint2* out = (blockIdx.z == 0) ? (uint2*)g_Qh
               : (blockIdx.z == 1) ? (uint2*)g_Kh : (uint2*)g_Vh;
    for (int i = blockIdx.x * 256 + threadIdx.x; i < n4; i += gridDim.x * 256) {
        float4 x = in[i];
        __half2 h0 = __floats2half2_rn(x.x, x.y);
        __half2 h1 = __floats2half2_rn(x.z, x.w);
        out[i] = make_uint2(*(uint32_t*)&h0, *(uint32_t*)&h1);
    }
}

// ---------------- bias rank-1 correction (general-bq path) ----------------
// veca_k: per-CTA bq!=0 flag (syncthreads_or) + g_vec = Wk^T bq; CTA0 also
// publishes g_flag for vrow_k (which runs after in stream order).
__global__ void __launch_bounds__(256)
veca_k(const float* __restrict__ Wk, const float* __restrict__ bq)
{
    int any = 0;
    for (int i = threadIdx.x; i < HID; i += 256) any |= (bq[i] != 0.0f);
    const int r = __syncthreads_or(any);
    if (threadIdx.x == 0 && blockIdx.x == 0) g_flag = r ? 1 : 0;

    const int i = blockIdx.x * 256 + threadIdx.x;
    float s = 0.0f;
    if (r) {
        for (int o = 0; o < HID; o++) s += Wk[(size_t)o * HID + i] * bq[o];
    }
    g_vec[i] = s;
}
__global__ void __launch_bounds__(256)
vrow_k(const float* __restrict__ keys)
{
    const int r = blockIdx.x * 256 + threadIdx.x;
    float s = 0.0f;
    if (g_flag) {
        const float* kr = keys + (size_t)r * HID;
        for (int i = 0; i < HID; i++) s += kr[i] * g_vec[i];
    }
    g_vrow[r] = s;
}

// ---------------- per-q inverse sums ----------------
__global__ void __launch_bounds__(256) inv_k()
{
    const int i = blockIdx.x * 256 + threadIdx.x;   // b*QLEN + q
    const int b = i >> 11, q = i & (QLEN - 1);
    float tot = 0.0f;
#pragma unroll
    for (int j = 0; j < 16; j++)
        tot += g_part[((size_t)b * 16 + j) * QLEN + q];
    g_inv[i] = 1.0f / tot;
}

// ---------------- launcher ----------------
extern "C" void kernel_launch(void* const* d_in, const int* in_sizes, int n_in,
                              void* d_out, int out_size)
{
    const float* queries = (const float*)d_in[0];
    const float* keys    = (const float*)d_in[1];
    const float* values  = (const float*)d_in[2];
    const float* Wq      = (const float*)d_in[3];
    const float* bq      = (const float*)d_in[4];
    const float* Wk      = (const float*)d_in[5];
    // d_in[6] = bk: enters scores only via per-q constants -> cancels in softmax
    const float* Wv      = (const float*)d_in[7];
    const float* bv      = (const float*)d_in[8];

    float* ctx  = (float*)d_out;                                // [B,Q,H]
    float* attn = (float*)d_out + (size_t)BNUM * QLEN * HID;    // [B,S,Q]

    __half *qh, *kmh, *ph;
    cudaGetSymbolAddress((void**)&qh, g_Qh);
    cudaGetSymbolAddress((void**)&kmh, g_KMh);
    cudaGetSymbolAddress((void**)&ph, g_Ph);

    static cudaStream_t s1 = nullptr;
    static cudaEvent_t  evFork = nullptr, evJoin = nullptr;
    static bool init_done = false;
    if (!init_done) {
        cudaStreamCreateWithFlags(&s1, cudaStreamNonBlocking);
        cudaEventCreateWithFlags(&evFork, cudaEventDisableTiming);
        cudaEventCreateWithFlags(&evJoin, cudaEventDisableTiming);
        cudaFuncSetAttribute(k_mt4,   cudaFuncAttributeMaxDynamicSharedMemorySize, 2 * 4 * SLOT);
        cudaFuncSetAttribute(k_proj2, cudaFuncAttributeMaxDynamicSharedMemorySize, 4 * 2 * SLOT);
        cudaFuncSetAttribute(k_sc,    cudaFuncAttributeMaxDynamicSharedMemorySize, 4 * 2 * SLOT);
        cudaFuncSetAttribute(k_ctxn,  cudaFuncAttributeMaxDynamicSharedMemorySize, 4 * 2 * SLOT);
        init_done = true;
    }

    const int nBig4 = (BNUM * SLEN * HID) / 4;

    // ---- fork: weight-conversion + Mt chain on side stream s1 ----
    cudaEventRecord(evFork, 0);
    cudaStreamWaitEvent(s1, evFork, 0);
    cvtw_k<<<dim3(256, 1, 3), 256, 0, s1>>>((const float4*)Wq,
                                            (const float4*)Wk,
                                            (const float4*)Wv);
    k_mt4<<<dim3(8, 8, 4), 256, 2 * 4 * SLOT, s1>>>();
    mt_red_k<<<(HID * HID / 4) / 256, 256, 0, s1>>>();
    cudaEventRecord(evJoin, s1);

    // ---- main stream: bias chain + activation conversions (overlaps s1) ----
    veca_k<<<HID / 256, 256>>>(Wk, bq);
    vrow_k<<<(BNUM * SLEN) / 256, 256>>>(keys);
    cvt3_k<<<dim3(2048, 1, 3), 256>>>((const float4*)queries,
                                      (const float4*)keys,
                                      (const float4*)values, nBig4);

    // ---- join: everything below needs both tracks ----
    cudaStreamWaitEvent(0, evJoin, 0);

    // merged Vp (z=0) and KM (z=1)
    k_proj2<<<dim3(HID / TN, (BNUM * SLEN) / TM, 2), 256, 4 * 2 * SLOT>>>(bv);

    // Ph[b,s,q] = f16(exp((1/32)*KM.q + vrow)) + col-sum partials
    k_sc<<<dim3(QLEN / TN, SLEN / TM, BNUM), 256, 4 * 2 * SLOT>>>(
        kmh, qh, ph, SLEN, QLEN, HID, 0.03125f,
        (size_t)SLEN * HID, (size_t)QLEN * HID, (size_t)SLEN * QLEN);

    // per-q inverse sums
    inv_k<<<(BNUM * QLEN) / 256, 256>>>();

    // merged: ctx GEMM (z<8, row-scaled by inv) + attn normalization (z>=8)
    k_ctxn<<<dim3(HID / TN, QLEN / TM, 16), 256, 4 * 2 * SLOT>>>(ctx, attn);
}